// round 1
// baseline (speedup 1.0000x reference)
#include <cuda_runtime.h>
#include <cuda_bf16.h>

// Problem constants
#define BB 2
#define NN 8192
#define CC 128
#define PP 3
#define KK 16
#define NPTS (BB*NN)          // 16384 total points
#define EPS 1e-5f

// ---------------- scratch (static device globals; no allocation) ----------------
__device__ float d_w1t[131*128];     // [c][o]  (c = 0..130 input feat, o = lin1 out)
__device__ float d_w2t[128*128];     // [h][o]
__device__ float d_m1t[128*128];
__device__ float d_m2t[128*128];
__device__ int   d_nbr[NPTS*KK];     // global row indices of K neighbors
__device__ float d_u [NPTS*CC];      // W1 @ [x;pos]
__device__ float d_ux[NPTS*CC];      // W1x @ x (self path)
__device__ float d_res[NPTS*CC];
__device__ float d_t [NPTS*CC];      // lin(m1) output
__device__ float d_p1[128*128];      // stats partials (sum)
__device__ float d_p2[128*128];      // stats partials (sumsq)
__device__ float d_scale1[CC], d_shift1[CC], d_scale2[CC], d_shift2[CC];

// ---------------- prep: transpose weight matrices ----------------
__global__ void prep_kernel(const float* __restrict__ w1, const float* __restrict__ w2,
                            const float* __restrict__ m1, const float* __restrict__ m2) {
    int i = blockIdx.x*blockDim.x + threadIdx.x;
    if (i < 131*128) { int o = i/131, c = i%131; d_w1t[c*128+o] = w1[i]; }
    if (i < 128*128) { int o = i>>7, c = i&127;
        d_w2t[c*128+o] = w2[i];
        d_m1t[c*128+o] = m1[i];
        d_m2t[c*128+o] = m2[i];
    }
}

// ---------------- KNN: thread-per-query, full-batch pos in smem ----------------
__global__ void knn_kernel(const float* __restrict__ pos) {
    extern __shared__ float4 sp[];               // 8192 float4 = 128KB
    const int b   = blockIdx.x >> 5;             // 32 blocks per batch
    const int blk = blockIdx.x & 31;
    const int tid = threadIdx.x;
    const float* pb = pos + (size_t)b*NN*3;
    for (int j = tid; j < NN; j += 256) {
        float px = pb[j*3+0], py = pb[j*3+1], pz = pb[j*3+2];
        sp[j] = make_float4(px, py, pz, px*px + py*py + pz*pz);
    }
    __syncthreads();
    const int q = blk*256 + tid;
    const float4 qp = sp[q];

    float bd[KK]; int bi[KK];
    #pragma unroll
    for (int t = 0; t < KK; t++) { bd[t] = 3.4e38f; bi[t] = 0; }

    for (int j = 0; j < NN; j++) {
        float4 c = sp[j];
        float d = qp.w + c.w - 2.f*(qp.x*c.x + qp.y*c.y + qp.z*c.z);
        if (d < bd[KK-1]) {
            float dd = d; int ii = j;
            #pragma unroll
            for (int t = 0; t < KK; t++) {
                if (dd < bd[t]) {
                    float tf = bd[t]; bd[t] = dd; dd = tf;
                    int   ti = bi[t]; bi[t] = ii; ii = ti;
                }
            }
        }
    }
    int base = (b*NN + q)*KK;
    #pragma unroll
    for (int t = 0; t < KK; t++) d_nbr[base + t] = b*NN + bi[t];
}

// ---------------- u GEMM: u = [x;pos] @ W1^T, also ux = x @ W1x^T ----------------
// 256 threads, 64 points/block, thread computes 4x8 tile.
__global__ void u_gemm_kernel(const float* __restrict__ x, const float* __restrict__ pos) {
    extern __shared__ float smu[];
    float* wts  = smu;            // 131*128 = 16768
    float* tile = smu + 16768;    // 64*132
    const int tid = threadIdx.x;
    const int g0  = blockIdx.x * 64;
    for (int i = tid; i < 16768; i += 256) wts[i] = d_w1t[i];
    for (int i = tid; i < 64*132; i += 256) {
        int p = i/132, c = i%132;
        int g = g0 + p;
        float v = 0.f;
        if (c < 128)      v = x[(size_t)g*128 + c];
        else if (c < 131) v = pos[(size_t)g*3 + (c-128)];
        tile[i] = v;
    }
    __syncthreads();
    const int rg = tid >> 4, og = tid & 15;
    const int r0 = rg*4, o0 = og*8;
    float acc[4][8] = {};
    int c = 0;
    #pragma unroll 2
    for (; c < 128; ++c) {
        float4 wa = *reinterpret_cast<const float4*>(&wts[c*128 + o0]);
        float4 wb = *reinterpret_cast<const float4*>(&wts[c*128 + o0 + 4]);
        float w8[8] = {wa.x,wa.y,wa.z,wa.w,wb.x,wb.y,wb.z,wb.w};
        float hh[4];
        #pragma unroll
        for (int r = 0; r < 4; r++) hh[r] = tile[(r0+r)*132 + c];
        #pragma unroll
        for (int r = 0; r < 4; r++)
            #pragma unroll
            for (int j = 0; j < 8; j++) acc[r][j] = fmaf(hh[r], w8[j], acc[r][j]);
    }
    #pragma unroll
    for (int r = 0; r < 4; r++) {
        float* op = d_ux + (size_t)(g0+r0+r)*128 + o0;
        #pragma unroll
        for (int j = 0; j < 8; j++) op[j] = acc[r][j];
    }
    for (; c < 131; ++c) {
        float4 wa = *reinterpret_cast<const float4*>(&wts[c*128 + o0]);
        float4 wb = *reinterpret_cast<const float4*>(&wts[c*128 + o0 + 4]);
        float w8[8] = {wa.x,wa.y,wa.z,wa.w,wb.x,wb.y,wb.z,wb.w};
        float hh[4];
        #pragma unroll
        for (int r = 0; r < 4; r++) hh[r] = tile[(r0+r)*132 + c];
        #pragma unroll
        for (int r = 0; r < 4; r++)
            #pragma unroll
            for (int j = 0; j < 8; j++) acc[r][j] = fmaf(hh[r], w8[j], acc[r][j]);
    }
    #pragma unroll
    for (int r = 0; r < 4; r++) {
        float* op = d_u + (size_t)(g0+r0+r)*128 + o0;
        #pragma unroll
        for (int j = 0; j < 8; j++) op[j] = acc[r][j];
    }
}

// ---------------- fused neighbor kernel (the dominant GEMM) ----------------
// 4 points/block, 256 threads. hidden = relu(u[g]-u[n]+b1); weights = sigmoid(W2 h + b2);
// res = x*(1+w_self) - sum_k rel_x*weights.
__global__ void neighbor_kernel(const float* __restrict__ x,
                                const float* __restrict__ b1, const float* __restrict__ b2) {
    extern __shared__ float smn[];
    float* w2s  = smn;              // 16384
    float* hid  = w2s  + 16384;     // 68*132 = 8976 (rows 0..63 neighbors, 64..67 self)
    float* ucen = hid  + 8976;      // 4*128
    float* xns  = ucen + 512;       // 4*128
    float* b1s  = xns  + 512;       // 128
    float* b2s  = b1s  + 128;       // 128
    float* part = b2s  + 128;       // 4*4*128
    float* ws   = part + 2048;      // 4*128
    int*   nidx = (int*)(ws + 512); // 64

    const int tid = threadIdx.x;
    const int g0  = blockIdx.x * 4;

    for (int i = tid; i < 16384; i += 256) w2s[i] = d_w2t[i];
    if (tid < 64)  nidx[tid] = d_nbr[g0*KK + tid];
    if (tid < 128) { b1s[tid] = b1[tid]; b2s[tid] = b2[tid]; }
    for (int i = tid; i < 512; i += 256) {
        int p = i >> 7, c = i & 127;
        ucen[i] = d_u[(size_t)(g0+p)*128 + c];
        xns[i]  = x  [(size_t)(g0+p)*128 + c];
    }
    __syncthreads();

    // build hidden rows
    for (int i = tid; i < 64*128; i += 256) {
        int r = i >> 7, c = i & 127, p = r >> 4;
        float v = d_u[(size_t)nidx[r]*128 + c] - ucen[p*128 + c] + b1s[c];
        hid[r*132 + c] = fmaxf(v, 0.f);
    }
    for (int i = tid; i < 512; i += 256) {
        int p = i >> 7, c = i & 127;
        float v = d_ux[(size_t)(g0+p)*128 + c] + b1s[c];
        hid[(64+p)*132 + c] = fmaxf(v, 0.f);
    }
    __syncthreads();

    // main GEMM: 64 rows x 128 cols, K=128; thread tile 4x8
    const int rg = tid >> 4, og = tid & 15;
    const int r0 = rg*4, o0 = og*8;
    const int p  = r0 >> 4;
    float acc[4][8] = {};
    #pragma unroll 2
    for (int c = 0; c < 128; ++c) {
        float4 wa = *reinterpret_cast<const float4*>(&w2s[c*128 + o0]);
        float4 wb = *reinterpret_cast<const float4*>(&w2s[c*128 + o0 + 4]);
        float w8[8] = {wa.x,wa.y,wa.z,wa.w,wb.x,wb.y,wb.z,wb.w};
        float hh[4];
        #pragma unroll
        for (int r = 0; r < 4; r++) hh[r] = hid[(r0+r)*132 + c];
        #pragma unroll
        for (int r = 0; r < 4; r++)
            #pragma unroll
            for (int j = 0; j < 8; j++) acc[r][j] = fmaf(hh[r], w8[j], acc[r][j]);
    }

    // sigmoid + gather rel_x + partial K-sum (ascending k for determinism)
    float psum[8] = {};
    #pragma unroll
    for (int r = 0; r < 4; r++) {
        int g = nidx[r0 + r];
        const float* xr = x + (size_t)g*128 + o0;
        float4 xa = *reinterpret_cast<const float4*>(xr);
        float4 xb = *reinterpret_cast<const float4*>(xr + 4);
        float xc[8] = {xa.x,xa.y,xa.z,xa.w,xb.x,xb.y,xb.z,xb.w};
        #pragma unroll
        for (int j = 0; j < 8; j++) {
            float z = acc[r][j] + b2s[o0 + j];
            float s = 1.f/(1.f + __expf(-z));
            psum[j] += (xc[j] - xns[p*128 + o0 + j]) * s;
        }
    }
    {
        int sub = rg & 3;
        float* pp = part + (p*4 + sub)*128 + o0;
        #pragma unroll
        for (int j = 0; j < 8; j++) pp[j] = psum[j];
    }

    // self rows: 4 points x 128 out = 512 dot products (2 per thread)
    for (int t = tid; t < 512; t += 256) {
        int sp = t >> 7, o = t & 127;
        float a = 0.f;
        for (int c = 0; c < 128; c++) a = fmaf(hid[(64+sp)*132 + c], w2s[c*128 + o], a);
        ws[t] = 1.f/(1.f + __expf(-(a + b2s[o])));
    }
    __syncthreads();

    // combine partials (fixed order) and write res
    for (int t = tid; t < 512; t += 256) {
        int sp = t >> 7, o = t & 127;
        float xv = xns[t];
        float s  = part[(sp*4+0)*128+o] + part[(sp*4+1)*128+o]
                 + part[(sp*4+2)*128+o] + part[(sp*4+3)*128+o];
        d_res[(size_t)(g0+sp)*128 + o] = xv*(1.f + ws[t]) - s;
    }
}

// ---------------- generic 64-row GEMMs for the tail MLP ----------------
__global__ void gemm_bias_kernel(const float* __restrict__ bias) {   // t = res @ m1^T + mb1
    extern __shared__ float smg[];
    float* wts  = smg;           // 16384
    float* tile = smg + 16384;   // 64*132
    const int tid = threadIdx.x, g0 = blockIdx.x*64;
    for (int i = tid; i < 16384; i += 256) wts[i] = d_m1t[i];
    for (int i = tid; i < 8192; i += 256) {
        int p = i >> 7, c = i & 127;
        tile[p*132 + c] = d_res[(size_t)(g0+p)*128 + c];
    }
    __syncthreads();
    const int rg = tid >> 4, og = tid & 15;
    const int r0 = rg*4, o0 = og*8;
    float acc[4][8] = {};
    #pragma unroll 2
    for (int c = 0; c < 128; ++c) {
        float4 wa = *reinterpret_cast<const float4*>(&wts[c*128 + o0]);
        float4 wb = *reinterpret_cast<const float4*>(&wts[c*128 + o0 + 4]);
        float w8[8] = {wa.x,wa.y,wa.z,wa.w,wb.x,wb.y,wb.z,wb.w};
        float hh[4];
        #pragma unroll
        for (int r = 0; r < 4; r++) hh[r] = tile[(r0+r)*132 + c];
        #pragma unroll
        for (int r = 0; r < 4; r++)
            #pragma unroll
            for (int j = 0; j < 8; j++) acc[r][j] = fmaf(hh[r], w8[j], acc[r][j]);
    }
    #pragma unroll
    for (int r = 0; r < 4; r++) {
        float* op = d_t + (size_t)(g0+r0+r)*128 + o0;
        #pragma unroll
        for (int j = 0; j < 8; j++) op[j] = acc[r][j] + bias[o0 + j];
    }
}

__global__ void gemm_bn_relu_kernel(const float* __restrict__ bias, float* __restrict__ out) {
    // h = relu(bn1(t)); out_raw = h @ m2^T + mb2
    extern __shared__ float smh[];
    float* wts  = smh;
    float* tile = smh + 16384;
    const int tid = threadIdx.x, g0 = blockIdx.x*64;
    for (int i = tid; i < 16384; i += 256) wts[i] = d_m2t[i];
    for (int i = tid; i < 8192; i += 256) {
        int p = i >> 7, c = i & 127;
        float v = d_t[(size_t)(g0+p)*128 + c];
        tile[p*132 + c] = fmaxf(fmaf(v, d_scale1[c], d_shift1[c]), 0.f);
    }
    __syncthreads();
    const int rg = tid >> 4, og = tid & 15;
    const int r0 = rg*4, o0 = og*8;
    float acc[4][8] = {};
    #pragma unroll 2
    for (int c = 0; c < 128; ++c) {
        float4 wa = *reinterpret_cast<const float4*>(&wts[c*128 + o0]);
        float4 wb = *reinterpret_cast<const float4*>(&wts[c*128 + o0 + 4]);
        float w8[8] = {wa.x,wa.y,wa.z,wa.w,wb.x,wb.y,wb.z,wb.w};
        float hh[4];
        #pragma unroll
        for (int r = 0; r < 4; r++) hh[r] = tile[(r0+r)*132 + c];
        #pragma unroll
        for (int r = 0; r < 4; r++)
            #pragma unroll
            for (int j = 0; j < 8; j++) acc[r][j] = fmaf(hh[r], w8[j], acc[r][j]);
    }
    #pragma unroll
    for (int r = 0; r < 4; r++) {
        float* op = out + (size_t)(g0+r0+r)*128 + o0;
        #pragma unroll
        for (int j = 0; j < 8; j++) op[j] = acc[r][j] + bias[o0 + j];
    }
}

// ---------------- deterministic BN stats (no atomics) ----------------
__global__ void stats_kernel(const float* __restrict__ ext, int use_ext) {
    const float* in = use_ext ? ext : d_t;
    const int blk = blockIdx.x, o = threadIdx.x;    // 128 blocks x 128 threads
    float s = 0.f, s2 = 0.f;
    for (int r = 0; r < 128; r++) {
        float v = in[(size_t)(blk*128 + r)*128 + o];
        s += v; s2 += v*v;
    }
    d_p1[blk*128 + o] = s;
    d_p2[blk*128 + o] = s2;
}

__global__ void bn_finalize_kernel(const float* __restrict__ g, const float* __restrict__ be,
                                   int which) {
    const int o = threadIdx.x;
    float s = 0.f, s2 = 0.f;
    for (int b = 0; b < 128; b++) { s += d_p1[b*128 + o]; s2 += d_p2[b*128 + o]; }
    float mu  = s  * (1.f/16384.f);
    float var = s2 * (1.f/16384.f) - mu*mu;
    float sc  = g[o] * rsqrtf(var + EPS);
    if (which == 0) { d_scale1[o] = sc; d_shift1[o] = be[o] - mu*sc; }
    else            { d_scale2[o] = sc; d_shift2[o] = be[o] - mu*sc; }
}

__global__ void bn_apply_kernel(float* __restrict__ out) {
    int i = blockIdx.x*blockDim.x + threadIdx.x;
    int o = i & 127;
    out[i] = fmaf(out[i], d_scale2[o], d_shift2[o]);
}

// ---------------- launch ----------------
extern "C" void kernel_launch(void* const* d_in, const int* in_sizes, int n_in,
                              void* d_out, int out_size) {
    (void)in_sizes; (void)n_in; (void)out_size;
    const float* x   = (const float*)d_in[0];
    const float* pos = (const float*)d_in[1];
    const float* w1  = (const float*)d_in[2];
    const float* b1  = (const float*)d_in[3];
    const float* w2  = (const float*)d_in[4];
    const float* b2  = (const float*)d_in[5];
    const float* m1  = (const float*)d_in[6];
    const float* mb1 = (const float*)d_in[7];
    const float* m2  = (const float*)d_in[8];
    const float* mb2 = (const float*)d_in[9];
    const float* g1  = (const float*)d_in[10];
    const float* be1 = (const float*)d_in[11];
    const float* g2  = (const float*)d_in[12];
    const float* be2 = (const float*)d_in[13];
    float* out = (float*)d_out;

    const int SMEM_KNN  = 8192 * sizeof(float4);          // 131072
    const int SMEM_UG   = (16768 + 64*132) * 4;           // 100864
    const int SMEM_NB   = 29200 * 4 + 64 * 4;             // 117056
    const int SMEM_GB   = (16384 + 64*132) * 4;           // 99328

    cudaFuncSetAttribute(knn_kernel,          cudaFuncAttributeMaxDynamicSharedMemorySize, SMEM_KNN);
    cudaFuncSetAttribute(u_gemm_kernel,       cudaFuncAttributeMaxDynamicSharedMemorySize, SMEM_UG);
    cudaFuncSetAttribute(neighbor_kernel,     cudaFuncAttributeMaxDynamicSharedMemorySize, SMEM_NB);
    cudaFuncSetAttribute(gemm_bias_kernel,    cudaFuncAttributeMaxDynamicSharedMemorySize, SMEM_GB);
    cudaFuncSetAttribute(gemm_bn_relu_kernel, cudaFuncAttributeMaxDynamicSharedMemorySize, SMEM_GB);

    prep_kernel<<<66, 256>>>(w1, w2, m1, m2);
    knn_kernel<<<64, 256, SMEM_KNN>>>(pos);
    u_gemm_kernel<<<NPTS/64, 256, SMEM_UG>>>(x, pos);
    neighbor_kernel<<<NPTS/4, 256, SMEM_NB>>>(x, b1, b2);
    gemm_bias_kernel<<<NPTS/64, 256, SMEM_GB>>>(mb1);
    stats_kernel<<<128, 128>>>(nullptr, 0);
    bn_finalize_kernel<<<1, 128>>>(g1, be1, 0);
    gemm_bn_relu_kernel<<<NPTS/64, 256, SMEM_GB>>>(mb2, out);
    stats_kernel<<<128, 128>>>(out, 1);
    bn_finalize_kernel<<<1, 128>>>(g2, be2, 1);
    bn_apply_kernel<<<(NPTS*CC)/256, 256>>>(out);
}

// round 2
// speedup vs baseline: 1.4359x; 1.4359x over previous
#include <cuda_runtime.h>
#include <cuda_bf16.h>

// Problem constants
#define BB 2
#define NN 8192
#define CC 128
#define PP 3
#define KK 16
#define NPTS (BB*NN)          // 16384 total points
#define EPS 1e-5f

// ---------------- scratch (static device globals; no allocation) ----------------
__device__ float d_w1t[131*128];     // [c][o]
__device__ float d_w2t[128*128];     // [h][o]
__device__ float d_m1t[128*128];
__device__ float d_m2t[128*128];
__device__ int   d_nbr[NPTS*KK];
__device__ float d_u [NPTS*CC];      // W1 @ [x;pos]
__device__ float d_ux[NPTS*CC];      // W1x @ x (self path)
__device__ float d_res[NPTS*CC];
__device__ float d_t [NPTS*CC];
__device__ float d_p1[128*128];
__device__ float d_p2[128*128];
__device__ float d_scale1[CC], d_shift1[CC], d_scale2[CC], d_shift2[CC];

// ---------------- prep: transpose weight matrices ----------------
__global__ void prep_kernel(const float* __restrict__ w1, const float* __restrict__ w2,
                            const float* __restrict__ m1, const float* __restrict__ m2) {
    int i = blockIdx.x*blockDim.x + threadIdx.x;
    if (i < 131*128) { int o = i/131, c = i%131; d_w1t[c*128+o] = w1[i]; }
    if (i < 128*128) { int o = i>>7, c = i&127;
        d_w2t[c*128+o] = w2[i];
        d_m1t[c*128+o] = m1[i];
        d_m2t[c*128+o] = m2[i];
    }
}

// ---------------- KNN: thread-per-query, full-batch pos in smem ----------------
// 128 blocks x 128 threads -> covers 128 SMs (was 64).
__global__ void knn_kernel(const float* __restrict__ pos) {
    extern __shared__ float4 sp[];               // 8192 float4 = 128KB
    const int b   = blockIdx.x >> 6;             // 64 blocks per batch
    const int blk = blockIdx.x & 63;
    const int tid = threadIdx.x;
    const float* pb = pos + (size_t)b*NN*3;
    for (int j = tid; j < NN; j += 128) {
        float px = pb[j*3+0], py = pb[j*3+1], pz = pb[j*3+2];
        sp[j] = make_float4(px, py, pz, px*px + py*py + pz*pz);
    }
    __syncthreads();
    const int q = blk*128 + tid;
    const float4 qp = sp[q];

    float bd[KK]; int bi[KK];
    #pragma unroll
    for (int t = 0; t < KK; t++) { bd[t] = 3.4e38f; bi[t] = 0; }

    #pragma unroll 2
    for (int j = 0; j < NN; j++) {
        float4 c = sp[j];
        float d = qp.w + c.w - 2.f*(qp.x*c.x + qp.y*c.y + qp.z*c.z);
        if (d < bd[KK-1]) {
            float dd = d; int ii = j;
            #pragma unroll
            for (int t = 0; t < KK; t++) {
                if (dd < bd[t]) {
                    float tf = bd[t]; bd[t] = dd; dd = tf;
                    int   ti = bi[t]; bi[t] = ii; ii = ti;
                }
            }
        }
    }
    int base = (b*NN + q)*KK;
    #pragma unroll
    for (int t = 0; t < KK; t++) d_nbr[base + t] = b*NN + bi[t];
}

// ---------------- u GEMM: u = [x;pos] @ W1^T, ux = x @ W1x^T ----------------
// 512 threads, 128 points/block, thread tile 8 rows x 4 cols.
__global__ void __launch_bounds__(512) u_gemm_kernel(const float* __restrict__ x,
                                                     const float* __restrict__ pos) {
    extern __shared__ float smu[];
    float* wts  = smu;            // 131*128 = 16768
    float* tile = smu + 16768;    // 128*132
    const int tid = threadIdx.x;
    const int g0  = blockIdx.x * 128;
    for (int i = tid; i < 16768; i += 512) wts[i] = d_w1t[i];
    for (int i = tid; i < 128*132; i += 512) {
        int p = i/132, c = i%132;
        int g = g0 + p;
        float v = 0.f;
        if (c < 128)      v = x[(size_t)g*128 + c];
        else if (c < 131) v = pos[(size_t)g*3 + (c-128)];
        tile[i] = v;
    }
    __syncthreads();
    const int rg = tid >> 5, og = tid & 31;     // 16 row-groups x 32 col-groups
    const int r0 = rg*8, o0 = og*4;
    float acc[8][4] = {};
    int c = 0;
    #pragma unroll 4
    for (; c < 128; ++c) {
        float4 w4 = *reinterpret_cast<const float4*>(&wts[c*128 + o0]);
        float hh[8];
        #pragma unroll
        for (int r = 0; r < 8; r++) hh[r] = tile[(r0+r)*132 + c];   // broadcast
        #pragma unroll
        for (int r = 0; r < 8; r++) {
            acc[r][0] = fmaf(hh[r], w4.x, acc[r][0]);
            acc[r][1] = fmaf(hh[r], w4.y, acc[r][1]);
            acc[r][2] = fmaf(hh[r], w4.z, acc[r][2]);
            acc[r][3] = fmaf(hh[r], w4.w, acc[r][3]);
        }
    }
    #pragma unroll
    for (int r = 0; r < 8; r++)
        *reinterpret_cast<float4*>(&d_ux[(size_t)(g0+r0+r)*128 + o0]) =
            make_float4(acc[r][0], acc[r][1], acc[r][2], acc[r][3]);
    for (; c < 131; ++c) {
        float4 w4 = *reinterpret_cast<const float4*>(&wts[c*128 + o0]);
        float hh[8];
        #pragma unroll
        for (int r = 0; r < 8; r++) hh[r] = tile[(r0+r)*132 + c];
        #pragma unroll
        for (int r = 0; r < 8; r++) {
            acc[r][0] = fmaf(hh[r], w4.x, acc[r][0]);
            acc[r][1] = fmaf(hh[r], w4.y, acc[r][1]);
            acc[r][2] = fmaf(hh[r], w4.z, acc[r][2]);
            acc[r][3] = fmaf(hh[r], w4.w, acc[r][3]);
        }
    }
    #pragma unroll
    for (int r = 0; r < 8; r++)
        *reinterpret_cast<float4*>(&d_u[(size_t)(g0+r0+r)*128 + o0]) =
            make_float4(acc[r][0], acc[r][1], acc[r][2], acc[r][3]);
}

// ---------------- fused neighbor kernel (the dominant GEMM) ----------------
// 8 points/block, 512 threads. 128 neighbor rows + 8 self rows.
__global__ void __launch_bounds__(512) neighbor_kernel(const float* __restrict__ x,
                                const float* __restrict__ b1, const float* __restrict__ b2) {
    extern __shared__ float smn[];
    float* w2s  = smn;              // 16384
    float* hid  = w2s  + 16384;     // 136*132 = 17952 (rows 0..127 nbrs, 128..135 self)
    float* ucen = hid  + 17952;     // 8*128
    float* xns  = ucen + 1024;      // 8*128
    float* b1s  = xns  + 1024;      // 128
    float* b2s  = b1s  + 128;       // 128
    float* part = b2s  + 128;       // 16*128 (2 subs per point)
    float* ws   = part + 2048;      // 8*128
    int*   nidx = (int*)(ws + 1024);// 128

    const int tid = threadIdx.x;
    const int g0  = blockIdx.x * 8;

    for (int i = tid; i < 16384; i += 512) w2s[i] = d_w2t[i];
    if (tid < 128) { nidx[tid] = d_nbr[g0*KK + tid]; b1s[tid] = b1[tid]; b2s[tid] = b2[tid]; }
    for (int i = tid; i < 1024; i += 512) {
        int p = i >> 7, c = i & 127;
        ucen[i] = d_u[(size_t)(g0+p)*128 + c];
        xns[i]  = x  [(size_t)(g0+p)*128 + c];
    }
    __syncthreads();

    // build hidden rows: warp-coalesced gather from d_u (float4 per lane)
    {
        const int lane = tid & 31, c0 = lane*4;
        for (int r = tid >> 5; r < 128; r += 16) {
            int p = r >> 4;
            float4 uv = *reinterpret_cast<const float4*>(&d_u[(size_t)nidx[r]*128 + c0]);
            float4 h;
            h.x = fmaxf(uv.x - ucen[p*128 + c0+0] + b1s[c0+0], 0.f);
            h.y = fmaxf(uv.y - ucen[p*128 + c0+1] + b1s[c0+1], 0.f);
            h.z = fmaxf(uv.z - ucen[p*128 + c0+2] + b1s[c0+2], 0.f);
            h.w = fmaxf(uv.w - ucen[p*128 + c0+3] + b1s[c0+3], 0.f);
            *reinterpret_cast<float4*>(&hid[r*132 + c0]) = h;
        }
        if (tid < 256) {
            int p = tid >> 5;
            float4 uv = *reinterpret_cast<const float4*>(&d_ux[(size_t)(g0+p)*128 + c0]);
            float4 h;
            h.x = fmaxf(uv.x + b1s[c0+0], 0.f);
            h.y = fmaxf(uv.y + b1s[c0+1], 0.f);
            h.z = fmaxf(uv.z + b1s[c0+2], 0.f);
            h.w = fmaxf(uv.w + b1s[c0+3], 0.f);
            *reinterpret_cast<float4*>(&hid[(128+p)*132 + c0]) = h;
        }
    }
    __syncthreads();

    // main GEMM: 128 rows x 128 cols, K=128; thread tile 8x4
    const int rg = tid >> 5, og = tid & 31;
    const int r0 = rg*8, o0 = og*4;
    const int p  = rg >> 1, sub = rg & 1;
    float acc[8][4] = {};
    #pragma unroll 4
    for (int c = 0; c < 128; ++c) {
        float4 w4 = *reinterpret_cast<const float4*>(&w2s[c*128 + o0]);
        float hh[8];
        #pragma unroll
        for (int r = 0; r < 8; r++) hh[r] = hid[(r0+r)*132 + c];   // broadcast
        #pragma unroll
        for (int r = 0; r < 8; r++) {
            acc[r][0] = fmaf(hh[r], w4.x, acc[r][0]);
            acc[r][1] = fmaf(hh[r], w4.y, acc[r][1]);
            acc[r][2] = fmaf(hh[r], w4.z, acc[r][2]);
            acc[r][3] = fmaf(hh[r], w4.w, acc[r][3]);
        }
    }

    // sigmoid + gather rel_x + partial K-sum (ascending k within sub)
    float psum[4] = {};
    #pragma unroll
    for (int r = 0; r < 8; r++) {
        int g = nidx[r0 + r];
        float4 xv = *reinterpret_cast<const float4*>(&x[(size_t)g*128 + o0]);
        float xc[4] = {xv.x, xv.y, xv.z, xv.w};
        #pragma unroll
        for (int j = 0; j < 4; j++) {
            float z = acc[r][j] + b2s[o0 + j];
            float s = 1.f/(1.f + __expf(-z));
            psum[j] += (xc[j] - xns[p*128 + o0 + j]) * s;
        }
    }
    {
        float* pp = part + (p*2 + sub)*128 + o0;
        #pragma unroll
        for (int j = 0; j < 4; j++) pp[j] = psum[j];
    }

    // self rows: 8 points x 128 out = 1024 dots (2 per thread)
    for (int t = tid; t < 1024; t += 512) {
        int sp = t >> 7, o = t & 127;
        float a = 0.f;
        #pragma unroll 4
        for (int c = 0; c < 128; c++) a = fmaf(hid[(128+sp)*132 + c], w2s[c*128 + o], a);
        ws[t] = 1.f/(1.f + __expf(-(a + b2s[o])));
    }
    __syncthreads();

    // combine partials (fixed order) and write res
    for (int t = tid; t < 1024; t += 512) {
        int sp = t >> 7, o = t & 127;
        float s = part[(sp*2+0)*128+o] + part[(sp*2+1)*128+o];
        d_res[(size_t)(g0+sp)*128 + o] = xns[t]*(1.f + ws[t]) - s;
    }
}

// ---------------- tail GEMMs: 128 rows/block, 512 threads ----------------
__global__ void __launch_bounds__(512) gemm_bias_kernel(const float* __restrict__ bias) {
    extern __shared__ float smg[];
    float* wts  = smg;           // 16384
    float* tile = smg + 16384;   // 128*132
    const int tid = threadIdx.x, g0 = blockIdx.x*128;
    for (int i = tid; i < 16384; i += 512) wts[i] = d_m1t[i];
    {
        const int lane = tid & 31, c0 = lane*4;
        for (int r = tid >> 5; r < 128; r += 16)
            *reinterpret_cast<float4*>(&tile[r*132 + c0]) =
                *reinterpret_cast<const float4*>(&d_res[(size_t)(g0+r)*128 + c0]);
    }
    __syncthreads();
    const int rg = tid >> 5, og = tid & 31;
    const int r0 = rg*8, o0 = og*4;
    float acc[8][4] = {};
    #pragma unroll 4
    for (int c = 0; c < 128; ++c) {
        float4 w4 = *reinterpret_cast<const float4*>(&wts[c*128 + o0]);
        float hh[8];
        #pragma unroll
        for (int r = 0; r < 8; r++) hh[r] = tile[(r0+r)*132 + c];
        #pragma unroll
        for (int r = 0; r < 8; r++) {
            acc[r][0] = fmaf(hh[r], w4.x, acc[r][0]);
            acc[r][1] = fmaf(hh[r], w4.y, acc[r][1]);
            acc[r][2] = fmaf(hh[r], w4.z, acc[r][2]);
            acc[r][3] = fmaf(hh[r], w4.w, acc[r][3]);
        }
    }
    float4 bb = *reinterpret_cast<const float4*>(&bias[o0]);
    #pragma unroll
    for (int r = 0; r < 8; r++)
        *reinterpret_cast<float4*>(&d_t[(size_t)(g0+r0+r)*128 + o0]) =
            make_float4(acc[r][0]+bb.x, acc[r][1]+bb.y, acc[r][2]+bb.z, acc[r][3]+bb.w);
}

__global__ void __launch_bounds__(512) gemm_bn_relu_kernel(const float* __restrict__ bias,
                                                           float* __restrict__ out) {
    extern __shared__ float smh[];
    float* wts  = smh;
    float* tile = smh + 16384;
    const int tid = threadIdx.x, g0 = blockIdx.x*128;
    for (int i = tid; i < 16384; i += 512) wts[i] = d_m2t[i];
    {
        const int lane = tid & 31, c0 = lane*4;
        for (int r = tid >> 5; r < 128; r += 16) {
            float4 v = *reinterpret_cast<const float4*>(&d_t[(size_t)(g0+r)*128 + c0]);
            float4 h;
            h.x = fmaxf(fmaf(v.x, d_scale1[c0+0], d_shift1[c0+0]), 0.f);
            h.y = fmaxf(fmaf(v.y, d_scale1[c0+1], d_shift1[c0+1]), 0.f);
            h.z = fmaxf(fmaf(v.z, d_scale1[c0+2], d_shift1[c0+2]), 0.f);
            h.w = fmaxf(fmaf(v.w, d_scale1[c0+3], d_shift1[c0+3]), 0.f);
            *reinterpret_cast<float4*>(&tile[r*132 + c0]) = h;
        }
    }
    __syncthreads();
    const int rg = tid >> 5, og = tid & 31;
    const int r0 = rg*8, o0 = og*4;
    float acc[8][4] = {};
    #pragma unroll 4
    for (int c = 0; c < 128; ++c) {
        float4 w4 = *reinterpret_cast<const float4*>(&wts[c*128 + o0]);
        float hh[8];
        #pragma unroll
        for (int r = 0; r < 8; r++) hh[r] = tile[(r0+r)*132 + c];
        #pragma unroll
        for (int r = 0; r < 8; r++) {
            acc[r][0] = fmaf(hh[r], w4.x, acc[r][0]);
            acc[r][1] = fmaf(hh[r], w4.y, acc[r][1]);
            acc[r][2] = fmaf(hh[r], w4.z, acc[r][2]);
            acc[r][3] = fmaf(hh[r], w4.w, acc[r][3]);
        }
    }
    float4 bb = *reinterpret_cast<const float4*>(&bias[o0]);
    #pragma unroll
    for (int r = 0; r < 8; r++)
        *reinterpret_cast<float4*>(&out[(size_t)(g0+r0+r)*128 + o0]) =
            make_float4(acc[r][0]+bb.x, acc[r][1]+bb.y, acc[r][2]+bb.z, acc[r][3]+bb.w);
}

// ---------------- deterministic BN stats (no atomics) ----------------
__global__ void stats_kernel(const float* __restrict__ ext, int use_ext) {
    const float* in = use_ext ? ext : d_t;
    const int blk = blockIdx.x, o = threadIdx.x;
    float s = 0.f, s2 = 0.f;
    for (int r = 0; r < 128; r++) {
        float v = in[(size_t)(blk*128 + r)*128 + o];
        s += v; s2 += v*v;
    }
    d_p1[blk*128 + o] = s;
    d_p2[blk*128 + o] = s2;
}

__global__ void bn_finalize_kernel(const float* __restrict__ g, const float* __restrict__ be,
                                   int which) {
    const int o = threadIdx.x;
    float s = 0.f, s2 = 0.f;
    for (int b = 0; b < 128; b++) { s += d_p1[b*128 + o]; s2 += d_p2[b*128 + o]; }
    float mu  = s  * (1.f/16384.f);
    float var = s2 * (1.f/16384.f) - mu*mu;
    float sc  = g[o] * rsqrtf(var + EPS);
    if (which == 0) { d_scale1[o] = sc; d_shift1[o] = be[o] - mu*sc; }
    else            { d_scale2[o] = sc; d_shift2[o] = be[o] - mu*sc; }
}

__global__ void bn_apply_kernel(float* __restrict__ out) {
    int i = blockIdx.x*blockDim.x + threadIdx.x;
    int o = i & 127;
    out[i] = fmaf(out[i], d_scale2[o], d_shift2[o]);
}

// ---------------- launch ----------------
extern "C" void kernel_launch(void* const* d_in, const int* in_sizes, int n_in,
                              void* d_out, int out_size) {
    (void)in_sizes; (void)n_in; (void)out_size;
    const float* x   = (const float*)d_in[0];
    const float* pos = (const float*)d_in[1];
    const float* w1  = (const float*)d_in[2];
    const float* b1  = (const float*)d_in[3];
    const float* w2  = (const float*)d_in[4];
    const float* b2  = (const float*)d_in[5];
    const float* m1  = (const float*)d_in[6];
    const float* mb1 = (const float*)d_in[7];
    const float* m2  = (const float*)d_in[8];
    const float* mb2 = (const float*)d_in[9];
    const float* g1  = (const float*)d_in[10];
    const float* be1 = (const float*)d_in[11];
    const float* g2  = (const float*)d_in[12];
    const float* be2 = (const float*)d_in[13];
    float* out = (float*)d_out;

    const int SMEM_KNN  = 8192 * sizeof(float4);              // 131072
    const int SMEM_UG   = (16768 + 128*132) * 4;              // 134656
    const int SMEM_NB   = (16384+17952+1024+1024+128+128+2048+1024) * 4 + 128*4; // ~159KB
    const int SMEM_GB   = (16384 + 128*132) * 4;              // 133120

    cudaFuncSetAttribute(knn_kernel,          cudaFuncAttributeMaxDynamicSharedMemorySize, SMEM_KNN);
    cudaFuncSetAttribute(u_gemm_kernel,       cudaFuncAttributeMaxDynamicSharedMemorySize, SMEM_UG);
    cudaFuncSetAttribute(neighbor_kernel,     cudaFuncAttributeMaxDynamicSharedMemorySize, SMEM_NB);
    cudaFuncSetAttribute(gemm_bias_kernel,    cudaFuncAttributeMaxDynamicSharedMemorySize, SMEM_GB);
    cudaFuncSetAttribute(gemm_bn_relu_kernel, cudaFuncAttributeMaxDynamicSharedMemorySize, SMEM_GB);

    prep_kernel<<<66, 256>>>(w1, w2, m1, m2);
    knn_kernel<<<128, 128, SMEM_KNN>>>(pos);
    u_gemm_kernel<<<NPTS/128, 512, SMEM_UG>>>(x, pos);
    neighbor_kernel<<<NPTS/8, 512, SMEM_NB>>>(x, b1, b2);
    gemm_bias_kernel<<<NPTS/128, 512, SMEM_GB>>>(mb1);
    stats_kernel<<<128, 128>>>(nullptr, 0);
    bn_finalize_kernel<<<1, 128>>>(g1, be1, 0);
    gemm_bn_relu_kernel<<<NPTS/128, 512, SMEM_GB>>>(mb2, out);
    stats_kernel<<<128, 128>>>(out, 1);
    bn_finalize_kernel<<<1, 128>>>(g2, be2, 1);
    bn_apply_kernel<<<(NPTS*CC)/256, 256>>>(out);
}

// round 4
// speedup vs baseline: 1.9012x; 1.3240x over previous
#include <cuda_runtime.h>
#include <cuda_bf16.h>

// Problem constants
#define BB 2
#define NN 8192
#define CC 128
#define PP 3
#define KK 16
#define NPTS (BB*NN)          // 16384 total points
#define EPS 1e-5f

// ---------------- scratch (static device globals; no allocation) ----------------
__device__ float d_w1t[131*128];     // [c][o]
__device__ float d_w2t[128*128];     // [h][o]
__device__ float d_m1t[128*128];
__device__ float d_m2t[128*128];
__device__ int   d_nbr[NPTS*KK];
__device__ float d_u [NPTS*CC];      // W1 @ [x;pos]
__device__ float d_ux[NPTS*CC];      // W1x @ x (self path)
__device__ float d_res[NPTS*CC];
__device__ float d_t [NPTS*CC];
__device__ float d_p1[128*128];
__device__ float d_p2[128*128];
__device__ float d_scale1[CC], d_shift1[CC], d_scale2[CC], d_shift2[CC];

// ---------------- prep: transpose weight matrices ----------------
__global__ void prep_kernel(const float* __restrict__ w1, const float* __restrict__ w2,
                            const float* __restrict__ m1, const float* __restrict__ m2) {
    int i = blockIdx.x*blockDim.x + threadIdx.x;
    if (i < 131*128) { int o = i/131, c = i%131; d_w1t[c*128+o] = w1[i]; }
    if (i < 128*128) { int o = i>>7, c = i&127;
        d_w2t[c*128+o] = w2[i];
        d_m1t[c*128+o] = m1[i];
        d_m2t[c*128+o] = m2[i];
    }
}

// ---------------- KNN: 4 threads per query (split-j), stable merge ----------------
// 128 blocks x 512 threads. Each block: 128 queries; thread (seg,ql) scans
// j in [seg*2048, seg*2048+2048). Merge preserves full-scan tie semantics.
__global__ void __launch_bounds__(512) knn_kernel(const float* __restrict__ pos) {
    extern __shared__ float sm[];
    float4* sp = (float4*)sm;            // 8192 float4 = 128KB
    float*  cd = sm + 32768;             // 512*16 dists
    int*    ci = (int*)(cd + 8192);      // 512*16 idx
    const int b   = blockIdx.x >> 6;     // 64 blocks per batch
    const int blk = blockIdx.x & 63;
    const int tid = threadIdx.x;
    const float* pb = pos + (size_t)b*NN*3;
    for (int j = tid; j < NN; j += 512) {
        float px = pb[j*3+0], py = pb[j*3+1], pz = pb[j*3+2];
        sp[j] = make_float4(px, py, pz, px*px + py*py + pz*pz);
    }
    __syncthreads();
    const int ql  = tid & 127;
    const int seg = tid >> 7;            // 0..3
    const int q   = blk*128 + ql;
    const float4 qp = sp[q];

    float bd[KK]; int bi[KK];
    #pragma unroll
    for (int t = 0; t < KK; t++) { bd[t] = 3.4e38f; bi[t] = 0; }

    const int j0 = seg*2048, j1 = j0 + 2048;
    #pragma unroll 2
    for (int j = j0; j < j1; j++) {
        float4 c = sp[j];
        float d = qp.w + c.w - 2.f*(qp.x*c.x + qp.y*c.y + qp.z*c.z);
        if (d < bd[KK-1]) {
            float dd = d; int ii = j;
            #pragma unroll
            for (int t = 0; t < KK; t++) {
                if (dd < bd[t]) {
                    float tf = bd[t]; bd[t] = dd; dd = tf;
                    int   ti = bi[t]; bi[t] = ii; ii = ti;
                }
            }
        }
    }
    {
        int row = tid*16;
        #pragma unroll
        for (int t = 0; t < KK; t++) { cd[row+t] = bd[t]; ci[row+t] = bi[t]; }
    }
    __syncthreads();

    // merge 4 sorted lists per query; on ties prefer lower segment (= lower j)
    if (tid < 128) {
        int p[4] = {0,0,0,0};
        int base[4];
        #pragma unroll
        for (int s = 0; s < 4; s++) base[s] = (s*128 + ql)*16;
        const int obase = (b*NN + q)*KK;
        #pragma unroll
        for (int t = 0; t < KK; t++) {
            float best = 3.5e38f; int bs = 0;
            #pragma unroll
            for (int s = 0; s < 4; s++) {
                float v = (p[s] < 16) ? cd[base[s] + p[s]] : 3.6e38f;
                if (v < best) { best = v; bs = s; }
            }
            d_nbr[obase + t] = b*NN + ci[base[bs] + p[bs]];
            p[bs]++;
        }
    }
}

// ---------------- u GEMM: u = [x;pos] @ W1^T, ux = x @ W1x^T ----------------
__global__ void __launch_bounds__(512) u_gemm_kernel(const float* __restrict__ x,
                                                     const float* __restrict__ pos) {
    extern __shared__ float smu[];
    float* wts  = smu;            // 131*128 = 16768
    float* tile = smu + 16768;    // 128*132
    const int tid = threadIdx.x;
    const int g0  = blockIdx.x * 128;
    for (int i = tid; i < 16768; i += 512) wts[i] = d_w1t[i];
    for (int i = tid; i < 128*132; i += 512) {
        int p = i/132, c = i%132;
        int g = g0 + p;
        float v = 0.f;
        if (c < 128)      v = x[(size_t)g*128 + c];
        else if (c < 131) v = pos[(size_t)g*3 + (c-128)];
        tile[i] = v;
    }
    __syncthreads();
    const int rg = tid >> 5, og = tid & 31;
    const int r0 = rg*8, o0 = og*4;
    float acc[8][4] = {};
    int c = 0;
    #pragma unroll 4
    for (; c < 128; ++c) {
        float4 w4 = *reinterpret_cast<const float4*>(&wts[c*128 + o0]);
        float hh[8];
        #pragma unroll
        for (int r = 0; r < 8; r++) hh[r] = tile[(r0+r)*132 + c];
        #pragma unroll
        for (int r = 0; r < 8; r++) {
            acc[r][0] = fmaf(hh[r], w4.x, acc[r][0]);
            acc[r][1] = fmaf(hh[r], w4.y, acc[r][1]);
            acc[r][2] = fmaf(hh[r], w4.z, acc[r][2]);
            acc[r][3] = fmaf(hh[r], w4.w, acc[r][3]);
        }
    }
    #pragma unroll
    for (int r = 0; r < 8; r++)
        *reinterpret_cast<float4*>(&d_ux[(size_t)(g0+r0+r)*128 + o0]) =
            make_float4(acc[r][0], acc[r][1], acc[r][2], acc[r][3]);
    for (; c < 131; ++c) {
        float4 w4 = *reinterpret_cast<const float4*>(&wts[c*128 + o0]);
        float hh[8];
        #pragma unroll
        for (int r = 0; r < 8; r++) hh[r] = tile[(r0+r)*132 + c];
        #pragma unroll
        for (int r = 0; r < 8; r++) {
            acc[r][0] = fmaf(hh[r], w4.x, acc[r][0]);
            acc[r][1] = fmaf(hh[r], w4.y, acc[r][1]);
            acc[r][2] = fmaf(hh[r], w4.z, acc[r][2]);
            acc[r][3] = fmaf(hh[r], w4.w, acc[r][3]);
        }
    }
    #pragma unroll
    for (int r = 0; r < 8; r++)
        *reinterpret_cast<float4*>(&d_u[(size_t)(g0+r0+r)*128 + o0]) =
            make_float4(acc[r][0], acc[r][1], acc[r][2], acc[r][3]);
}

// ---------------- fused neighbor kernel (the dominant GEMM) ----------------
// 8 points/block, 512 threads. hid stride 136 (16B-aligned rows for LDS.128).
#define HS 136
__global__ void __launch_bounds__(512) neighbor_kernel(const float* __restrict__ x,
                                const float* __restrict__ b1, const float* __restrict__ b2) {
    extern __shared__ float smn[];
    float* w2s  = smn;              // 16384
    float* hid  = w2s  + 16384;     // 136 rows * 136 = 18496 (0..127 nbrs, 128..135 self)
    float* ucen = hid  + 18496;     // 8*128
    float* xns  = ucen + 1024;      // 8*128
    float* b1s  = xns  + 1024;      // 128
    float* b2s  = b1s  + 128;       // 128
    float* part = b2s  + 128;       // 16*128
    float* ws   = part + 2048;      // 8*128
    int*   nidx = (int*)(ws + 1024);// 128

    const int tid = threadIdx.x;
    const int g0  = blockIdx.x * 8;

    for (int i = tid; i < 16384; i += 512) w2s[i] = d_w2t[i];
    if (tid < 128) { nidx[tid] = d_nbr[g0*KK + tid]; b1s[tid] = b1[tid]; b2s[tid] = b2[tid]; }
    for (int i = tid; i < 1024; i += 512) {
        int p = i >> 7, c = i & 127;
        ucen[i] = d_u[(size_t)(g0+p)*128 + c];
        xns[i]  = x  [(size_t)(g0+p)*128 + c];
    }
    __syncthreads();

    // build hidden rows: warp-coalesced gather from d_u (float4 per lane)
    {
        const int lane = tid & 31, c0 = lane*4;
        for (int r = tid >> 5; r < 128; r += 16) {
            int p = r >> 4;
            float4 uv = *reinterpret_cast<const float4*>(&d_u[(size_t)nidx[r]*128 + c0]);
            float4 h;
            h.x = fmaxf(uv.x - ucen[p*128 + c0+0] + b1s[c0+0], 0.f);
            h.y = fmaxf(uv.y - ucen[p*128 + c0+1] + b1s[c0+1], 0.f);
            h.z = fmaxf(uv.z - ucen[p*128 + c0+2] + b1s[c0+2], 0.f);
            h.w = fmaxf(uv.w - ucen[p*128 + c0+3] + b1s[c0+3], 0.f);
            *reinterpret_cast<float4*>(&hid[r*HS + c0]) = h;
        }
        if (tid < 256) {
            int p = tid >> 5;
            float4 uv = *reinterpret_cast<const float4*>(&d_ux[(size_t)(g0+p)*128 + c0]);
            float4 h;
            h.x = fmaxf(uv.x + b1s[c0+0], 0.f);
            h.y = fmaxf(uv.y + b1s[c0+1], 0.f);
            h.z = fmaxf(uv.z + b1s[c0+2], 0.f);
            h.w = fmaxf(uv.w + b1s[c0+3], 0.f);
            *reinterpret_cast<float4*>(&hid[(128+p)*HS + c0]) = h;
        }
    }
    __syncthreads();

    // main GEMM: 128 rows x 128 cols, K=128; thread tile 8x4, k-chunk 4
    const int rg = tid >> 5, og = tid & 31;
    const int r0 = rg*8, o0 = og*4;
    const int p  = rg >> 1, sub = rg & 1;
    float acc[8][4] = {};
    #pragma unroll 2
    for (int c0 = 0; c0 < 128; c0 += 4) {
        float4 wa = *reinterpret_cast<const float4*>(&w2s[(c0+0)*128 + o0]);
        float4 wb = *reinterpret_cast<const float4*>(&w2s[(c0+1)*128 + o0]);
        float4 wc = *reinterpret_cast<const float4*>(&w2s[(c0+2)*128 + o0]);
        float4 wd = *reinterpret_cast<const float4*>(&w2s[(c0+3)*128 + o0]);
        #pragma unroll
        for (int r = 0; r < 8; r++) {
            float4 h = *reinterpret_cast<const float4*>(&hid[(r0+r)*HS + c0]);
            acc[r][0] = fmaf(h.x, wa.x, acc[r][0]);
            acc[r][1] = fmaf(h.x, wa.y, acc[r][1]);
            acc[r][2] = fmaf(h.x, wa.z, acc[r][2]);
            acc[r][3] = fmaf(h.x, wa.w, acc[r][3]);
            acc[r][0] = fmaf(h.y, wb.x, acc[r][0]);
            acc[r][1] = fmaf(h.y, wb.y, acc[r][1]);
            acc[r][2] = fmaf(h.y, wb.z, acc[r][2]);
            acc[r][3] = fmaf(h.y, wb.w, acc[r][3]);
            acc[r][0] = fmaf(h.z, wc.x, acc[r][0]);
            acc[r][1] = fmaf(h.z, wc.y, acc[r][1]);
            acc[r][2] = fmaf(h.z, wc.z, acc[r][2]);
            acc[r][3] = fmaf(h.z, wc.w, acc[r][3]);
            acc[r][0] = fmaf(h.w, wd.x, acc[r][0]);
            acc[r][1] = fmaf(h.w, wd.y, acc[r][1]);
            acc[r][2] = fmaf(h.w, wd.z, acc[r][2]);
            acc[r][3] = fmaf(h.w, wd.w, acc[r][3]);
        }
    }

    // sigmoid + gather rel_x + partial K-sum (ascending k within sub)
    float psum[4] = {};
    #pragma unroll
    for (int r = 0; r < 8; r++) {
        int g = nidx[r0 + r];
        float4 xv = *reinterpret_cast<const float4*>(&x[(size_t)g*128 + o0]);
        float xc[4] = {xv.x, xv.y, xv.z, xv.w};
        #pragma unroll
        for (int j = 0; j < 4; j++) {
            float z = acc[r][j] + b2s[o0 + j];
            float s = 1.f/(1.f + __expf(-z));
            psum[j] += (xc[j] - xns[p*128 + o0 + j]) * s;
        }
    }
    {
        float* pp = part + (p*2 + sub)*128 + o0;
        #pragma unroll
        for (int j = 0; j < 4; j++) pp[j] = psum[j];
    }

    // self rows: 8 points x 128 out = 1024 dots (2 per thread)
    for (int t = tid; t < 1024; t += 512) {
        int sp = t >> 7, o = t & 127;
        float a = 0.f;
        #pragma unroll 4
        for (int c = 0; c < 128; c++) a = fmaf(hid[(128+sp)*HS + c], w2s[c*128 + o], a);
        ws[t] = 1.f/(1.f + __expf(-(a + b2s[o])));
    }
    __syncthreads();

    // combine partials (fixed order) and write res
    for (int t = tid; t < 1024; t += 512) {
        int sp = t >> 7, o = t & 127;
        float s = part[(sp*2+0)*128+o] + part[(sp*2+1)*128+o];
        d_res[(size_t)(g0+sp)*128 + o] = xns[t]*(1.f + ws[t]) - s;
    }
}

// ---------------- tail GEMMs: 128 rows/block, 512 threads ----------------
__global__ void __launch_bounds__(512) gemm_bias_kernel(const float* __restrict__ bias) {
    extern __shared__ float smg[];
    float* wts  = smg;           // 16384
    float* tile = smg + 16384;   // 128*132
    const int tid = threadIdx.x, g0 = blockIdx.x*128;
    for (int i = tid; i < 16384; i += 512) wts[i] = d_m1t[i];
    {
        const int lane = tid & 31, c0 = lane*4;
        for (int r = tid >> 5; r < 128; r += 16)
            *reinterpret_cast<float4*>(&tile[r*132 + c0]) =
                *reinterpret_cast<const float4*>(&d_res[(size_t)(g0+r)*128 + c0]);
    }
    __syncthreads();
    const int rg = tid >> 5, og = tid & 31;
    const int r0 = rg*8, o0 = og*4;
    float acc[8][4] = {};
    #pragma unroll 4
    for (int c = 0; c < 128; ++c) {
        float4 w4 = *reinterpret_cast<const float4*>(&wts[c*128 + o0]);
        float hh[8];
        #pragma unroll
        for (int r = 0; r < 8; r++) hh[r] = tile[(r0+r)*132 + c];
        #pragma unroll
        for (int r = 0; r < 8; r++) {
            acc[r][0] = fmaf(hh[r], w4.x, acc[r][0]);
            acc[r][1] = fmaf(hh[r], w4.y, acc[r][1]);
            acc[r][2] = fmaf(hh[r], w4.z, acc[r][2]);
            acc[r][3] = fmaf(hh[r], w4.w, acc[r][3]);
        }
    }
    float4 bb = *reinterpret_cast<const float4*>(&bias[o0]);
    #pragma unroll
    for (int r = 0; r < 8; r++)
        *reinterpret_cast<float4*>(&d_t[(size_t)(g0+r0+r)*128 + o0]) =
            make_float4(acc[r][0]+bb.x, acc[r][1]+bb.y, acc[r][2]+bb.z, acc[r][3]+bb.w);
}

__global__ void __launch_bounds__(512) gemm_bn_relu_kernel(const float* __restrict__ bias,
                                                           float* __restrict__ out) {
    extern __shared__ float smh[];
    float* wts  = smh;
    float* tile = smh + 16384;
    const int tid = threadIdx.x, g0 = blockIdx.x*128;
    for (int i = tid; i < 16384; i += 512) wts[i] = d_m2t[i];
    {
        const int lane = tid & 31, c0 = lane*4;
        for (int r = tid >> 5; r < 128; r += 16) {
            float4 v = *reinterpret_cast<const float4*>(&d_t[(size_t)(g0+r)*128 + c0]);
            float4 h;
            h.x = fmaxf(fmaf(v.x, d_scale1[c0+0], d_shift1[c0+0]), 0.f);
            h.y = fmaxf(fmaf(v.y, d_scale1[c0+1], d_shift1[c0+1]), 0.f);
            h.z = fmaxf(fmaf(v.z, d_scale1[c0+2], d_shift1[c0+2]), 0.f);
            h.w = fmaxf(fmaf(v.w, d_scale1[c0+3], d_shift1[c0+3]), 0.f);
            *reinterpret_cast<float4*>(&tile[r*132 + c0]) = h;
        }
    }
    __syncthreads();
    const int rg = tid >> 5, og = tid & 31;
    const int r0 = rg*8, o0 = og*4;
    float acc[8][4] = {};
    #pragma unroll 4
    for (int c = 0; c < 128; ++c) {
        float4 w4 = *reinterpret_cast<const float4*>(&wts[c*128 + o0]);
        float hh[8];
        #pragma unroll
        for (int r = 0; r < 8; r++) hh[r] = tile[(r0+r)*132 + c];
        #pragma unroll
        for (int r = 0; r < 8; r++) {
            acc[r][0] = fmaf(hh[r], w4.x, acc[r][0]);
            acc[r][1] = fmaf(hh[r], w4.y, acc[r][1]);
            acc[r][2] = fmaf(hh[r], w4.z, acc[r][2]);
            acc[r][3] = fmaf(hh[r], w4.w, acc[r][3]);
        }
    }
    float4 bb = *reinterpret_cast<const float4*>(&bias[o0]);
    #pragma unroll
    for (int r = 0; r < 8; r++)
        *reinterpret_cast<float4*>(&out[(size_t)(g0+r0+r)*128 + o0]) =
            make_float4(acc[r][0]+bb.x, acc[r][1]+bb.y, acc[r][2]+bb.z, acc[r][3]+bb.w);
}

// ---------------- deterministic BN stats (no atomics) ----------------
__global__ void stats_kernel(const float* __restrict__ ext, int use_ext) {
    const float* in = use_ext ? ext : d_t;
    const int blk = blockIdx.x, o = threadIdx.x;
    float s = 0.f, s2 = 0.f;
    for (int r = 0; r < 128; r++) {
        float v = in[(size_t)(blk*128 + r)*128 + o];
        s += v; s2 += v*v;
    }
    d_p1[blk*128 + o] = s;
    d_p2[blk*128 + o] = s2;
}

__global__ void bn_finalize_kernel(const float* __restrict__ g, const float* __restrict__ be,
                                   int which) {
    const int o = threadIdx.x;
    float s = 0.f, s2 = 0.f;
    for (int b = 0; b < 128; b++) { s += d_p1[b*128 + o]; s2 += d_p2[b*128 + o]; }
    float mu  = s  * (1.f/16384.f);
    float var = s2 * (1.f/16384.f) - mu*mu;
    float sc  = g[o] * rsqrtf(var + EPS);
    if (which == 0) { d_scale1[o] = sc; d_shift1[o] = be[o] - mu*sc; }
    else            { d_scale2[o] = sc; d_shift2[o] = be[o] - mu*sc; }
}

__global__ void bn_apply_kernel(float* __restrict__ out) {
    int i = blockIdx.x*blockDim.x + threadIdx.x;
    int o = i & 127;
    out[i] = fmaf(out[i], d_scale2[o], d_shift2[o]);
}

// ---------------- launch ----------------
extern "C" void kernel_launch(void* const* d_in, const int* in_sizes, int n_in,
                              void* d_out, int out_size) {
    (void)in_sizes; (void)n_in; (void)out_size;
    const float* x   = (const float*)d_in[0];
    const float* pos = (const float*)d_in[1];
    const float* w1  = (const float*)d_in[2];
    const float* b1  = (const float*)d_in[3];
    const float* w2  = (const float*)d_in[4];
    const float* b2  = (const float*)d_in[5];
    const float* m1  = (const float*)d_in[6];
    const float* mb1 = (const float*)d_in[7];
    const float* m2  = (const float*)d_in[8];
    const float* mb2 = (const float*)d_in[9];
    const float* g1  = (const float*)d_in[10];
    const float* be1 = (const float*)d_in[11];
    const float* g2  = (const float*)d_in[12];
    const float* be2 = (const float*)d_in[13];
    float* out = (float*)d_out;

    const int SMEM_KNN  = (32768 + 8192 + 8192) * 4;          // 196608
    const int SMEM_UG   = (16768 + 128*132) * 4;              // 134656
    const int SMEM_NB   = (16384+18496+1024+1024+128+128+2048+1024) * 4 + 128*4; // ~161.7KB
    const int SMEM_GB   = (16384 + 128*132) * 4;              // 133120

    cudaFuncSetAttribute(knn_kernel,          cudaFuncAttributeMaxDynamicSharedMemorySize, SMEM_KNN);
    cudaFuncSetAttribute(u_gemm_kernel,       cudaFuncAttributeMaxDynamicSharedMemorySize, SMEM_UG);
    cudaFuncSetAttribute(neighbor_kernel,     cudaFuncAttributeMaxDynamicSharedMemorySize, SMEM_NB);
    cudaFuncSetAttribute(gemm_bias_kernel,    cudaFuncAttributeMaxDynamicSharedMemorySize, SMEM_GB);
    cudaFuncSetAttribute(gemm_bn_relu_kernel, cudaFuncAttributeMaxDynamicSharedMemorySize, SMEM_GB);

    prep_kernel<<<66, 256>>>(w1, w2, m1, m2);
    knn_kernel<<<128, 512, SMEM_KNN>>>(pos);
    u_gemm_kernel<<<NPTS/128, 512, SMEM_UG>>>(x, pos);
    neighbor_kernel<<<NPTS/8, 512, SMEM_NB>>>(x, b1, b2);
    gemm_bias_kernel<<<NPTS/128, 512, SMEM_GB>>>(mb1);
    stats_kernel<<<128, 128>>>(nullptr, 0);
    bn_finalize_kernel<<<1, 128>>>(g1, be1, 0);
    gemm_bn_relu_kernel<<<NPTS/128, 512, SMEM_GB>>>(mb2, out);
    stats_kernel<<<128, 128>>>(out, 1);
    bn_finalize_kernel<<<1, 128>>>(g2, be2, 1);
    bn_apply_kernel<<<(NPTS*CC)/256, 256>>>(out);
}

// round 6
// speedup vs baseline: 2.0073x; 1.0558x over previous
#include <cuda_runtime.h>
#include <cuda_bf16.h>
#include <cstdint>

// Problem constants
#define BB 2
#define NN 8192
#define CC 128
#define PP 3
#define KK 16
#define NPTS (BB*NN)          // 16384 total points
#define EPS 1e-5f

#define WS2 136               // bf16 row stride for MMA operands (conflict-free)

// ---------------- scratch (static device globals; no allocation) ----------------
__device__ float d_w1t[131*128];     // [c][o]
__device__ float d_w2t[128*128];     // [h][o]  (for self_gemm)
__device__ float d_m1t[128*128];
__device__ float d_m2t[128*128];
__device__ __nv_bfloat16 d_w2h[128*WS2];  // w2 hi-split, [n][k] stride 136
__device__ __nv_bfloat16 d_w2l[128*WS2];  // w2 lo-split
__device__ int   d_nbr[NPTS*KK];
__device__ float d_u [NPTS*CC];      // W1 @ [x;pos]
__device__ float d_ux[NPTS*CC];      // W1x @ x (self path)
__device__ float d_wself[NPTS*CC];   // sigmoid(W2 relu(ux+b1) + b2)
__device__ float d_res[NPTS*CC];
__device__ float d_t [NPTS*CC];
__device__ float d_p1[128*128];
__device__ float d_p2[128*128];
__device__ float d_scale1[CC], d_shift1[CC], d_scale2[CC], d_shift2[CC];

// ---------------- mma.sync helper (baseline PTX, works on compute_103) ----------------
__device__ __forceinline__ void mma16816(float* c, const uint32_t* a, const uint32_t* b) {
    asm volatile(
        "mma.sync.aligned.m16n8k16.row.col.f32.bf16.bf16.f32 "
        "{%0,%1,%2,%3}, {%4,%5,%6,%7}, {%8,%9}, {%0,%1,%2,%3};"
        : "+f"(c[0]), "+f"(c[1]), "+f"(c[2]), "+f"(c[3])
        : "r"(a[0]), "r"(a[1]), "r"(a[2]), "r"(a[3]), "r"(b[0]), "r"(b[1]));
}

// ---------------- prep: transpose weights + build w2 bf16 splits ----------------
__global__ void prep_kernel(const float* __restrict__ w1, const float* __restrict__ w2,
                            const float* __restrict__ m1, const float* __restrict__ m2) {
    int i = blockIdx.x*blockDim.x + threadIdx.x;
    if (i < 131*128) { int o = i/131, c = i%131; d_w1t[c*128+o] = w1[i]; }
    if (i < 128*128) { int o = i>>7, c = i&127;
        d_w2t[c*128+o] = w2[i];
        d_m1t[c*128+o] = m1[i];
        d_m2t[c*128+o] = m2[i];
        float w = w2[i];
        __nv_bfloat16 hi = __float2bfloat16(w);
        __nv_bfloat16 lo = __float2bfloat16(w - __bfloat162float(hi));
        d_w2h[o*WS2 + c] = hi;      // [n][k]
        d_w2l[o*WS2 + c] = lo;
    }
}

// ---------------- KNN: 4 threads per query (split-j), stable merge ----------------
__global__ void __launch_bounds__(512) knn_kernel(const float* __restrict__ pos) {
    extern __shared__ float sm[];
    float4* sp = (float4*)sm;            // 8192 float4 = 128KB
    float*  cd = sm + 32768;             // 512*16 dists
    int*    ci = (int*)(cd + 8192);      // 512*16 idx
    const int b   = blockIdx.x >> 6;
    const int blk = blockIdx.x & 63;
    const int tid = threadIdx.x;
    const float* pb = pos + (size_t)b*NN*3;
    for (int j = tid; j < NN; j += 512) {
        float px = pb[j*3+0], py = pb[j*3+1], pz = pb[j*3+2];
        sp[j] = make_float4(px, py, pz, px*px + py*py + pz*pz);
    }
    __syncthreads();
    const int ql  = tid & 127;
    const int seg = tid >> 7;
    const int q   = blk*128 + ql;
    const float4 qp = sp[q];

    float bd[KK]; int bi[KK];
    #pragma unroll
    for (int t = 0; t < KK; t++) { bd[t] = 3.4e38f; bi[t] = 0; }

    const int j0 = seg*2048, j1 = j0 + 2048;
    #pragma unroll 2
    for (int j = j0; j < j1; j++) {
        float4 c = sp[j];
        float d = qp.w + c.w - 2.f*(qp.x*c.x + qp.y*c.y + qp.z*c.z);
        if (d < bd[KK-1]) {
            float dd = d; int ii = j;
            #pragma unroll
            for (int t = 0; t < KK; t++) {
                if (dd < bd[t]) {
                    float tf = bd[t]; bd[t] = dd; dd = tf;
                    int   ti = bi[t]; bi[t] = ii; ii = ti;
                }
            }
        }
    }
    {
        int row = tid*16;
        #pragma unroll
        for (int t = 0; t < KK; t++) { cd[row+t] = bd[t]; ci[row+t] = bi[t]; }
    }
    __syncthreads();

    if (tid < 128) {
        int p[4] = {0,0,0,0};
        int base[4];
        #pragma unroll
        for (int s = 0; s < 4; s++) base[s] = (s*128 + ql)*16;
        const int obase = (b*NN + q)*KK;
        #pragma unroll
        for (int t = 0; t < KK; t++) {
            float best = 3.5e38f; int bs = 0;
            #pragma unroll
            for (int s = 0; s < 4; s++) {
                float v = (p[s] < 16) ? cd[base[s] + p[s]] : 3.6e38f;
                if (v < best) { best = v; bs = s; }
            }
            d_nbr[obase + t] = b*NN + ci[base[bs] + p[bs]];
            p[bs]++;
        }
    }
}

// ---------------- u GEMM: u = [x;pos] @ W1^T, ux = x @ W1x^T ----------------
__global__ void __launch_bounds__(512) u_gemm_kernel(const float* __restrict__ x,
                                                     const float* __restrict__ pos) {
    extern __shared__ float smu[];
    float* wts  = smu;            // 131*128
    float* tile = smu + 16768;    // 128*132
    const int tid = threadIdx.x;
    const int g0  = blockIdx.x * 128;
    for (int i = tid; i < 16768; i += 512) wts[i] = d_w1t[i];
    for (int i = tid; i < 128*132; i += 512) {
        int p = i/132, c = i%132;
        int g = g0 + p;
        float v = 0.f;
        if (c < 128)      v = x[(size_t)g*128 + c];
        else if (c < 131) v = pos[(size_t)g*3 + (c-128)];
        tile[i] = v;
    }
    __syncthreads();
    const int rg = tid >> 5, og = tid & 31;
    const int r0 = rg*8, o0 = og*4;
    float acc[8][4] = {};
    int c = 0;
    #pragma unroll 4
    for (; c < 128; ++c) {
        float4 w4 = *reinterpret_cast<const float4*>(&wts[c*128 + o0]);
        float hh[8];
        #pragma unroll
        for (int r = 0; r < 8; r++) hh[r] = tile[(r0+r)*132 + c];
        #pragma unroll
        for (int r = 0; r < 8; r++) {
            acc[r][0] = fmaf(hh[r], w4.x, acc[r][0]);
            acc[r][1] = fmaf(hh[r], w4.y, acc[r][1]);
            acc[r][2] = fmaf(hh[r], w4.z, acc[r][2]);
            acc[r][3] = fmaf(hh[r], w4.w, acc[r][3]);
        }
    }
    #pragma unroll
    for (int r = 0; r < 8; r++)
        *reinterpret_cast<float4*>(&d_ux[(size_t)(g0+r0+r)*128 + o0]) =
            make_float4(acc[r][0], acc[r][1], acc[r][2], acc[r][3]);
    for (; c < 131; ++c) {
        float4 w4 = *reinterpret_cast<const float4*>(&wts[c*128 + o0]);
        float hh[8];
        #pragma unroll
        for (int r = 0; r < 8; r++) hh[r] = tile[(r0+r)*132 + c];
        #pragma unroll
        for (int r = 0; r < 8; r++) {
            acc[r][0] = fmaf(hh[r], w4.x, acc[r][0]);
            acc[r][1] = fmaf(hh[r], w4.y, acc[r][1]);
            acc[r][2] = fmaf(hh[r], w4.z, acc[r][2]);
            acc[r][3] = fmaf(hh[r], w4.w, acc[r][3]);
        }
    }
    #pragma unroll
    for (int r = 0; r < 8; r++)
        *reinterpret_cast<float4*>(&d_u[(size_t)(g0+r0+r)*128 + o0]) =
            make_float4(acc[r][0], acc[r][1], acc[r][2], acc[r][3]);
}

// ---------------- self weights GEMM: wself = sigmoid(W2 relu(ux+b1) + b2) ----------------
__global__ void __launch_bounds__(512) self_gemm_kernel(const float* __restrict__ b1,
                                                        const float* __restrict__ b2) {
    extern __shared__ float sms[];
    float* wts  = sms;           // 16384
    float* tile = sms + 16384;   // 128*132
    const int tid = threadIdx.x, g0 = blockIdx.x*128;
    for (int i = tid; i < 16384; i += 512) wts[i] = d_w2t[i];
    {
        const int lane = tid & 31, c0 = lane*4;
        for (int r = tid >> 5; r < 128; r += 16) {
            float4 v = *reinterpret_cast<const float4*>(&d_ux[(size_t)(g0+r)*128 + c0]);
            float4 h;
            h.x = fmaxf(v.x + b1[c0+0], 0.f);
            h.y = fmaxf(v.y + b1[c0+1], 0.f);
            h.z = fmaxf(v.z + b1[c0+2], 0.f);
            h.w = fmaxf(v.w + b1[c0+3], 0.f);
            *reinterpret_cast<float4*>(&tile[r*132 + c0]) = h;
        }
    }
    __syncthreads();
    const int rg = tid >> 5, og = tid & 31;
    const int r0 = rg*8, o0 = og*4;
    float acc[8][4] = {};
    #pragma unroll 4
    for (int c = 0; c < 128; ++c) {
        float4 w4 = *reinterpret_cast<const float4*>(&wts[c*128 + o0]);
        float hh[8];
        #pragma unroll
        for (int r = 0; r < 8; r++) hh[r] = tile[(r0+r)*132 + c];
        #pragma unroll
        for (int r = 0; r < 8; r++) {
            acc[r][0] = fmaf(hh[r], w4.x, acc[r][0]);
            acc[r][1] = fmaf(hh[r], w4.y, acc[r][1]);
            acc[r][2] = fmaf(hh[r], w4.z, acc[r][2]);
            acc[r][3] = fmaf(hh[r], w4.w, acc[r][3]);
        }
    }
    float4 bb = *reinterpret_cast<const float4*>(&b2[o0]);
    #pragma unroll
    for (int r = 0; r < 8; r++) {
        float4 o4;
        o4.x = 1.f/(1.f + __expf(-(acc[r][0]+bb.x)));
        o4.y = 1.f/(1.f + __expf(-(acc[r][1]+bb.y)));
        o4.z = 1.f/(1.f + __expf(-(acc[r][2]+bb.z)));
        o4.w = 1.f/(1.f + __expf(-(acc[r][3]+bb.w)));
        *reinterpret_cast<float4*>(&d_wself[(size_t)(g0+r0+r)*128 + o0]) = o4;
    }
}

// ---------------- fused neighbor kernel: mma.sync bf16-split GEMM ----------------
// 8 points/block, 512 threads (16 warps, 4x4 warp-tile grid of 32x32 tiles).
// z[128,128] = hid @ w2^T via 3 split terms; epilogue does sigmoid+gather+reduce.
// SMEM byte map:
#define NB_WH   0                 // 34816  w2 hi  [n][k] bf16 stride 136
#define NB_WL   34816             // 34816  w2 lo
#define NB_AH   69632             // 34816  hid hi [m][k]
#define NB_AL   104448            // 34816  hid lo          (AH..AL end 139264)
#define NB_XG   69632             // 67584  gathered x fp32 [128][132] (reuses AH/AL)
#define NB_XNS  139264            // 4096
#define NB_B1   143360            // 512
#define NB_B2   143872            // 512
#define NB_NIDX 144384            // 512
#define NB_UCEN 144896            // 4096
#define NB_SMEM 148992

__global__ void __launch_bounds__(512) neighbor_kernel(const float* __restrict__ x,
                                const float* __restrict__ b1, const float* __restrict__ b2) {
    extern __shared__ char smem[];
    __nv_bfloat16* WH = (__nv_bfloat16*)(smem + NB_WH);
    __nv_bfloat16* WL = (__nv_bfloat16*)(smem + NB_WL);
    __nv_bfloat16* AH = (__nv_bfloat16*)(smem + NB_AH);
    __nv_bfloat16* AL = (__nv_bfloat16*)(smem + NB_AL);
    float* xg   = (float*)(smem + NB_XG);
    float* xns  = (float*)(smem + NB_XNS);
    float* b1s  = (float*)(smem + NB_B1);
    float* b2s  = (float*)(smem + NB_B2);
    int*   nidx = (int*)  (smem + NB_NIDX);
    float* ucen = (float*)(smem + NB_UCEN);

    const int tid  = threadIdx.x;
    const int wid  = tid >> 5;
    const int lane = tid & 31;
    const int g0   = blockIdx.x * 8;

    // load w2 splits (16B copies; device globals are zero-initialized so pad is defined)
    {
        const uint4* whg = (const uint4*)d_w2h;
        const uint4* wlg = (const uint4*)d_w2l;
        uint4* whs = (uint4*)WH;
        uint4* wls = (uint4*)WL;
        for (int i = tid; i < 2176; i += 512) { whs[i] = whg[i]; wls[i] = wlg[i]; }
    }
    if (tid < 128) { nidx[tid] = d_nbr[g0*KK + tid]; b1s[tid] = b1[tid]; b2s[tid] = b2[tid]; }
    for (int i = tid; i < 1024; i += 512) {
        int p = i >> 7, c = i & 127;
        ucen[i] = d_u[(size_t)(g0+p)*128 + c];
        xns[i]  = x  [(size_t)(g0+p)*128 + c];
    }
    __syncthreads();

    // build hidden rows -> bf16 hi/lo splits [m][k]
    {
        const int c0 = lane*4;
        for (int r = wid; r < 128; r += 16) {
            int p = r >> 4;
            float4 uv = *reinterpret_cast<const float4*>(&d_u[(size_t)nidx[r]*128 + c0]);
            float h0 = fmaxf(uv.x - ucen[p*128 + c0+0] + b1s[c0+0], 0.f);
            float h1 = fmaxf(uv.y - ucen[p*128 + c0+1] + b1s[c0+1], 0.f);
            float h2 = fmaxf(uv.z - ucen[p*128 + c0+2] + b1s[c0+2], 0.f);
            float h3 = fmaxf(uv.w - ucen[p*128 + c0+3] + b1s[c0+3], 0.f);
            __nv_bfloat162 hA = __floats2bfloat162_rn(h0, h1);
            __nv_bfloat162 hB = __floats2bfloat162_rn(h2, h3);
            __nv_bfloat162 lA = __floats2bfloat162_rn(h0 - __low2float(hA), h1 - __high2float(hA));
            __nv_bfloat162 lB = __floats2bfloat162_rn(h2 - __low2float(hB), h3 - __high2float(hB));
            *(__nv_bfloat162*)&AH[r*WS2 + c0]     = hA;
            *(__nv_bfloat162*)&AH[r*WS2 + c0 + 2] = hB;
            *(__nv_bfloat162*)&AL[r*WS2 + c0]     = lA;
            *(__nv_bfloat162*)&AL[r*WS2 + c0 + 2] = lB;
        }
    }
    __syncthreads();

    // warp-tiled GEMM: warp (wm, wn) computes rows m0..m0+31, cols n0..n0+31
    const int wm = wid >> 2, wn = wid & 3;
    const int m0 = wm*32, n0 = wn*32;
    const int rA = lane >> 2;          // fragment row group
    const int kA = (lane & 3) * 2;     // fragment k offset
    float acc[2][4][4];
    #pragma unroll
    for (int mt = 0; mt < 2; mt++)
        #pragma unroll
        for (int nt = 0; nt < 4; nt++)
            #pragma unroll
            for (int q = 0; q < 4; q++) acc[mt][nt][q] = 0.f;

    const __nv_bfloat16* Aterm[3] = {AH, AH, AL};
    const __nv_bfloat16* Bterm[3] = {WH, WL, WH};
    #pragma unroll
    for (int term = 0; term < 3; term++) {
        const __nv_bfloat16* A = Aterm[term];
        const __nv_bfloat16* B = Bterm[term];
        #pragma unroll
        for (int kk = 0; kk < 128; kk += 16) {
            uint32_t a[2][4], bfr[4][2];
            #pragma unroll
            for (int mt = 0; mt < 2; mt++) {
                const __nv_bfloat16* ap = A + (m0 + mt*16 + rA)*WS2 + kk + kA;
                a[mt][0] = *(const uint32_t*)ap;
                a[mt][1] = *(const uint32_t*)(ap + 8*WS2);
                a[mt][2] = *(const uint32_t*)(ap + 8);
                a[mt][3] = *(const uint32_t*)(ap + 8*WS2 + 8);
            }
            #pragma unroll
            for (int nt = 0; nt < 4; nt++) {
                const __nv_bfloat16* bp = B + (n0 + nt*8 + rA)*WS2 + kk + kA;
                bfr[nt][0] = *(const uint32_t*)bp;
                bfr[nt][1] = *(const uint32_t*)(bp + 8);
            }
            #pragma unroll
            for (int mt = 0; mt < 2; mt++)
                #pragma unroll
                for (int nt = 0; nt < 4; nt++)
                    mma16816(acc[mt][nt], a[mt], bfr[nt]);
        }
    }
    __syncthreads();   // done with AH/AL -> reuse as xg

    // gather neighbor x rows into smem (coalesced)
    {
        const int c0 = lane*4;
        for (int r = wid; r < 128; r += 16)
            *reinterpret_cast<float4*>(&xg[r*132 + c0]) =
                *reinterpret_cast<const float4*>(&x[(size_t)nidx[r]*128 + c0]);
    }
    __syncthreads();

    // epilogue: sigmoid, weight rel_x, reduce 16 rows, write res
    #pragma unroll
    for (int mt = 0; mt < 2; mt++) {
        const int p  = wm*2 + mt;
        const int r0 = m0 + mt*16 + rA;
        const int r1 = r0 + 8;
        #pragma unroll
        for (int nt = 0; nt < 4; nt++) {
            const int col0 = n0 + nt*8 + (lane & 3)*2;
            float z00 = acc[mt][nt][0] + b2s[col0];
            float z01 = acc[mt][nt][1] + b2s[col0+1];
            float z10 = acc[mt][nt][2] + b2s[col0];
            float z11 = acc[mt][nt][3] + b2s[col0+1];
            float s00 = 1.f/(1.f + __expf(-z00));
            float s01 = 1.f/(1.f + __expf(-z01));
            float s10 = 1.f/(1.f + __expf(-z10));
            float s11 = 1.f/(1.f + __expf(-z11));
            float xc0 = xns[p*128 + col0], xc1 = xns[p*128 + col0+1];
            float t0 = (xg[r0*132 + col0]   - xc0)*s00 + (xg[r1*132 + col0]   - xc0)*s10;
            float t1 = (xg[r0*132 + col0+1] - xc1)*s01 + (xg[r1*132 + col0+1] - xc1)*s11;
            t0 += __shfl_xor_sync(0xffffffffu, t0, 4);
            t0 += __shfl_xor_sync(0xffffffffu, t0, 8);
            t0 += __shfl_xor_sync(0xffffffffu, t0, 16);
            t1 += __shfl_xor_sync(0xffffffffu, t1, 4);
            t1 += __shfl_xor_sync(0xffffffffu, t1, 8);
            t1 += __shfl_xor_sync(0xffffffffu, t1, 16);
            if (lane < 4) {
                const size_t ob = (size_t)(g0+p)*128;
                float w0 = d_wself[ob + col0], w1 = d_wself[ob + col0+1];
                d_res[ob + col0]   = xc0*(1.f + w0) - t0;
                d_res[ob + col0+1] = xc1*(1.f + w1) - t1;
            }
        }
    }
}

// ---------------- tail GEMMs: 128 rows/block, 512 threads ----------------
__global__ void __launch_bounds__(512) gemm_bias_kernel(const float* __restrict__ bias) {
    extern __shared__ float smg[];
    float* wts  = smg;           // 16384
    float* tile = smg + 16384;   // 128*132
    const int tid = threadIdx.x, g0 = blockIdx.x*128;
    for (int i = tid; i < 16384; i += 512) wts[i] = d_m1t[i];
    {
        const int lane = tid & 31, c0 = lane*4;
        for (int r = tid >> 5; r < 128; r += 16)
            *reinterpret_cast<float4*>(&tile[r*132 + c0]) =
                *reinterpret_cast<const float4*>(&d_res[(size_t)(g0+r)*128 + c0]);
    }
    __syncthreads();
    const int rg = tid >> 5, og = tid & 31;
    const int r0 = rg*8, o0 = og*4;
    float acc[8][4] = {};
    #pragma unroll 4
    for (int c = 0; c < 128; ++c) {
        float4 w4 = *reinterpret_cast<const float4*>(&wts[c*128 + o0]);
        float hh[8];
        #pragma unroll
        for (int r = 0; r < 8; r++) hh[r] = tile[(r0+r)*132 + c];
        #pragma unroll
        for (int r = 0; r < 8; r++) {
            acc[r][0] = fmaf(hh[r], w4.x, acc[r][0]);
            acc[r][1] = fmaf(hh[r], w4.y, acc[r][1]);
            acc[r][2] = fmaf(hh[r], w4.z, acc[r][2]);
            acc[r][3] = fmaf(hh[r], w4.w, acc[r][3]);
        }
    }
    float4 bb = *reinterpret_cast<const float4*>(&bias[o0]);
    #pragma unroll
    for (int r = 0; r < 8; r++)
        *reinterpret_cast<float4*>(&d_t[(size_t)(g0+r0+r)*128 + o0]) =
            make_float4(acc[r][0]+bb.x, acc[r][1]+bb.y, acc[r][2]+bb.z, acc[r][3]+bb.w);
}

__global__ void __launch_bounds__(512) gemm_bn_relu_kernel(const float* __restrict__ bias,
                                                           float* __restrict__ out) {
    extern __shared__ float smh[];
    float* wts  = smh;
    float* tile = smh + 16384;
    const int tid = threadIdx.x, g0 = blockIdx.x*128;
    for (int i = tid; i < 16384; i += 512) wts[i] = d_m2t[i];
    {
        const int lane = tid & 31, c0 = lane*4;
        for (int r = tid >> 5; r < 128; r += 16) {
            float4 v = *reinterpret_cast<const float4*>(&d_t[(size_t)(g0+r)*128 + c0]);
            float4 h;
            h.x = fmaxf(fmaf(v.x, d_scale1[c0+0], d_shift1[c0+0]), 0.f);
            h.y = fmaxf(fmaf(v.y, d_scale1[c0+1], d_shift1[c0+1]), 0.f);
            h.z = fmaxf(fmaf(v.z, d_scale1[c0+2], d_shift1[c0+2]), 0.f);
            h.w = fmaxf(fmaf(v.w, d_scale1[c0+3], d_shift1[c0+3]), 0.f);
            *reinterpret_cast<float4*>(&tile[r*132 + c0]) = h;
        }
    }
    __syncthreads();
    const int rg = tid >> 5, og = tid & 31;
    const int r0 = rg*8, o0 = og*4;
    float acc[8][4] = {};
    #pragma unroll 4
    for (int c = 0; c < 128; ++c) {
        float4 w4 = *reinterpret_cast<const float4*>(&wts[c*128 + o0]);
        float hh[8];
        #pragma unroll
        for (int r = 0; r < 8; r++) hh[r] = tile[(r0+r)*132 + c];
        #pragma unroll
        for (int r = 0; r < 8; r++) {
            acc[r][0] = fmaf(hh[r], w4.x, acc[r][0]);
            acc[r][1] = fmaf(hh[r], w4.y, acc[r][1]);
            acc[r][2] = fmaf(hh[r], w4.z, acc[r][2]);
            acc[r][3] = fmaf(hh[r], w4.w, acc[r][3]);
        }
    }
    float4 bb = *reinterpret_cast<const float4*>(&bias[o0]);
    #pragma unroll
    for (int r = 0; r < 8; r++)
        *reinterpret_cast<float4*>(&out[(size_t)(g0+r0+r)*128 + o0]) =
            make_float4(acc[r][0]+bb.x, acc[r][1]+bb.y, acc[r][2]+bb.z, acc[r][3]+bb.w);
}

// ---------------- deterministic BN stats (no atomics) ----------------
__global__ void stats_kernel(const float* __restrict__ ext, int use_ext) {
    const float* in = use_ext ? ext : d_t;
    const int blk = blockIdx.x, o = threadIdx.x;
    float s = 0.f, s2 = 0.f;
    for (int r = 0; r < 128; r++) {
        float v = in[(size_t)(blk*128 + r)*128 + o];
        s += v; s2 += v*v;
    }
    d_p1[blk*128 + o] = s;
    d_p2[blk*128 + o] = s2;
}

__global__ void bn_finalize_kernel(const float* __restrict__ g, const float* __restrict__ be,
                                   int which) {
    const int o = threadIdx.x;
    float s = 0.f, s2 = 0.f;
    for (int b = 0; b < 128; b++) { s += d_p1[b*128 + o]; s2 += d_p2[b*128 + o]; }
    float mu  = s  * (1.f/16384.f);
    float var = s2 * (1.f/16384.f) - mu*mu;
    float sc  = g[o] * rsqrtf(var + EPS);
    if (which == 0) { d_scale1[o] = sc; d_shift1[o] = be[o] - mu*sc; }
    else            { d_scale2[o] = sc; d_shift2[o] = be[o] - mu*sc; }
}

__global__ void bn_apply_kernel(float* __restrict__ out) {
    int i = blockIdx.x*blockDim.x + threadIdx.x;
    int o = i & 127;
    out[i] = fmaf(out[i], d_scale2[o], d_shift2[o]);
}

// ---------------- launch ----------------
extern "C" void kernel_launch(void* const* d_in, const int* in_sizes, int n_in,
                              void* d_out, int out_size) {
    (void)in_sizes; (void)n_in; (void)out_size;
    const float* x   = (const float*)d_in[0];
    const float* pos = (const float*)d_in[1];
    const float* w1  = (const float*)d_in[2];
    const float* b1  = (const float*)d_in[3];
    const float* w2  = (const float*)d_in[4];
    const float* b2  = (const float*)d_in[5];
    const float* m1  = (const float*)d_in[6];
    const float* mb1 = (const float*)d_in[7];
    const float* m2  = (const float*)d_in[8];
    const float* mb2 = (const float*)d_in[9];
    const float* g1  = (const float*)d_in[10];
    const float* be1 = (const float*)d_in[11];
    const float* g2  = (const float*)d_in[12];
    const float* be2 = (const float*)d_in[13];
    float* out = (float*)d_out;

    const int SMEM_KNN  = (32768 + 8192 + 8192) * 4;          // 196608
    const int SMEM_UG   = (16768 + 128*132) * 4;              // 134656
    const int SMEM_NB   = NB_SMEM;                            // 148992
    const int SMEM_GB   = (16384 + 128*132) * 4;              // 133120

    cudaFuncSetAttribute(knn_kernel,          cudaFuncAttributeMaxDynamicSharedMemorySize, SMEM_KNN);
    cudaFuncSetAttribute(u_gemm_kernel,       cudaFuncAttributeMaxDynamicSharedMemorySize, SMEM_UG);
    cudaFuncSetAttribute(self_gemm_kernel,    cudaFuncAttributeMaxDynamicSharedMemorySize, SMEM_GB);
    cudaFuncSetAttribute(neighbor_kernel,     cudaFuncAttributeMaxDynamicSharedMemorySize, SMEM_NB);
    cudaFuncSetAttribute(gemm_bias_kernel,    cudaFuncAttributeMaxDynamicSharedMemorySize, SMEM_GB);
    cudaFuncSetAttribute(gemm_bn_relu_kernel, cudaFuncAttributeMaxDynamicSharedMemorySize, SMEM_GB);

    prep_kernel<<<66, 256>>>(w1, w2, m1, m2);
    knn_kernel<<<128, 512, SMEM_KNN>>>(pos);
    u_gemm_kernel<<<NPTS/128, 512, SMEM_UG>>>(x, pos);
    self_gemm_kernel<<<NPTS/128, 512, SMEM_GB>>>(b1, b2);
    neighbor_kernel<<<NPTS/8, 512, SMEM_NB>>>(x, b1, b2);
    gemm_bias_kernel<<<NPTS/128, 512, SMEM_GB>>>(mb1);
    stats_kernel<<<128, 128>>>(nullptr, 0);
    bn_finalize_kernel<<<1, 128>>>(g1, be1, 0);
    gemm_bn_relu_kernel<<<NPTS/128, 512, SMEM_GB>>>(mb2, out);
    stats_kernel<<<128, 128>>>(out, 1);
    bn_finalize_kernel<<<1, 128>>>(g2, be2, 1);
    bn_apply_kernel<<<(NPTS*CC)/256, 256>>>(out);
}

// round 7
// speedup vs baseline: 2.8308x; 1.4103x over previous
#include <cuda_runtime.h>
#include <cuda_bf16.h>
#include <cstdint>

// Problem constants
#define BB 2
#define NN 8192
#define CC 128
#define PP 3
#define KK 16
#define NPTS (BB*NN)          // 16384 total points
#define EPS 1e-5f

#define WS2 136               // bf16 row stride for MMA operands (conflict-free)

// ---------------- scratch (static device globals; no allocation) ----------------
__device__ float d_w1t[131*128];     // [c][o]
__device__ float d_w2t[128*128];     // [h][o]  (for self_gemm)
__device__ float d_m1t[128*128];
__device__ float d_m2t[128*128];
__device__ __nv_bfloat16 d_w2h[128*WS2];  // w2 hi-split, [n][k] stride 136
__device__ __nv_bfloat16 d_w2l[128*WS2];  // w2 lo-split
__device__ int   d_nbr[NPTS*KK];
__device__ float d_u [NPTS*CC];      // W1 @ [x;pos]
__device__ float d_ux[NPTS*CC];      // W1x @ x (self path)
__device__ float d_wself[NPTS*CC];   // sigmoid(W2 relu(ux+b1) + b2)
__device__ float d_res[NPTS*CC];
__device__ float d_t [NPTS*CC];
__device__ float d_p1[128*128];
__device__ float d_p2[128*128];
__device__ float d_scale1[CC], d_shift1[CC], d_scale2[CC], d_shift2[CC];

// ---------------- mma.sync helper (baseline PTX, works on compute_103) ----------------
__device__ __forceinline__ void mma16816(float* c, const uint32_t* a, const uint32_t* b) {
    asm volatile(
        "mma.sync.aligned.m16n8k16.row.col.f32.bf16.bf16.f32 "
        "{%0,%1,%2,%3}, {%4,%5,%6,%7}, {%8,%9}, {%0,%1,%2,%3};"
        : "+f"(c[0]), "+f"(c[1]), "+f"(c[2]), "+f"(c[3])
        : "r"(a[0]), "r"(a[1]), "r"(a[2]), "r"(a[3]), "r"(b[0]), "r"(b[1]));
}

// ---------------- prep: transpose weights + build w2 bf16 splits ----------------
__global__ void prep_kernel(const float* __restrict__ w1, const float* __restrict__ w2,
                            const float* __restrict__ m1, const float* __restrict__ m2) {
    int i = blockIdx.x*blockDim.x + threadIdx.x;
    if (i < 131*128) { int o = i/131, c = i%131; d_w1t[c*128+o] = w1[i]; }
    if (i < 128*128) { int o = i>>7, c = i&127;
        d_w2t[c*128+o] = w2[i];
        d_m1t[c*128+o] = m1[i];
        d_m2t[c*128+o] = m2[i];
        float w = w2[i];
        __nv_bfloat16 hi = __float2bfloat16(w);
        __nv_bfloat16 lo = __float2bfloat16(w - __bfloat162float(hi));
        d_w2h[o*WS2 + c] = hi;      // [n][k]
        d_w2l[o*WS2 + c] = lo;
    }
}

// ---------------- KNN: 4 threads per query, two-pass (threshold + capture) --------
// Pass 1: values-only top-16 (branchless FMNMX insertion) -> exact 16th value tau.
// Pass 2: predicated capture of all d <= tau (scan order), then replay the exact
// strict-< insertion over the captured set => bitwise-identical to a full scan.
__global__ void __launch_bounds__(512) knn_kernel(const float* __restrict__ pos) {
    extern __shared__ float sm[];
    float4* sp = (float4*)sm;            // 8192 float4 = 128KB
    float*  cd = sm + 32768;             // 512*16 dists
    int*    ci = (int*)(cd + 8192);      // 512*16 idx
    const int b   = blockIdx.x >> 6;
    const int blk = blockIdx.x & 63;
    const int tid = threadIdx.x;
    const float* pb = pos + (size_t)b*NN*3;
    for (int j = tid; j < NN; j += 512) {
        float px = pb[j*3+0], py = pb[j*3+1], pz = pb[j*3+2];
        sp[j] = make_float4(px, py, pz, px*px + py*py + pz*pz);
    }
    __syncthreads();
    const int ql  = tid & 127;
    const int seg = tid >> 7;
    const int q   = blk*128 + ql;
    const float4 qp = sp[q];
    const int j0 = seg*2048, j1 = j0 + 2048;

    // ---- pass 1: values-only sorted top-16 ----
    float bd[KK];
    #pragma unroll
    for (int t = 0; t < KK; t++) bd[t] = 3.4e38f;
    #pragma unroll 2
    for (int j = j0; j < j1; j++) {
        float4 c = sp[j];
        float d = qp.w + c.w - 2.f*(qp.x*c.x + qp.y*c.y + qp.z*c.z);
        if (d < bd[KK-1]) {
            float dd = d;
            #pragma unroll
            for (int t = 0; t < KK; t++) {
                float mn = fminf(bd[t], dd);
                dd = fmaxf(bd[t], dd);
                bd[t] = mn;
            }
        }
    }
    const float tau = bd[KK-1];

    // ---- pass 2: capture all candidates with d <= tau, in scan order ----
    unsigned long long capb[48];
    int cnt = 0;
    #pragma unroll 2
    for (int j = j0; j < j1; j++) {
        float4 c = sp[j];
        float d = qp.w + c.w - 2.f*(qp.x*c.x + qp.y*c.y + qp.z*c.z);
        if (d <= tau && cnt < 48) {
            capb[cnt] = ((unsigned long long)__float_as_uint(d) << 32) | (unsigned)j;
            cnt++;
        }
    }

    // ---- replay exact strict-< insertion over captured set ----
    float bd2[KK]; int bi2[KK];
    #pragma unroll
    for (int t = 0; t < KK; t++) { bd2[t] = 3.4e38f; bi2[t] = 0; }
    for (int cix = 0; cix < cnt; cix++) {
        unsigned long long v = capb[cix];
        float dd = __uint_as_float((unsigned)(v >> 32));
        int   ii = (int)(unsigned)(v & 0xffffffffu);
        if (dd < bd2[KK-1]) {
            #pragma unroll
            for (int t = 0; t < KK; t++) {
                if (dd < bd2[t]) {
                    float tf = bd2[t]; bd2[t] = dd; dd = tf;
                    int   ti = bi2[t]; bi2[t] = ii; ii = ti;
                }
            }
        }
    }
    {
        int row = tid*16;
        #pragma unroll
        for (int t = 0; t < KK; t++) { cd[row+t] = bd2[t]; ci[row+t] = bi2[t]; }
    }
    __syncthreads();

    // merge 4 sorted lists per query; on ties prefer lower segment (= lower j)
    if (tid < 128) {
        int p[4] = {0,0,0,0};
        int base[4];
        #pragma unroll
        for (int s = 0; s < 4; s++) base[s] = (s*128 + ql)*16;
        const int obase = (b*NN + q)*KK;
        #pragma unroll
        for (int t = 0; t < KK; t++) {
            float best = 3.5e38f; int bs = 0;
            #pragma unroll
            for (int s = 0; s < 4; s++) {
                float v = (p[s] < 16) ? cd[base[s] + p[s]] : 3.6e38f;
                if (v < best) { best = v; bs = s; }
            }
            d_nbr[obase + t] = b*NN + ci[base[bs] + p[bs]];
            p[bs]++;
        }
    }
}

// ---------------- u GEMM: u = [x;pos] @ W1^T, ux = x @ W1x^T ----------------
__global__ void __launch_bounds__(512) u_gemm_kernel(const float* __restrict__ x,
                                                     const float* __restrict__ pos) {
    extern __shared__ float smu[];
    float* wts  = smu;            // 131*128
    float* tile = smu + 16768;    // 128*132
    const int tid = threadIdx.x;
    const int g0  = blockIdx.x * 128;
    for (int i = tid; i < 16768; i += 512) wts[i] = d_w1t[i];
    for (int i = tid; i < 128*132; i += 512) {
        int p = i/132, c = i%132;
        int g = g0 + p;
        float v = 0.f;
        if (c < 128)      v = x[(size_t)g*128 + c];
        else if (c < 131) v = pos[(size_t)g*3 + (c-128)];
        tile[i] = v;
    }
    __syncthreads();
    const int rg = tid >> 5, og = tid & 31;
    const int r0 = rg*8, o0 = og*4;
    float acc[8][4] = {};
    int c = 0;
    #pragma unroll 4
    for (; c < 128; ++c) {
        float4 w4 = *reinterpret_cast<const float4*>(&wts[c*128 + o0]);
        float hh[8];
        #pragma unroll
        for (int r = 0; r < 8; r++) hh[r] = tile[(r0+r)*132 + c];
        #pragma unroll
        for (int r = 0; r < 8; r++) {
            acc[r][0] = fmaf(hh[r], w4.x, acc[r][0]);
            acc[r][1] = fmaf(hh[r], w4.y, acc[r][1]);
            acc[r][2] = fmaf(hh[r], w4.z, acc[r][2]);
            acc[r][3] = fmaf(hh[r], w4.w, acc[r][3]);
        }
    }
    #pragma unroll
    for (int r = 0; r < 8; r++)
        *reinterpret_cast<float4*>(&d_ux[(size_t)(g0+r0+r)*128 + o0]) =
            make_float4(acc[r][0], acc[r][1], acc[r][2], acc[r][3]);
    for (; c < 131; ++c) {
        float4 w4 = *reinterpret_cast<const float4*>(&wts[c*128 + o0]);
        float hh[8];
        #pragma unroll
        for (int r = 0; r < 8; r++) hh[r] = tile[(r0+r)*132 + c];
        #pragma unroll
        for (int r = 0; r < 8; r++) {
            acc[r][0] = fmaf(hh[r], w4.x, acc[r][0]);
            acc[r][1] = fmaf(hh[r], w4.y, acc[r][1]);
            acc[r][2] = fmaf(hh[r], w4.z, acc[r][2]);
            acc[r][3] = fmaf(hh[r], w4.w, acc[r][3]);
        }
    }
    #pragma unroll
    for (int r = 0; r < 8; r++)
        *reinterpret_cast<float4*>(&d_u[(size_t)(g0+r0+r)*128 + o0]) =
            make_float4(acc[r][0], acc[r][1], acc[r][2], acc[r][3]);
}

// ---------------- self weights GEMM: wself = sigmoid(W2 relu(ux+b1) + b2) ----------------
__global__ void __launch_bounds__(512) self_gemm_kernel(const float* __restrict__ b1,
                                                        const float* __restrict__ b2) {
    extern __shared__ float sms[];
    float* wts  = sms;           // 16384
    float* tile = sms + 16384;   // 128*132
    const int tid = threadIdx.x, g0 = blockIdx.x*128;
    for (int i = tid; i < 16384; i += 512) wts[i] = d_w2t[i];
    {
        const int lane = tid & 31, c0 = lane*4;
        for (int r = tid >> 5; r < 128; r += 16) {
            float4 v = *reinterpret_cast<const float4*>(&d_ux[(size_t)(g0+r)*128 + c0]);
            float4 h;
            h.x = fmaxf(v.x + b1[c0+0], 0.f);
            h.y = fmaxf(v.y + b1[c0+1], 0.f);
            h.z = fmaxf(v.z + b1[c0+2], 0.f);
            h.w = fmaxf(v.w + b1[c0+3], 0.f);
            *reinterpret_cast<float4*>(&tile[r*132 + c0]) = h;
        }
    }
    __syncthreads();
    const int rg = tid >> 5, og = tid & 31;
    const int r0 = rg*8, o0 = og*4;
    float acc[8][4] = {};
    #pragma unroll 4
    for (int c = 0; c < 128; ++c) {
        float4 w4 = *reinterpret_cast<const float4*>(&wts[c*128 + o0]);
        float hh[8];
        #pragma unroll
        for (int r = 0; r < 8; r++) hh[r] = tile[(r0+r)*132 + c];
        #pragma unroll
        for (int r = 0; r < 8; r++) {
            acc[r][0] = fmaf(hh[r], w4.x, acc[r][0]);
            acc[r][1] = fmaf(hh[r], w4.y, acc[r][1]);
            acc[r][2] = fmaf(hh[r], w4.z, acc[r][2]);
            acc[r][3] = fmaf(hh[r], w4.w, acc[r][3]);
        }
    }
    float4 bb = *reinterpret_cast<const float4*>(&b2[o0]);
    #pragma unroll
    for (int r = 0; r < 8; r++) {
        float4 o4;
        o4.x = 1.f/(1.f + __expf(-(acc[r][0]+bb.x)));
        o4.y = 1.f/(1.f + __expf(-(acc[r][1]+bb.y)));
        o4.z = 1.f/(1.f + __expf(-(acc[r][2]+bb.z)));
        o4.w = 1.f/(1.f + __expf(-(acc[r][3]+bb.w)));
        *reinterpret_cast<float4*>(&d_wself[(size_t)(g0+r0+r)*128 + o0]) = o4;
    }
}

// ---------------- fused neighbor kernel: mma.sync bf16-split GEMM ----------------
#define NB_WH   0                 // 34816  w2 hi  [n][k] bf16 stride 136
#define NB_WL   34816             // 34816  w2 lo
#define NB_AH   69632             // 34816  hid hi [m][k]
#define NB_AL   104448            // 34816  hid lo          (AH..AL end 139264)
#define NB_XG   69632             // 67584  gathered x fp32 [128][132] (reuses AH/AL)
#define NB_XNS  139264            // 4096
#define NB_B1   143360            // 512
#define NB_B2   143872            // 512
#define NB_NIDX 144384            // 512
#define NB_UCEN 144896            // 4096
#define NB_SMEM 148992

__global__ void __launch_bounds__(512) neighbor_kernel(const float* __restrict__ x,
                                const float* __restrict__ b1, const float* __restrict__ b2) {
    extern __shared__ char smem[];
    __nv_bfloat16* WH = (__nv_bfloat16*)(smem + NB_WH);
    __nv_bfloat16* WL = (__nv_bfloat16*)(smem + NB_WL);
    __nv_bfloat16* AH = (__nv_bfloat16*)(smem + NB_AH);
    __nv_bfloat16* AL = (__nv_bfloat16*)(smem + NB_AL);
    float* xg   = (float*)(smem + NB_XG);
    float* xns  = (float*)(smem + NB_XNS);
    float* b1s  = (float*)(smem + NB_B1);
    float* b2s  = (float*)(smem + NB_B2);
    int*   nidx = (int*)  (smem + NB_NIDX);
    float* ucen = (float*)(smem + NB_UCEN);

    const int tid  = threadIdx.x;
    const int wid  = tid >> 5;
    const int lane = tid & 31;
    const int g0   = blockIdx.x * 8;

    {
        const uint4* whg = (const uint4*)d_w2h;
        const uint4* wlg = (const uint4*)d_w2l;
        uint4* whs = (uint4*)WH;
        uint4* wls = (uint4*)WL;
        for (int i = tid; i < 2176; i += 512) { whs[i] = whg[i]; wls[i] = wlg[i]; }
    }
    if (tid < 128) { nidx[tid] = d_nbr[g0*KK + tid]; b1s[tid] = b1[tid]; b2s[tid] = b2[tid]; }
    for (int i = tid; i < 1024; i += 512) {
        int p = i >> 7, c = i & 127;
        ucen[i] = d_u[(size_t)(g0+p)*128 + c];
        xns[i]  = x  [(size_t)(g0+p)*128 + c];
    }
    __syncthreads();

    // build hidden rows -> bf16 hi/lo splits [m][k]
    {
        const int c0 = lane*4;
        for (int r = wid; r < 128; r += 16) {
            int p = r >> 4;
            float4 uv = *reinterpret_cast<const float4*>(&d_u[(size_t)nidx[r]*128 + c0]);
            float h0 = fmaxf(uv.x - ucen[p*128 + c0+0] + b1s[c0+0], 0.f);
            float h1 = fmaxf(uv.y - ucen[p*128 + c0+1] + b1s[c0+1], 0.f);
            float h2 = fmaxf(uv.z - ucen[p*128 + c0+2] + b1s[c0+2], 0.f);
            float h3 = fmaxf(uv.w - ucen[p*128 + c0+3] + b1s[c0+3], 0.f);
            __nv_bfloat162 hA = __floats2bfloat162_rn(h0, h1);
            __nv_bfloat162 hB = __floats2bfloat162_rn(h2, h3);
            __nv_bfloat162 lA = __floats2bfloat162_rn(h0 - __low2float(hA), h1 - __high2float(hA));
            __nv_bfloat162 lB = __floats2bfloat162_rn(h2 - __low2float(hB), h3 - __high2float(hB));
            *(__nv_bfloat162*)&AH[r*WS2 + c0]     = hA;
            *(__nv_bfloat162*)&AH[r*WS2 + c0 + 2] = hB;
            *(__nv_bfloat162*)&AL[r*WS2 + c0]     = lA;
            *(__nv_bfloat162*)&AL[r*WS2 + c0 + 2] = lB;
        }
    }
    __syncthreads();

    // warp-tiled GEMM: warp (wm, wn) computes rows m0..m0+31, cols n0..n0+31
    const int wm = wid >> 2, wn = wid & 3;
    const int m0 = wm*32, n0 = wn*32;
    const int rA = lane >> 2;
    const int kA = (lane & 3) * 2;
    float acc[2][4][4];
    #pragma unroll
    for (int mt = 0; mt < 2; mt++)
        #pragma unroll
        for (int nt = 0; nt < 4; nt++)
            #pragma unroll
            for (int q = 0; q < 4; q++) acc[mt][nt][q] = 0.f;

    const __nv_bfloat16* Aterm[3] = {AH, AH, AL};
    const __nv_bfloat16* Bterm[3] = {WH, WL, WH};
    #pragma unroll
    for (int term = 0; term < 3; term++) {
        const __nv_bfloat16* A = Aterm[term];
        const __nv_bfloat16* B = Bterm[term];
        #pragma unroll
        for (int kk = 0; kk < 128; kk += 16) {
            uint32_t a[2][4], bfr[4][2];
            #pragma unroll
            for (int mt = 0; mt < 2; mt++) {
                const __nv_bfloat16* ap = A + (m0 + mt*16 + rA)*WS2 + kk + kA;
                a[mt][0] = *(const uint32_t*)ap;
                a[mt][1] = *(const uint32_t*)(ap + 8*WS2);
                a[mt][2] = *(const uint32_t*)(ap + 8);
                a[mt][3] = *(const uint32_t*)(ap + 8*WS2 + 8);
            }
            #pragma unroll
            for (int nt = 0; nt < 4; nt++) {
                const __nv_bfloat16* bp = B + (n0 + nt*8 + rA)*WS2 + kk + kA;
                bfr[nt][0] = *(const uint32_t*)bp;
                bfr[nt][1] = *(const uint32_t*)(bp + 8);
            }
            #pragma unroll
            for (int mt = 0; mt < 2; mt++)
                #pragma unroll
                for (int nt = 0; nt < 4; nt++)
                    mma16816(acc[mt][nt], a[mt], bfr[nt]);
        }
    }
    __syncthreads();   // done with AH/AL -> reuse as xg

    // gather neighbor x rows into smem (coalesced)
    {
        const int c0 = lane*4;
        for (int r = wid; r < 128; r += 16)
            *reinterpret_cast<float4*>(&xg[r*132 + c0]) =
                *reinterpret_cast<const float4*>(&x[(size_t)nidx[r]*128 + c0]);
    }
    __syncthreads();

    // epilogue: sigmoid, weight rel_x, reduce 16 rows, write res
    #pragma unroll
    for (int mt = 0; mt < 2; mt++) {
        const int p  = wm*2 + mt;
        const int r0 = m0 + mt*16 + rA;
        const int r1 = r0 + 8;
        #pragma unroll
        for (int nt = 0; nt < 4; nt++) {
            const int col0 = n0 + nt*8 + (lane & 3)*2;
            float z00 = acc[mt][nt][0] + b2s[col0];
            float z01 = acc[mt][nt][1] + b2s[col0+1];
            float z10 = acc[mt][nt][2] + b2s[col0];
            float z11 = acc[mt][nt][3] + b2s[col0+1];
            float s00 = 1.f/(1.f + __expf(-z00));
            float s01 = 1.f/(1.f + __expf(-z01));
            float s10 = 1.f/(1.f + __expf(-z10));
            float s11 = 1.f/(1.f + __expf(-z11));
            float xc0 = xns[p*128 + col0], xc1 = xns[p*128 + col0+1];
            float t0 = (xg[r0*132 + col0]   - xc0)*s00 + (xg[r1*132 + col0]   - xc0)*s10;
            float t1 = (xg[r0*132 + col0+1] - xc1)*s01 + (xg[r1*132 + col0+1] - xc1)*s11;
            t0 += __shfl_xor_sync(0xffffffffu, t0, 4);
            t0 += __shfl_xor_sync(0xffffffffu, t0, 8);
            t0 += __shfl_xor_sync(0xffffffffu, t0, 16);
            t1 += __shfl_xor_sync(0xffffffffu, t1, 4);
            t1 += __shfl_xor_sync(0xffffffffu, t1, 8);
            t1 += __shfl_xor_sync(0xffffffffu, t1, 16);
            if (lane < 4) {
                const size_t ob = (size_t)(g0+p)*128;
                float w0 = d_wself[ob + col0], w1 = d_wself[ob + col0+1];
                d_res[ob + col0]   = xc0*(1.f + w0) - t0;
                d_res[ob + col0+1] = xc1*(1.f + w1) - t1;
            }
        }
    }
}

// ---------------- tail GEMMs: 128 rows/block, 512 threads, fused BN stats ----------------
__global__ void __launch_bounds__(512) gemm_bias_kernel(const float* __restrict__ bias) {
    extern __shared__ float smg[];
    float* wts  = smg;           // 16384
    float* tile = smg + 16384;   // 128*132
    const int tid = threadIdx.x, g0 = blockIdx.x*128;
    for (int i = tid; i < 16384; i += 512) wts[i] = d_m1t[i];
    {
        const int lane = tid & 31, c0 = lane*4;
        for (int r = tid >> 5; r < 128; r += 16)
            *reinterpret_cast<float4*>(&tile[r*132 + c0]) =
                *reinterpret_cast<const float4*>(&d_res[(size_t)(g0+r)*128 + c0]);
    }
    __syncthreads();
    const int rg = tid >> 5, og = tid & 31;
    const int r0 = rg*8, o0 = og*4;
    float acc[8][4] = {};
    #pragma unroll 4
    for (int c = 0; c < 128; ++c) {
        float4 w4 = *reinterpret_cast<const float4*>(&wts[c*128 + o0]);
        float hh[8];
        #pragma unroll
        for (int r = 0; r < 8; r++) hh[r] = tile[(r0+r)*132 + c];
        #pragma unroll
        for (int r = 0; r < 8; r++) {
            acc[r][0] = fmaf(hh[r], w4.x, acc[r][0]);
            acc[r][1] = fmaf(hh[r], w4.y, acc[r][1]);
            acc[r][2] = fmaf(hh[r], w4.z, acc[r][2]);
            acc[r][3] = fmaf(hh[r], w4.w, acc[r][3]);
        }
    }
    float4 bb = *reinterpret_cast<const float4*>(&bias[o0]);
    float s[4] = {0,0,0,0}, s2[4] = {0,0,0,0};
    #pragma unroll
    for (int r = 0; r < 8; r++) {
        float v0 = acc[r][0]+bb.x, v1 = acc[r][1]+bb.y, v2 = acc[r][2]+bb.z, v3 = acc[r][3]+bb.w;
        *reinterpret_cast<float4*>(&d_t[(size_t)(g0+r0+r)*128 + o0]) =
            make_float4(v0, v1, v2, v3);
        s[0]+=v0; s[1]+=v1; s[2]+=v2; s[3]+=v3;
        s2[0]+=v0*v0; s2[1]+=v1*v1; s2[2]+=v2*v2; s2[3]+=v3*v3;
    }
    // fused BN stats: deterministic fixed-order partials
    __syncthreads();                  // done reading wts -> reuse as scratch
    float* ps  = wts;                 // 2048
    float* ps2 = wts + 2048;          // 2048
    #pragma unroll
    for (int q = 0; q < 4; q++) { ps[rg*128 + o0+q] = s[q]; ps2[rg*128 + o0+q] = s2[q]; }
    __syncthreads();
    if (tid < 128) {
        float a = 0.f, b = 0.f;
        #pragma unroll
        for (int g = 0; g < 16; g++) { a += ps[g*128 + tid]; b += ps2[g*128 + tid]; }
        d_p1[blockIdx.x*128 + tid] = a;
        d_p2[blockIdx.x*128 + tid] = b;
    }
}

__global__ void __launch_bounds__(512) gemm_bn_relu_kernel(const float* __restrict__ bias,
                                                           float* __restrict__ out) {
    extern __shared__ float smh[];
    float* wts  = smh;
    float* tile = smh + 16384;
    const int tid = threadIdx.x, g0 = blockIdx.x*128;
    for (int i = tid; i < 16384; i += 512) wts[i] = d_m2t[i];
    {
        const int lane = tid & 31, c0 = lane*4;
        for (int r = tid >> 5; r < 128; r += 16) {
            float4 v = *reinterpret_cast<const float4*>(&d_t[(size_t)(g0+r)*128 + c0]);
            float4 h;
            h.x = fmaxf(fmaf(v.x, d_scale1[c0+0], d_shift1[c0+0]), 0.f);
            h.y = fmaxf(fmaf(v.y, d_scale1[c0+1], d_shift1[c0+1]), 0.f);
            h.z = fmaxf(fmaf(v.z, d_scale1[c0+2], d_shift1[c0+2]), 0.f);
            h.w = fmaxf(fmaf(v.w, d_scale1[c0+3], d_shift1[c0+3]), 0.f);
            *reinterpret_cast<float4*>(&tile[r*132 + c0]) = h;
        }
    }
    __syncthreads();
    const int rg = tid >> 5, og = tid & 31;
    const int r0 = rg*8, o0 = og*4;
    float acc[8][4] = {};
    #pragma unroll 4
    for (int c = 0; c < 128; ++c) {
        float4 w4 = *reinterpret_cast<const float4*>(&wts[c*128 + o0]);
        float hh[8];
        #pragma unroll
        for (int r = 0; r < 8; r++) hh[r] = tile[(r0+r)*132 + c];
        #pragma unroll
        for (int r = 0; r < 8; r++) {
            acc[r][0] = fmaf(hh[r], w4.x, acc[r][0]);
            acc[r][1] = fmaf(hh[r], w4.y, acc[r][1]);
            acc[r][2] = fmaf(hh[r], w4.z, acc[r][2]);
            acc[r][3] = fmaf(hh[r], w4.w, acc[r][3]);
        }
    }
    float4 bb = *reinterpret_cast<const float4*>(&bias[o0]);
    float s[4] = {0,0,0,0}, s2[4] = {0,0,0,0};
    #pragma unroll
    for (int r = 0; r < 8; r++) {
        float v0 = acc[r][0]+bb.x, v1 = acc[r][1]+bb.y, v2 = acc[r][2]+bb.z, v3 = acc[r][3]+bb.w;
        *reinterpret_cast<float4*>(&out[(size_t)(g0+r0+r)*128 + o0]) =
            make_float4(v0, v1, v2, v3);
        s[0]+=v0; s[1]+=v1; s[2]+=v2; s[3]+=v3;
        s2[0]+=v0*v0; s2[1]+=v1*v1; s2[2]+=v2*v2; s2[3]+=v3*v3;
    }
    __syncthreads();
    float* ps  = wts;
    float* ps2 = wts + 2048;
    #pragma unroll
    for (int q = 0; q < 4; q++) { ps[rg*128 + o0+q] = s[q]; ps2[rg*128 + o0+q] = s2[q]; }
    __syncthreads();
    if (tid < 128) {
        float a = 0.f, b = 0.f;
        #pragma unroll
        for (int g = 0; g < 16; g++) { a += ps[g*128 + tid]; b += ps2[g*128 + tid]; }
        d_p1[blockIdx.x*128 + tid] = a;
        d_p2[blockIdx.x*128 + tid] = b;
    }
}

// ---------------- BN finalize / apply ----------------
__global__ void bn_finalize_kernel(const float* __restrict__ g, const float* __restrict__ be,
                                   int which) {
    const int o = threadIdx.x;
    float s = 0.f, s2 = 0.f;
    for (int b = 0; b < 128; b++) { s += d_p1[b*128 + o]; s2 += d_p2[b*128 + o]; }
    float mu  = s  * (1.f/16384.f);
    float var = s2 * (1.f/16384.f) - mu*mu;
    float sc  = g[o] * rsqrtf(var + EPS);
    if (which == 0) { d_scale1[o] = sc; d_shift1[o] = be[o] - mu*sc; }
    else            { d_scale2[o] = sc; d_shift2[o] = be[o] - mu*sc; }
}

__global__ void bn_apply_kernel(float* __restrict__ out) {
    int i = blockIdx.x*blockDim.x + threadIdx.x;
    int o = i & 127;
    out[i] = fmaf(out[i], d_scale2[o], d_shift2[o]);
}

// ---------------- launch ----------------
extern "C" void kernel_launch(void* const* d_in, const int* in_sizes, int n_in,
                              void* d_out, int out_size) {
    (void)in_sizes; (void)n_in; (void)out_size;
    const float* x   = (const float*)d_in[0];
    const float* pos = (const float*)d_in[1];
    const float* w1  = (const float*)d_in[2];
    const float* b1  = (const float*)d_in[3];
    const float* w2  = (const float*)d_in[4];
    const float* b2  = (const float*)d_in[5];
    const float* m1  = (const float*)d_in[6];
    const float* mb1 = (const float*)d_in[7];
    const float* m2  = (const float*)d_in[8];
    const float* mb2 = (const float*)d_in[9];
    const float* g1  = (const float*)d_in[10];
    const float* be1 = (const float*)d_in[11];
    const float* g2  = (const float*)d_in[12];
    const float* be2 = (const float*)d_in[13];
    float* out = (float*)d_out;

    const int SMEM_KNN  = (32768 + 8192 + 8192) * 4;          // 196608
    const int SMEM_UG   = (16768 + 128*132) * 4;              // 134656
    const int SMEM_NB   = NB_SMEM;                            // 148992
    const int SMEM_GB   = (16384 + 128*132) * 4;              // 133120

    cudaFuncSetAttribute(knn_kernel,          cudaFuncAttributeMaxDynamicSharedMemorySize, SMEM_KNN);
    cudaFuncSetAttribute(u_gemm_kernel,       cudaFuncAttributeMaxDynamicSharedMemorySize, SMEM_UG);
    cudaFuncSetAttribute(self_gemm_kernel,    cudaFuncAttributeMaxDynamicSharedMemorySize, SMEM_GB);
    cudaFuncSetAttribute(neighbor_kernel,     cudaFuncAttributeMaxDynamicSharedMemorySize, SMEM_NB);
    cudaFuncSetAttribute(gemm_bias_kernel,    cudaFuncAttributeMaxDynamicSharedMemorySize, SMEM_GB);
    cudaFuncSetAttribute(gemm_bn_relu_kernel, cudaFuncAttributeMaxDynamicSharedMemorySize, SMEM_GB);

    prep_kernel<<<66, 256>>>(w1, w2, m1, m2);
    knn_kernel<<<128, 512, SMEM_KNN>>>(pos);
    u_gemm_kernel<<<NPTS/128, 512, SMEM_UG>>>(x, pos);
    self_gemm_kernel<<<NPTS/128, 512, SMEM_GB>>>(b1, b2);
    neighbor_kernel<<<NPTS/8, 512, SMEM_NB>>>(x, b1, b2);
    gemm_bias_kernel<<<NPTS/128, 512, SMEM_GB>>>(mb1);
    bn_finalize_kernel<<<1, 128>>>(g1, be1, 0);
    gemm_bn_relu_kernel<<<NPTS/128, 512, SMEM_GB>>>(mb2, out);
    bn_finalize_kernel<<<1, 128>>>(g2, be2, 1);
    bn_apply_kernel<<<(NPTS*CC)/256, 256>>>(out);
}

// round 8
// speedup vs baseline: 2.8726x; 1.0148x over previous
#include <cuda_runtime.h>
#include <cuda_bf16.h>
#include <cstdint>

// Problem constants
#define BB 2
#define NN 8192
#define CC 128
#define PP 3
#define KK 16
#define NPTS (BB*NN)          // 16384 total points
#define EPS 1e-5f

#define WS2 136               // bf16 row stride for MMA operands (conflict-free)

// ---------------- scratch (static device globals; no allocation) ----------------
__device__ float d_w1t[131*128];     // [c][o]
__device__ float d_w2t[128*128];     // [h][o]
__device__ float d_m1t[128*128];
__device__ float d_m2t[128*128];
__device__ __nv_bfloat16 d_w2h[128*WS2];  // w2 hi-split, [n][k] stride 136
__device__ __nv_bfloat16 d_w2l[128*WS2];  // w2 lo-split
__device__ int   d_nbr[NPTS*KK];
__device__ float d_u [NPTS*CC];      // W1 @ [x;pos]
__device__ float d_wself[NPTS*CC];   // sigmoid(W2 relu(ux+b1) + b2)
__device__ float d_res[NPTS*CC];
__device__ float d_t [NPTS*CC];
__device__ float d_p1[128*128];
__device__ float d_p2[128*128];
__device__ float d_scale1[CC], d_shift1[CC], d_scale2[CC], d_shift2[CC];

// ---------------- mma.sync helper (baseline PTX, works on compute_103) ----------------
__device__ __forceinline__ void mma16816(float* c, const uint32_t* a, const uint32_t* b) {
    asm volatile(
        "mma.sync.aligned.m16n8k16.row.col.f32.bf16.bf16.f32 "
        "{%0,%1,%2,%3}, {%4,%5,%6,%7}, {%8,%9}, {%0,%1,%2,%3};"
        : "+f"(c[0]), "+f"(c[1]), "+f"(c[2]), "+f"(c[3])
        : "r"(a[0]), "r"(a[1]), "r"(a[2]), "r"(a[3]), "r"(b[0]), "r"(b[1]));
}

// ---------------- prep: transpose weights + build w2 bf16 splits ----------------
__global__ void prep_kernel(const float* __restrict__ w1, const float* __restrict__ w2,
                            const float* __restrict__ m1, const float* __restrict__ m2) {
    int i = blockIdx.x*blockDim.x + threadIdx.x;
    if (i < 131*128) { int o = i/131, c = i%131; d_w1t[c*128+o] = w1[i]; }
    if (i < 128*128) { int o = i>>7, c = i&127;
        d_w2t[c*128+o] = w2[i];
        d_m1t[c*128+o] = m1[i];
        d_m2t[c*128+o] = m2[i];
        float w = w2[i];
        __nv_bfloat16 hi = __float2bfloat16(w);
        __nv_bfloat16 lo = __float2bfloat16(w - __bfloat162float(hi));
        d_w2h[o*WS2 + c] = hi;      // [n][k]
        d_w2l[o*WS2 + c] = lo;
    }
}

// ---------------- KNN: 4 threads per query, two-pass (threshold + capture) --------
__global__ void __launch_bounds__(512) knn_kernel(const float* __restrict__ pos) {
    extern __shared__ float sm[];
    float4* sp = (float4*)sm;            // 8192 float4 = 128KB
    float*  cd = sm + 32768;             // 512*16 dists
    int*    ci = (int*)(cd + 8192);      // 512*16 idx
    const int b   = blockIdx.x >> 6;
    const int blk = blockIdx.x & 63;
    const int tid = threadIdx.x;
    const float* pb = pos + (size_t)b*NN*3;
    for (int j = tid; j < NN; j += 512) {
        float px = pb[j*3+0], py = pb[j*3+1], pz = pb[j*3+2];
        sp[j] = make_float4(px, py, pz, px*px + py*py + pz*pz);
    }
    __syncthreads();
    const int ql  = tid & 127;
    const int seg = tid >> 7;
    const int q   = blk*128 + ql;
    const float4 qp = sp[q];
    const int j0 = seg*2048, j1 = j0 + 2048;

    // ---- pass 1: values-only sorted top-16 ----
    float bd[KK];
    #pragma unroll
    for (int t = 0; t < KK; t++) bd[t] = 3.4e38f;
    #pragma unroll 2
    for (int j = j0; j < j1; j++) {
        float4 c = sp[j];
        float d = qp.w + c.w - 2.f*(qp.x*c.x + qp.y*c.y + qp.z*c.z);
        if (d < bd[KK-1]) {
            float dd = d;
            #pragma unroll
            for (int t = 0; t < KK; t++) {
                float mn = fminf(bd[t], dd);
                dd = fmaxf(bd[t], dd);
                bd[t] = mn;
            }
        }
    }
    const float tau = bd[KK-1];

    // ---- pass 2: capture all candidates with d <= tau, in scan order ----
    unsigned long long capb[48];
    int cnt = 0;
    #pragma unroll 2
    for (int j = j0; j < j1; j++) {
        float4 c = sp[j];
        float d = qp.w + c.w - 2.f*(qp.x*c.x + qp.y*c.y + qp.z*c.z);
        if (d <= tau && cnt < 48) {
            capb[cnt] = ((unsigned long long)__float_as_uint(d) << 32) | (unsigned)j;
            cnt++;
        }
    }

    // ---- replay exact strict-< insertion over captured set ----
    float bd2[KK]; int bi2[KK];
    #pragma unroll
    for (int t = 0; t < KK; t++) { bd2[t] = 3.4e38f; bi2[t] = 0; }
    for (int cix = 0; cix < cnt; cix++) {
        unsigned long long v = capb[cix];
        float dd = __uint_as_float((unsigned)(v >> 32));
        int   ii = (int)(unsigned)(v & 0xffffffffu);
        if (dd < bd2[KK-1]) {
            #pragma unroll
            for (int t = 0; t < KK; t++) {
                if (dd < bd2[t]) {
                    float tf = bd2[t]; bd2[t] = dd; dd = tf;
                    int   ti = bi2[t]; bi2[t] = ii; ii = ti;
                }
            }
        }
    }
    {
        int row = tid*16;
        #pragma unroll
        for (int t = 0; t < KK; t++) { cd[row+t] = bd2[t]; ci[row+t] = bi2[t]; }
    }
    __syncthreads();

    if (tid < 128) {
        int p[4] = {0,0,0,0};
        int base[4];
        #pragma unroll
        for (int s = 0; s < 4; s++) base[s] = (s*128 + ql)*16;
        const int obase = (b*NN + q)*KK;
        #pragma unroll
        for (int t = 0; t < KK; t++) {
            float best = 3.5e38f; int bs = 0;
            #pragma unroll
            for (int s = 0; s < 4; s++) {
                float v = (p[s] < 16) ? cd[base[s] + p[s]] : 3.6e38f;
                if (v < best) { best = v; bs = s; }
            }
            d_nbr[obase + t] = b*NN + ci[base[bs] + p[bs]];
            p[bs]++;
        }
    }
}

// ---------------- fused u + self GEMM ----------------
// GEMM1: acc(c<128) = ux;  hidden = relu(ux+b1) -> tile;  +pos cols -> d_u.
// GEMM2: wself = sigmoid(hidden @ w2^T + b2).
__global__ void __launch_bounds__(512) u_self_kernel(const float* __restrict__ x,
                                                     const float* __restrict__ pos,
                                                     const float* __restrict__ b1,
                                                     const float* __restrict__ b2) {
    extern __shared__ float smu[];
    float* wts  = smu;            // 16768 (w1t, later w2t)
    float* tile = smu + 16768;    // 128*132 (inputs, later hidden)
    const int tid = threadIdx.x;
    const int g0  = blockIdx.x * 128;
    for (int i = tid; i < 16768; i += 512) wts[i] = d_w1t[i];
    for (int i = tid; i < 128*132; i += 512) {
        int p = i/132, c = i%132;
        int g = g0 + p;
        float v = 0.f;
        if (c < 128)      v = x[(size_t)g*128 + c];
        else if (c < 131) v = pos[(size_t)g*3 + (c-128)];
        tile[i] = v;
    }
    __syncthreads();
    const int rg = tid >> 5, og = tid & 31;
    const int r0 = rg*8, o0 = og*4;
    float acc[8][4] = {};
    int c = 0;
    #pragma unroll 4
    for (; c < 128; ++c) {
        float4 w4 = *reinterpret_cast<const float4*>(&wts[c*128 + o0]);
        float hh[8];
        #pragma unroll
        for (int r = 0; r < 8; r++) hh[r] = tile[(r0+r)*132 + c];
        #pragma unroll
        for (int r = 0; r < 8; r++) {
            acc[r][0] = fmaf(hh[r], w4.x, acc[r][0]);
            acc[r][1] = fmaf(hh[r], w4.y, acc[r][1]);
            acc[r][2] = fmaf(hh[r], w4.z, acc[r][2]);
            acc[r][3] = fmaf(hh[r], w4.w, acc[r][3]);
        }
    }
    __syncthreads();   // all threads done reading tile cols 0..127 (acc == ux here)
    // write hidden = relu(ux + b1) into tile cols 0..127 (pos cols 128..130 untouched)
    {
        float4 bb = *reinterpret_cast<const float4*>(&b1[o0]);
        #pragma unroll
        for (int r = 0; r < 8; r++) {
            tile[(r0+r)*132 + o0+0] = fmaxf(acc[r][0] + bb.x, 0.f);
            tile[(r0+r)*132 + o0+1] = fmaxf(acc[r][1] + bb.y, 0.f);
            tile[(r0+r)*132 + o0+2] = fmaxf(acc[r][2] + bb.z, 0.f);
            tile[(r0+r)*132 + o0+3] = fmaxf(acc[r][3] + bb.w, 0.f);
        }
    }
    // finish pos columns -> full u
    for (; c < 131; ++c) {
        float4 w4 = *reinterpret_cast<const float4*>(&wts[c*128 + o0]);
        float hh[8];
        #pragma unroll
        for (int r = 0; r < 8; r++) hh[r] = tile[(r0+r)*132 + c];
        #pragma unroll
        for (int r = 0; r < 8; r++) {
            acc[r][0] = fmaf(hh[r], w4.x, acc[r][0]);
            acc[r][1] = fmaf(hh[r], w4.y, acc[r][1]);
            acc[r][2] = fmaf(hh[r], w4.z, acc[r][2]);
            acc[r][3] = fmaf(hh[r], w4.w, acc[r][3]);
        }
    }
    #pragma unroll
    for (int r = 0; r < 8; r++)
        *reinterpret_cast<float4*>(&d_u[(size_t)(g0+r0+r)*128 + o0]) =
            make_float4(acc[r][0], acc[r][1], acc[r][2], acc[r][3]);
    // load w2 and run GEMM2 on hidden
    __syncthreads();
    for (int i = tid; i < 16384; i += 512) wts[i] = d_w2t[i];
    __syncthreads();
    float acc2[8][4] = {};
    #pragma unroll 4
    for (int cc = 0; cc < 128; ++cc) {
        float4 w4 = *reinterpret_cast<const float4*>(&wts[cc*128 + o0]);
        float hh[8];
        #pragma unroll
        for (int r = 0; r < 8; r++) hh[r] = tile[(r0+r)*132 + cc];
        #pragma unroll
        for (int r = 0; r < 8; r++) {
            acc2[r][0] = fmaf(hh[r], w4.x, acc2[r][0]);
            acc2[r][1] = fmaf(hh[r], w4.y, acc2[r][1]);
            acc2[r][2] = fmaf(hh[r], w4.z, acc2[r][2]);
            acc2[r][3] = fmaf(hh[r], w4.w, acc2[r][3]);
        }
    }
    float4 bb2 = *reinterpret_cast<const float4*>(&b2[o0]);
    #pragma unroll
    for (int r = 0; r < 8; r++) {
        float4 o4;
        o4.x = 1.f/(1.f + __expf(-(acc2[r][0]+bb2.x)));
        o4.y = 1.f/(1.f + __expf(-(acc2[r][1]+bb2.y)));
        o4.z = 1.f/(1.f + __expf(-(acc2[r][2]+bb2.z)));
        o4.w = 1.f/(1.f + __expf(-(acc2[r][3]+bb2.w)));
        *reinterpret_cast<float4*>(&d_wself[(size_t)(g0+r0+r)*128 + o0]) = o4;
    }
}

// ---------------- fused neighbor kernel: mma.sync bf16-split, 2 CTAs/SM ----------------
// 8 points/block, 256 threads (8 warps, 4m x 2n grid of 32x64 tiles).
// 3-slot smem: S0=WH, S1=AH, S2=WL (terms 1-2) then rebuilt as AL (term 3).
#define NB_WH   0                 // 34816
#define NB_AH   34816             // 34816
#define NB_S2   69632             // 34816  (WL, then AL)
#define NB_XG   34816             // [128][132] f32 = 67584, spans S1+S2 after GEMM
#define NB_XNS  104448            // 4096
#define NB_UCEN 108544            // 4096
#define NB_B1   112640            // 512
#define NB_B2   113152            // 512
#define NB_NIDX 113664            // 512
#define NB_SMEM 114176

__global__ void __launch_bounds__(256, 2) neighbor_kernel(const float* __restrict__ x,
                                const float* __restrict__ b1, const float* __restrict__ b2) {
    extern __shared__ char smem[];
    __nv_bfloat16* WH = (__nv_bfloat16*)(smem + NB_WH);
    __nv_bfloat16* AH = (__nv_bfloat16*)(smem + NB_AH);
    __nv_bfloat16* S2 = (__nv_bfloat16*)(smem + NB_S2);
    float* xg   = (float*)(smem + NB_XG);
    float* xns  = (float*)(smem + NB_XNS);
    float* ucen = (float*)(smem + NB_UCEN);
    float* b1s  = (float*)(smem + NB_B1);
    float* b2s  = (float*)(smem + NB_B2);
    int*   nidx = (int*)  (smem + NB_NIDX);

    const int tid  = threadIdx.x;
    const int wid  = tid >> 5;          // 0..7
    const int lane = tid & 31;
    const int g0   = blockIdx.x * 8;

    {
        const uint4* whg = (const uint4*)d_w2h;
        const uint4* wlg = (const uint4*)d_w2l;
        uint4* whs = (uint4*)WH;
        uint4* wls = (uint4*)S2;
        for (int i = tid; i < 2176; i += 256) { whs[i] = whg[i]; wls[i] = wlg[i]; }
    }
    if (tid < 128) { nidx[tid] = d_nbr[g0*KK + tid]; b1s[tid] = b1[tid]; b2s[tid] = b2[tid]; }
    for (int i = tid; i < 1024; i += 256) {
        int p = i >> 7, c = i & 127;
        ucen[i] = d_u[(size_t)(g0+p)*128 + c];
        xns[i]  = x  [(size_t)(g0+p)*128 + c];
    }
    __syncthreads();

    // build hidden hi-split into AH (lo recomputed later)
    const int c0 = lane*4;
    for (int r = wid; r < 128; r += 8) {
        int p = r >> 4;
        float4 uv = *reinterpret_cast<const float4*>(&d_u[(size_t)nidx[r]*128 + c0]);
        float h0 = fmaxf(uv.x - ucen[p*128 + c0+0] + b1s[c0+0], 0.f);
        float h1 = fmaxf(uv.y - ucen[p*128 + c0+1] + b1s[c0+1], 0.f);
        float h2 = fmaxf(uv.z - ucen[p*128 + c0+2] + b1s[c0+2], 0.f);
        float h3 = fmaxf(uv.w - ucen[p*128 + c0+3] + b1s[c0+3], 0.f);
        __nv_bfloat162 hA = __floats2bfloat162_rn(h0, h1);
        __nv_bfloat162 hB = __floats2bfloat162_rn(h2, h3);
        *(__nv_bfloat162*)&AH[r*WS2 + c0]     = hA;
        *(__nv_bfloat162*)&AH[r*WS2 + c0 + 2] = hB;
    }
    __syncthreads();

    // warp tiling: 4m x 2n, warp tile 32 rows x 64 cols
    const int wm = wid >> 1, wn = wid & 1;
    const int m0 = wm*32, n0 = wn*64;
    const int rA = lane >> 2;
    const int kA = (lane & 3) * 2;
    float acc[2][8][4];
    #pragma unroll
    for (int mt = 0; mt < 2; mt++)
        #pragma unroll
        for (int nt = 0; nt < 8; nt++)
            #pragma unroll
            for (int q = 0; q < 4; q++) acc[mt][nt][q] = 0.f;

#define GEMM_TERM(Ap, Bp) \
    { \
        const __nv_bfloat16* A = (Ap); \
        const __nv_bfloat16* B = (Bp); \
        _Pragma("unroll") \
        for (int kk = 0; kk < 128; kk += 16) { \
            uint32_t a[2][4], bfr[8][2]; \
            _Pragma("unroll") \
            for (int mt = 0; mt < 2; mt++) { \
                const __nv_bfloat16* ap = A + (m0 + mt*16 + rA)*WS2 + kk + kA; \
                a[mt][0] = *(const uint32_t*)ap; \
                a[mt][1] = *(const uint32_t*)(ap + 8*WS2); \
                a[mt][2] = *(const uint32_t*)(ap + 8); \
                a[mt][3] = *(const uint32_t*)(ap + 8*WS2 + 8); \
            } \
            _Pragma("unroll") \
            for (int nt = 0; nt < 8; nt++) { \
                const __nv_bfloat16* bp = B + (n0 + nt*8 + rA)*WS2 + kk + kA; \
                bfr[nt][0] = *(const uint32_t*)bp; \
                bfr[nt][1] = *(const uint32_t*)(bp + 8); \
            } \
            _Pragma("unroll") \
            for (int mt = 0; mt < 2; mt++) \
                _Pragma("unroll") \
                for (int nt = 0; nt < 8; nt++) \
                    mma16816(acc[mt][nt], a[mt], bfr[nt]); \
        } \
    }

    GEMM_TERM(AH, WH)    // Ah * Bh
    GEMM_TERM(AH, S2)    // Ah * Bl
    __syncthreads();

    // rebuild S2 as AL (same inputs, same arithmetic -> identical lo values)
    for (int r = wid; r < 128; r += 8) {
        int p = r >> 4;
        float4 uv = *reinterpret_cast<const float4*>(&d_u[(size_t)nidx[r]*128 + c0]);
        float h0 = fmaxf(uv.x - ucen[p*128 + c0+0] + b1s[c0+0], 0.f);
        float h1 = fmaxf(uv.y - ucen[p*128 + c0+1] + b1s[c0+1], 0.f);
        float h2 = fmaxf(uv.z - ucen[p*128 + c0+2] + b1s[c0+2], 0.f);
        float h3 = fmaxf(uv.w - ucen[p*128 + c0+3] + b1s[c0+3], 0.f);
        __nv_bfloat162 hA = __floats2bfloat162_rn(h0, h1);
        __nv_bfloat162 hB = __floats2bfloat162_rn(h2, h3);
        __nv_bfloat162 lA = __floats2bfloat162_rn(h0 - __low2float(hA), h1 - __high2float(hA));
        __nv_bfloat162 lB = __floats2bfloat162_rn(h2 - __low2float(hB), h3 - __high2float(hB));
        *(__nv_bfloat162*)&S2[r*WS2 + c0]     = lA;
        *(__nv_bfloat162*)&S2[r*WS2 + c0 + 2] = lB;
    }
    __syncthreads();

    GEMM_TERM(S2, WH)    // Al * Bh
    __syncthreads();     // done with AH/S2 -> reuse as xg

    // gather neighbor x rows into smem (coalesced)
    for (int r = wid; r < 128; r += 8)
        *reinterpret_cast<float4*>(&xg[r*132 + c0]) =
            *reinterpret_cast<const float4*>(&x[(size_t)nidx[r]*128 + c0]);
    __syncthreads();

    // epilogue: sigmoid, weight rel_x, reduce 16 rows, write res
    #pragma unroll
    for (int mt = 0; mt < 2; mt++) {
        const int p  = wm*2 + mt;
        const int r0 = m0 + mt*16 + rA;
        const int r1 = r0 + 8;
        #pragma unroll
        for (int nt = 0; nt < 8; nt++) {
            const int col0 = n0 + nt*8 + (lane & 3)*2;
            float z00 = acc[mt][nt][0] + b2s[col0];
            float z01 = acc[mt][nt][1] + b2s[col0+1];
            float z10 = acc[mt][nt][2] + b2s[col0];
            float z11 = acc[mt][nt][3] + b2s[col0+1];
            float s00 = 1.f/(1.f + __expf(-z00));
            float s01 = 1.f/(1.f + __expf(-z01));
            float s10 = 1.f/(1.f + __expf(-z10));
            float s11 = 1.f/(1.f + __expf(-z11));
            float xc0 = xns[p*128 + col0], xc1 = xns[p*128 + col0+1];
            float t0 = (xg[r0*132 + col0]   - xc0)*s00 + (xg[r1*132 + col0]   - xc0)*s10;
            float t1 = (xg[r0*132 + col0+1] - xc1)*s01 + (xg[r1*132 + col0+1] - xc1)*s11;
            t0 += __shfl_xor_sync(0xffffffffu, t0, 4);
            t0 += __shfl_xor_sync(0xffffffffu, t0, 8);
            t0 += __shfl_xor_sync(0xffffffffu, t0, 16);
            t1 += __shfl_xor_sync(0xffffffffu, t1, 4);
            t1 += __shfl_xor_sync(0xffffffffu, t1, 8);
            t1 += __shfl_xor_sync(0xffffffffu, t1, 16);
            if (lane < 4) {
                const size_t ob = (size_t)(g0+p)*128;
                float w0 = d_wself[ob + col0], w1 = d_wself[ob + col0+1];
                d_res[ob + col0]   = xc0*(1.f + w0) - t0;
                d_res[ob + col0+1] = xc1*(1.f + w1) - t1;
            }
        }
    }
#undef GEMM_TERM
}

// ---------------- tail GEMMs: 128 rows/block, 512 threads, fused BN stats ----------------
__global__ void __launch_bounds__(512) gemm_bias_kernel(const float* __restrict__ bias) {
    extern __shared__ float smg[];
    float* wts  = smg;           // 16384
    float* tile = smg + 16384;   // 128*132
    const int tid = threadIdx.x, g0 = blockIdx.x*128;
    for (int i = tid; i < 16384; i += 512) wts[i] = d_m1t[i];
    {
        const int lane = tid & 31, c0 = lane*4;
        for (int r = tid >> 5; r < 128; r += 16)
            *reinterpret_cast<float4*>(&tile[r*132 + c0]) =
                *reinterpret_cast<const float4*>(&d_res[(size_t)(g0+r)*128 + c0]);
    }
    __syncthreads();
    const int rg = tid >> 5, og = tid & 31;
    const int r0 = rg*8, o0 = og*4;
    float acc[8][4] = {};
    #pragma unroll 4
    for (int c = 0; c < 128; ++c) {
        float4 w4 = *reinterpret_cast<const float4*>(&wts[c*128 + o0]);
        float hh[8];
        #pragma unroll
        for (int r = 0; r < 8; r++) hh[r] = tile[(r0+r)*132 + c];
        #pragma unroll
        for (int r = 0; r < 8; r++) {
            acc[r][0] = fmaf(hh[r], w4.x, acc[r][0]);
            acc[r][1] = fmaf(hh[r], w4.y, acc[r][1]);
            acc[r][2] = fmaf(hh[r], w4.z, acc[r][2]);
            acc[r][3] = fmaf(hh[r], w4.w, acc[r][3]);
        }
    }
    float4 bb = *reinterpret_cast<const float4*>(&bias[o0]);
    float s[4] = {0,0,0,0}, s2[4] = {0,0,0,0};
    #pragma unroll
    for (int r = 0; r < 8; r++) {
        float v0 = acc[r][0]+bb.x, v1 = acc[r][1]+bb.y, v2 = acc[r][2]+bb.z, v3 = acc[r][3]+bb.w;
        *reinterpret_cast<float4*>(&d_t[(size_t)(g0+r0+r)*128 + o0]) =
            make_float4(v0, v1, v2, v3);
        s[0]+=v0; s[1]+=v1; s[2]+=v2; s[3]+=v3;
        s2[0]+=v0*v0; s2[1]+=v1*v1; s2[2]+=v2*v2; s2[3]+=v3*v3;
    }
    __syncthreads();
    float* ps  = wts;
    float* ps2 = wts + 2048;
    #pragma unroll
    for (int q = 0; q < 4; q++) { ps[rg*128 + o0+q] = s[q]; ps2[rg*128 + o0+q] = s2[q]; }
    __syncthreads();
    if (tid < 128) {
        float a = 0.f, b = 0.f;
        #pragma unroll
        for (int g = 0; g < 16; g++) { a += ps[g*128 + tid]; b += ps2[g*128 + tid]; }
        d_p1[blockIdx.x*128 + tid] = a;
        d_p2[blockIdx.x*128 + tid] = b;
    }
}

__global__ void __launch_bounds__(512) gemm_bn_relu_kernel(const float* __restrict__ bias,
                                                           float* __restrict__ out) {
    extern __shared__ float smh[];
    float* wts  = smh;
    float* tile = smh + 16384;
    const int tid = threadIdx.x, g0 = blockIdx.x*128;
    for (int i = tid; i < 16384; i += 512) wts[i] = d_m2t[i];
    {
        const int lane = tid & 31, c0 = lane*4;
        for (int r = tid >> 5; r < 128; r += 16) {
            float4 v = *reinterpret_cast<const float4*>(&d_t[(size_t)(g0+r)*128 + c0]);
            float4 h;
            h.x = fmaxf(fmaf(v.x, d_scale1[c0+0], d_shift1[c0+0]), 0.f);
            h.y = fmaxf(fmaf(v.y, d_scale1[c0+1], d_shift1[c0+1]), 0.f);
            h.z = fmaxf(fmaf(v.z, d_scale1[c0+2], d_shift1[c0+2]), 0.f);
            h.w = fmaxf(fmaf(v.w, d_scale1[c0+3], d_shift1[c0+3]), 0.f);
            *reinterpret_cast<float4*>(&tile[r*132 + c0]) = h;
        }
    }
    __syncthreads();
    const int rg = tid >> 5, og = tid & 31;
    const int r0 = rg*8, o0 = og*4;
    float acc[8][4] = {};
    #pragma unroll 4
    for (int c = 0; c < 128; ++c) {
        float4 w4 = *reinterpret_cast<const float4*>(&wts[c*128 + o0]);
        float hh[8];
        #pragma unroll
        for (int r = 0; r < 8; r++) hh[r] = tile[(r0+r)*132 + c];
        #pragma unroll
        for (int r = 0; r < 8; r++) {
            acc[r][0] = fmaf(hh[r], w4.x, acc[r][0]);
            acc[r][1] = fmaf(hh[r], w4.y, acc[r][1]);
            acc[r][2] = fmaf(hh[r], w4.z, acc[r][2]);
            acc[r][3] = fmaf(hh[r], w4.w, acc[r][3]);
        }
    }
    float4 bb = *reinterpret_cast<const float4*>(&bias[o0]);
    float s[4] = {0,0,0,0}, s2[4] = {0,0,0,0};
    #pragma unroll
    for (int r = 0; r < 8; r++) {
        float v0 = acc[r][0]+bb.x, v1 = acc[r][1]+bb.y, v2 = acc[r][2]+bb.z, v3 = acc[r][3]+bb.w;
        *reinterpret_cast<float4*>(&out[(size_t)(g0+r0+r)*128 + o0]) =
            make_float4(v0, v1, v2, v3);
        s[0]+=v0; s[1]+=v1; s[2]+=v2; s[3]+=v3;
        s2[0]+=v0*v0; s2[1]+=v1*v1; s2[2]+=v2*v2; s2[3]+=v3*v3;
    }
    __syncthreads();
    float* ps  = wts;
    float* ps2 = wts + 2048;
    #pragma unroll
    for (int q = 0; q < 4; q++) { ps[rg*128 + o0+q] = s[q]; ps2[rg*128 + o0+q] = s2[q]; }
    __syncthreads();
    if (tid < 128) {
        float a = 0.f, b = 0.f;
        #pragma unroll
        for (int g = 0; g < 16; g++) { a += ps[g*128 + tid]; b += ps2[g*128 + tid]; }
        d_p1[blockIdx.x*128 + tid] = a;
        d_p2[blockIdx.x*128 + tid] = b;
    }
}

// ---------------- BN finalize / apply ----------------
__global__ void bn_finalize_kernel(const float* __restrict__ g, const float* __restrict__ be,
                                   int which) {
    const int o = threadIdx.x;
    float s = 0.f, s2 = 0.f;
    for (int b = 0; b < 128; b++) { s += d_p1[b*128 + o]; s2 += d_p2[b*128 + o]; }
    float mu  = s  * (1.f/16384.f);
    float var = s2 * (1.f/16384.f) - mu*mu;
    float sc  = g[o] * rsqrtf(var + EPS);
    if (which == 0) { d_scale1[o] = sc; d_shift1[o] = be[o] - mu*sc; }
    else            { d_scale2[o] = sc; d_shift2[o] = be[o] - mu*sc; }
}

__global__ void bn_apply_kernel(float* __restrict__ out) {
    int i = blockIdx.x*blockDim.x + threadIdx.x;
    int o = i & 127;
    out[i] = fmaf(out[i], d_scale2[o], d_shift2[o]);
}

// ---------------- launch ----------------
extern "C" void kernel_launch(void* const* d_in, const int* in_sizes, int n_in,
                              void* d_out, int out_size) {
    (void)in_sizes; (void)n_in; (void)out_size;
    const float* x   = (const float*)d_in[0];
    const float* pos = (const float*)d_in[1];
    const float* w1  = (const float*)d_in[2];
    const float* b1  = (const float*)d_in[3];
    const float* w2  = (const float*)d_in[4];
    const float* b2  = (const float*)d_in[5];
    const float* m1  = (const float*)d_in[6];
    const float* mb1 = (const float*)d_in[7];
    const float* m2  = (const float*)d_in[8];
    const float* mb2 = (const float*)d_in[9];
    const float* g1  = (const float*)d_in[10];
    const float* be1 = (const float*)d_in[11];
    const float* g2  = (const float*)d_in[12];
    const float* be2 = (const float*)d_in[13];
    float* out = (float*)d_out;

    const int SMEM_KNN  = (32768 + 8192 + 8192) * 4;          // 196608
    const int SMEM_UG   = (16768 + 128*132) * 4;              // 134656
    const int SMEM_NB   = NB_SMEM;                            // 114176 -> 2 CTAs/SM
    const int SMEM_GB   = (16384 + 128*132) * 4;              // 133120

    cudaFuncSetAttribute(knn_kernel,          cudaFuncAttributeMaxDynamicSharedMemorySize, SMEM_KNN);
    cudaFuncSetAttribute(u_self_kernel,       cudaFuncAttributeMaxDynamicSharedMemorySize, SMEM_UG);
    cudaFuncSetAttribute(neighbor_kernel,     cudaFuncAttributeMaxDynamicSharedMemorySize, SMEM_NB);
    cudaFuncSetAttribute(gemm_bias_kernel,    cudaFuncAttributeMaxDynamicSharedMemorySize, SMEM_GB);
    cudaFuncSetAttribute(gemm_bn_relu_kernel, cudaFuncAttributeMaxDynamicSharedMemorySize, SMEM_GB);

    prep_kernel<<<66, 256>>>(w1, w2, m1, m2);
    knn_kernel<<<128, 512, SMEM_KNN>>>(pos);
    u_self_kernel<<<NPTS/128, 512, SMEM_UG>>>(x, pos, b1, b2);
    neighbor_kernel<<<NPTS/8, 256, SMEM_NB>>>(x, b1, b2);
    gemm_bias_kernel<<<NPTS/128, 512, SMEM_GB>>>(mb1);
    bn_finalize_kernel<<<1, 128>>>(g1, be1, 0);
    gemm_bn_relu_kernel<<<NPTS/128, 512, SMEM_GB>>>(mb2, out);
    bn_finalize_kernel<<<1, 128>>>(g2, be2, 1);
    bn_apply_kernel<<<(NPTS*CC)/256, 256>>>(out);
}

// round 11
// speedup vs baseline: 3.0555x; 1.0637x over previous
#include <cuda_runtime.h>
#include <cuda_bf16.h>
#include <cstdint>

// Problem constants
#define BB 2
#define NN 8192
#define CC 128
#define PP 3
#define KK 16
#define NPTS (BB*NN)          // 16384 total points
#define EPS 1e-5f

#define WS2 136               // bf16 row stride for MMA operands (conflict-free)

// ---------------- scratch (static device globals; no allocation) ----------------
__device__ __nv_bfloat16 d_w1h[128*WS2];  // W1x hi-split [o][c]
__device__ __nv_bfloat16 d_w1l[128*WS2];
__device__ float         d_w1p[128*3];    // W1 pos part (exact fp32)
__device__ __nv_bfloat16 d_w2h[128*WS2];
__device__ __nv_bfloat16 d_w2l[128*WS2];
__device__ __nv_bfloat16 d_m1h[128*WS2];
__device__ __nv_bfloat16 d_m1l[128*WS2];
__device__ __nv_bfloat16 d_m2h[128*WS2];
__device__ __nv_bfloat16 d_m2l[128*WS2];
__device__ int   d_nbr[NPTS*KK];
__device__ float d_u [NPTS*CC];      // W1 @ [x;pos]
__device__ float d_wself[NPTS*CC];   // sigmoid(W2 relu(ux+b1) + b2)
__device__ float d_res[NPTS*CC];
__device__ float d_t [NPTS*CC];
__device__ float d_p1[128*128];
__device__ float d_p2[128*128];
__device__ float d_scale1[CC], d_shift1[CC], d_scale2[CC], d_shift2[CC];

// ---------------- mma.sync helper (baseline PTX, works on compute_103) ----------------
__device__ __forceinline__ void mma16816(float* c, const uint32_t* a, const uint32_t* b) {
    asm volatile(
        "mma.sync.aligned.m16n8k16.row.col.f32.bf16.bf16.f32 "
        "{%0,%1,%2,%3}, {%4,%5,%6,%7}, {%8,%9}, {%0,%1,%2,%3};"
        : "+f"(c[0]), "+f"(c[1]), "+f"(c[2]), "+f"(c[3])
        : "r"(a[0]), "r"(a[1]), "r"(a[2]), "r"(a[3]), "r"(b[0]), "r"(b[1]));
}

__device__ __forceinline__ void split_store(__nv_bfloat16* H, __nv_bfloat16* L,
                                            int off, float a, float b) {
    __nv_bfloat162 hi = __floats2bfloat162_rn(a, b);
    __nv_bfloat162 lo = __floats2bfloat162_rn(a - __low2float(hi), b - __high2float(hi));
    *(__nv_bfloat162*)&H[off] = hi;
    *(__nv_bfloat162*)&L[off] = lo;
}

// ---------------- prep: build all bf16 weight splits ----------------
__global__ void prep_kernel(const float* __restrict__ w1, const float* __restrict__ w2,
                            const float* __restrict__ m1, const float* __restrict__ m2) {
    int i = blockIdx.x*blockDim.x + threadIdx.x;
    if (i < 128*128) {
        int o = i>>7, c = i&127;
        int off = o*WS2 + c;
        {
            float w = w1[o*131 + c];
            __nv_bfloat16 hi = __float2bfloat16(w);
            d_w1h[off] = hi; d_w1l[off] = __float2bfloat16(w - __bfloat162float(hi));
        }
        {
            float w = w2[i];
            __nv_bfloat16 hi = __float2bfloat16(w);
            d_w2h[off] = hi; d_w2l[off] = __float2bfloat16(w - __bfloat162float(hi));
        }
        {
            float w = m1[i];
            __nv_bfloat16 hi = __float2bfloat16(w);
            d_m1h[off] = hi; d_m1l[off] = __float2bfloat16(w - __bfloat162float(hi));
        }
        {
            float w = m2[i];
            __nv_bfloat16 hi = __float2bfloat16(w);
            d_m2h[off] = hi; d_m2l[off] = __float2bfloat16(w - __bfloat162float(hi));
        }
        if (c < 3) d_w1p[o*3 + c] = w1[o*131 + 128 + c];
    }
}

// ---------------- KNN: 4 threads per query, two-pass (threshold + capture) --------
__global__ void __launch_bounds__(512) knn_kernel(const float* __restrict__ pos) {
    extern __shared__ float sm[];
    float4* sp = (float4*)sm;            // 8192 float4 = 128KB
    float*  cd = sm + 32768;
    int*    ci = (int*)(cd + 8192);
    const int b   = blockIdx.x >> 6;
    const int blk = blockIdx.x & 63;
    const int tid = threadIdx.x;
    const float* pb = pos + (size_t)b*NN*3;
    for (int j = tid; j < NN; j += 512) {
        float px = pb[j*3+0], py = pb[j*3+1], pz = pb[j*3+2];
        sp[j] = make_float4(px, py, pz, px*px + py*py + pz*pz);
    }
    __syncthreads();
    const int ql  = tid & 127;
    const int seg = tid >> 7;
    const int q   = blk*128 + ql;
    const float4 qp = sp[q];
    const int j0 = seg*2048, j1 = j0 + 2048;

    float bd[KK];
    #pragma unroll
    for (int t = 0; t < KK; t++) bd[t] = 3.4e38f;
    #pragma unroll 2
    for (int j = j0; j < j1; j++) {
        float4 c = sp[j];
        float d = qp.w + c.w - 2.f*(qp.x*c.x + qp.y*c.y + qp.z*c.z);
        if (d < bd[KK-1]) {
            float dd = d;
            #pragma unroll
            for (int t = 0; t < KK; t++) {
                float mn = fminf(bd[t], dd);
                dd = fmaxf(bd[t], dd);
                bd[t] = mn;
            }
        }
    }
    const float tau = bd[KK-1];

    unsigned long long capb[48];
    int cnt = 0;
    #pragma unroll 2
    for (int j = j0; j < j1; j++) {
        float4 c = sp[j];
        float d = qp.w + c.w - 2.f*(qp.x*c.x + qp.y*c.y + qp.z*c.z);
        if (d <= tau && cnt < 48) {
            capb[cnt] = ((unsigned long long)__float_as_uint(d) << 32) | (unsigned)j;
            cnt++;
        }
    }

    float bd2[KK]; int bi2[KK];
    #pragma unroll
    for (int t = 0; t < KK; t++) { bd2[t] = 3.4e38f; bi2[t] = 0; }
    for (int cix = 0; cix < cnt; cix++) {
        unsigned long long v = capb[cix];
        float dd = __uint_as_float((unsigned)(v >> 32));
        int   ii = (int)(unsigned)(v & 0xffffffffu);
        if (dd < bd2[KK-1]) {
            #pragma unroll
            for (int t = 0; t < KK; t++) {
                if (dd < bd2[t]) {
                    float tf = bd2[t]; bd2[t] = dd; dd = tf;
                    int   ti = bi2[t]; bi2[t] = ii; ii = ti;
                }
            }
        }
    }
    {
        int row = tid*16;
        #pragma unroll
        for (int t = 0; t < KK; t++) { cd[row+t] = bd2[t]; ci[row+t] = bi2[t]; }
    }
    __syncthreads();

    if (tid < 128) {
        int p[4] = {0,0,0,0};
        int base[4];
        #pragma unroll
        for (int s = 0; s < 4; s++) base[s] = (s*128 + ql)*16;
        const int obase = (b*NN + q)*KK;
        #pragma unroll
        for (int t = 0; t < KK; t++) {
            float best = 3.5e38f; int bs = 0;
            #pragma unroll
            for (int s = 0; s < 4; s++) {
                float v = (p[s] < 16) ? cd[base[s] + p[s]] : 3.6e38f;
                if (v < best) { best = v; bs = s; }
            }
            d_nbr[obase + t] = b*NN + ci[base[bs] + p[bs]];
            p[bs]++;
        }
    }
}

// shared GEMM-term macro (warp tile 32x32, 4x4 warp grid, acc[2][4][4])
#define GEMM_TERM44(A_, B_, ACC_) \
    { \
        const __nv_bfloat16* A = (A_); \
        const __nv_bfloat16* B = (B_); \
        _Pragma("unroll") \
        for (int kk = 0; kk < 128; kk += 16) { \
            uint32_t a[2][4], bfr[4][2]; \
            _Pragma("unroll") \
            for (int mt = 0; mt < 2; mt++) { \
                const __nv_bfloat16* ap = A + (m0 + mt*16 + rA)*WS2 + kk + kA; \
                a[mt][0] = *(const uint32_t*)ap; \
                a[mt][1] = *(const uint32_t*)(ap + 8*WS2); \
                a[mt][2] = *(const uint32_t*)(ap + 8); \
                a[mt][3] = *(const uint32_t*)(ap + 8*WS2 + 8); \
            } \
            _Pragma("unroll") \
            for (int nt = 0; nt < 4; nt++) { \
                const __nv_bfloat16* bp = B + (n0 + nt*8 + rA)*WS2 + kk + kA; \
                bfr[nt][0] = *(const uint32_t*)bp; \
                bfr[nt][1] = *(const uint32_t*)(bp + 8); \
            } \
            _Pragma("unroll") \
            for (int mt = 0; mt < 2; mt++) \
                _Pragma("unroll") \
                for (int nt = 0; nt < 4; nt++) \
                    mma16816(ACC_[mt][nt], a[mt], bfr[nt]); \
        } \
    }

// ---------------- fused u + self kernel (all-MMA) ----------------
// GEMM1: ux = x @ W1x^T (split MMA); u = ux + pos @ W1p^T (exact fp32) -> d_u
// hidden = relu(ux + b1) -> smem splits;  GEMM2: wself = sigmoid(hidden @ w2^T + b2)
#define US_W1H 0
#define US_W1L 34816
#define US_W2H 69632
#define US_W2L 104448
#define US_AH  139264
#define US_AL  174080
#define US_POS 208896    // 128*3 f32
#define US_WP  210432    // 128*3 f32
#define US_B1  211968
#define US_B2  212480
#define US_SMEM 212992

__global__ void __launch_bounds__(512) u_self_kernel(const float* __restrict__ x,
                                                     const float* __restrict__ pos,
                                                     const float* __restrict__ b1,
                                                     const float* __restrict__ b2) {
    extern __shared__ char smem[];
    __nv_bfloat16* W1H = (__nv_bfloat16*)(smem + US_W1H);
    __nv_bfloat16* W1L = (__nv_bfloat16*)(smem + US_W1L);
    __nv_bfloat16* W2H = (__nv_bfloat16*)(smem + US_W2H);
    __nv_bfloat16* W2L = (__nv_bfloat16*)(smem + US_W2L);
    __nv_bfloat16* AH  = (__nv_bfloat16*)(smem + US_AH);
    __nv_bfloat16* AL  = (__nv_bfloat16*)(smem + US_AL);
    float* posS = (float*)(smem + US_POS);
    float* wpS  = (float*)(smem + US_WP);
    float* b1s  = (float*)(smem + US_B1);
    float* b2s  = (float*)(smem + US_B2);

    const int tid  = threadIdx.x;
    const int wid  = tid >> 5;
    const int lane = tid & 31;
    const int g0   = blockIdx.x * 128;

    {
        uint4* s1 = (uint4*)W1H; const uint4* g1 = (const uint4*)d_w1h;
        uint4* s2 = (uint4*)W1L; const uint4* g2 = (const uint4*)d_w1l;
        uint4* s3 = (uint4*)W2H; const uint4* g3 = (const uint4*)d_w2h;
        uint4* s4 = (uint4*)W2L; const uint4* g4 = (const uint4*)d_w2l;
        for (int i = tid; i < 2176; i += 512) {
            s1[i] = g1[i]; s2[i] = g2[i]; s3[i] = g3[i]; s4[i] = g4[i];
        }
    }
    if (tid < 384) {
        posS[tid] = pos[(size_t)g0*3 + tid];
        int o = tid/3, j = tid - o*3;
        wpS[tid] = d_w1p[o*3 + j];
    }
    if (tid < 128) { b1s[tid] = b1[tid]; b2s[tid] = b2[tid]; }
    // build x splits
    {
        const int c0 = lane*4;
        for (int r = wid; r < 128; r += 16) {
            float4 v = *(const float4*)&x[(size_t)(g0+r)*128 + c0];
            split_store(AH, AL, r*WS2 + c0,     v.x, v.y);
            split_store(AH, AL, r*WS2 + c0 + 2, v.z, v.w);
        }
    }
    __syncthreads();

    const int wm = wid >> 2, wn = wid & 3;
    const int m0 = wm*32, n0 = wn*32;
    const int rA = lane >> 2;
    const int kA = (lane & 3) * 2;
    float acc[2][4][4];
    #pragma unroll
    for (int mt = 0; mt < 2; mt++)
        #pragma unroll
        for (int nt = 0; nt < 4; nt++)
            #pragma unroll
            for (int q = 0; q < 4; q++) acc[mt][nt][q] = 0.f;

    GEMM_TERM44(AH, W1H, acc)
    GEMM_TERM44(AH, W1L, acc)
    GEMM_TERM44(AL, W1H, acc)

    // epilogue 1: u = ux + pos part (exact), write d_u; hidden splits into regs
    __nv_bfloat162 hhi[2][4][2], hlo[2][4][2];
    #pragma unroll
    for (int mt = 0; mt < 2; mt++) {
        const int row0 = m0 + mt*16 + rA, row1 = row0 + 8;
        float p00 = posS[row0*3], p01 = posS[row0*3+1], p02 = posS[row0*3+2];
        float p10 = posS[row1*3], p11 = posS[row1*3+1], p12 = posS[row1*3+2];
        #pragma unroll
        for (int nt = 0; nt < 4; nt++) {
            const int col0 = n0 + nt*8 + (lane & 3)*2;
            float wa0 = wpS[col0*3], wa1 = wpS[col0*3+1], wa2 = wpS[col0*3+2];
            float wb0 = wpS[col0*3+3], wb1 = wpS[col0*3+4], wb2 = wpS[col0*3+5];
            float u00 = fmaf(p02, wa2, fmaf(p01, wa1, fmaf(p00, wa0, acc[mt][nt][0])));
            float u01 = fmaf(p02, wb2, fmaf(p01, wb1, fmaf(p00, wb0, acc[mt][nt][1])));
            float u10 = fmaf(p12, wa2, fmaf(p11, wa1, fmaf(p10, wa0, acc[mt][nt][2])));
            float u11 = fmaf(p12, wb2, fmaf(p11, wb1, fmaf(p10, wb0, acc[mt][nt][3])));
            *(float2*)&d_u[(size_t)(g0+row0)*128 + col0] = make_float2(u00, u01);
            *(float2*)&d_u[(size_t)(g0+row1)*128 + col0] = make_float2(u10, u11);
            float h00 = fmaxf(acc[mt][nt][0] + b1s[col0],   0.f);
            float h01 = fmaxf(acc[mt][nt][1] + b1s[col0+1], 0.f);
            float h10 = fmaxf(acc[mt][nt][2] + b1s[col0],   0.f);
            float h11 = fmaxf(acc[mt][nt][3] + b1s[col0+1], 0.f);
            __nv_bfloat162 hi0 = __floats2bfloat162_rn(h00, h01);
            __nv_bfloat162 hi1 = __floats2bfloat162_rn(h10, h11);
            hhi[mt][nt][0] = hi0;
            hhi[mt][nt][1] = hi1;
            hlo[mt][nt][0] = __floats2bfloat162_rn(h00 - __low2float(hi0), h01 - __high2float(hi0));
            hlo[mt][nt][1] = __floats2bfloat162_rn(h10 - __low2float(hi1), h11 - __high2float(hi1));
        }
    }
    __syncthreads();     // everyone done reading AH/AL (x splits)
    #pragma unroll
    for (int mt = 0; mt < 2; mt++) {
        const int row0 = m0 + mt*16 + rA, row1 = row0 + 8;
        #pragma unroll
        for (int nt = 0; nt < 4; nt++) {
            const int col0 = n0 + nt*8 + (lane & 3)*2;
            *(__nv_bfloat162*)&AH[row0*WS2 + col0] = hhi[mt][nt][0];
            *(__nv_bfloat162*)&AH[row1*WS2 + col0] = hhi[mt][nt][1];
            *(__nv_bfloat162*)&AL[row0*WS2 + col0] = hlo[mt][nt][0];
            *(__nv_bfloat162*)&AL[row1*WS2 + col0] = hlo[mt][nt][1];
        }
    }
    __syncthreads();

    #pragma unroll
    for (int mt = 0; mt < 2; mt++)
        #pragma unroll
        for (int nt = 0; nt < 4; nt++)
            #pragma unroll
            for (int q = 0; q < 4; q++) acc[mt][nt][q] = 0.f;
    GEMM_TERM44(AH, W2H, acc)
    GEMM_TERM44(AH, W2L, acc)
    GEMM_TERM44(AL, W2H, acc)

    #pragma unroll
    for (int mt = 0; mt < 2; mt++) {
        const int row0 = m0 + mt*16 + rA, row1 = row0 + 8;
        #pragma unroll
        for (int nt = 0; nt < 4; nt++) {
            const int col0 = n0 + nt*8 + (lane & 3)*2;
            float s00 = 1.f/(1.f + __expf(-(acc[mt][nt][0] + b2s[col0])));
            float s01 = 1.f/(1.f + __expf(-(acc[mt][nt][1] + b2s[col0+1])));
            float s10 = 1.f/(1.f + __expf(-(acc[mt][nt][2] + b2s[col0])));
            float s11 = 1.f/(1.f + __expf(-(acc[mt][nt][3] + b2s[col0+1])));
            *(float2*)&d_wself[(size_t)(g0+row0)*128 + col0] = make_float2(s00, s01);
            *(float2*)&d_wself[(size_t)(g0+row1)*128 + col0] = make_float2(s10, s11);
        }
    }
}

// ---------------- fused neighbor kernel: mma.sync bf16-split, 2 CTAs/SM ----------------
#define NB_WH   0
#define NB_AH   34816
#define NB_S2   69632
#define NB_XG   34816
#define NB_XNS  104448
#define NB_UCEN 108544
#define NB_B1   112640
#define NB_B2   113152
#define NB_NIDX 113664
#define NB_SMEM 114176

__global__ void __launch_bounds__(256, 2) neighbor_kernel(const float* __restrict__ x,
                                const float* __restrict__ b1, const float* __restrict__ b2) {
    extern __shared__ char smem[];
    __nv_bfloat16* WH = (__nv_bfloat16*)(smem + NB_WH);
    __nv_bfloat16* AH = (__nv_bfloat16*)(smem + NB_AH);
    __nv_bfloat16* S2 = (__nv_bfloat16*)(smem + NB_S2);
    float* xg   = (float*)(smem + NB_XG);
    float* xns  = (float*)(smem + NB_XNS);
    float* ucen = (float*)(smem + NB_UCEN);
    float* b1s  = (float*)(smem + NB_B1);
    float* b2s  = (float*)(smem + NB_B2);
    int*   nidx = (int*)  (smem + NB_NIDX);

    const int tid  = threadIdx.x;
    const int wid  = tid >> 5;
    const int lane = tid & 31;
    const int g0   = blockIdx.x * 8;

    {
        const uint4* whg = (const uint4*)d_w2h;
        const uint4* wlg = (const uint4*)d_w2l;
        uint4* whs = (uint4*)WH;
        uint4* wls = (uint4*)S2;
        for (int i = tid; i < 2176; i += 256) { whs[i] = whg[i]; wls[i] = wlg[i]; }
    }
    if (tid < 128) { nidx[tid] = d_nbr[g0*KK + tid]; b1s[tid] = b1[tid]; b2s[tid] = b2[tid]; }
    for (int i = tid; i < 1024; i += 256) {
        int p = i >> 7, c = i & 127;
        ucen[i] = d_u[(size_t)(g0+p)*128 + c];
        xns[i]  = x  [(size_t)(g0+p)*128 + c];
    }
    __syncthreads();

    const int c0 = lane*4;
    for (int r = wid; r < 128; r += 8) {
        int p = r >> 4;
        float4 uv = *reinterpret_cast<const float4*>(&d_u[(size_t)nidx[r]*128 + c0]);
        float h0 = fmaxf(uv.x - ucen[p*128 + c0+0] + b1s[c0+0], 0.f);
        float h1 = fmaxf(uv.y - ucen[p*128 + c0+1] + b1s[c0+1], 0.f);
        float h2 = fmaxf(uv.z - ucen[p*128 + c0+2] + b1s[c0+2], 0.f);
        float h3 = fmaxf(uv.w - ucen[p*128 + c0+3] + b1s[c0+3], 0.f);
        __nv_bfloat162 hA = __floats2bfloat162_rn(h0, h1);
        __nv_bfloat162 hB = __floats2bfloat162_rn(h2, h3);
        *(__nv_bfloat162*)&AH[r*WS2 + c0]     = hA;
        *(__nv_bfloat162*)&AH[r*WS2 + c0 + 2] = hB;
    }
    __syncthreads();

    const int wm = wid >> 1, wn = wid & 1;
    const int m0 = wm*32, n0 = wn*64;
    const int rA = lane >> 2;
    const int kA = (lane & 3) * 2;
    float acc[2][8][4];
    #pragma unroll
    for (int mt = 0; mt < 2; mt++)
        #pragma unroll
        for (int nt = 0; nt < 8; nt++)
            #pragma unroll
            for (int q = 0; q < 4; q++) acc[mt][nt][q] = 0.f;

#define GEMM_TERM(Ap, Bp) \
    { \
        const __nv_bfloat16* A = (Ap); \
        const __nv_bfloat16* B = (Bp); \
        _Pragma("unroll") \
        for (int kk = 0; kk < 128; kk += 16) { \
            uint32_t a[2][4], bfr[8][2]; \
            _Pragma("unroll") \
            for (int mt = 0; mt < 2; mt++) { \
                const __nv_bfloat16* ap = A + (m0 + mt*16 + rA)*WS2 + kk + kA; \
                a[mt][0] = *(const uint32_t*)ap; \
                a[mt][1] = *(const uint32_t*)(ap + 8*WS2); \
                a[mt][2] = *(const uint32_t*)(ap + 8); \
                a[mt][3] = *(const uint32_t*)(ap + 8*WS2 + 8); \
            } \
            _Pragma("unroll") \
            for (int nt = 0; nt < 8; nt++) { \
                const __nv_bfloat16* bp = B + (n0 + nt*8 + rA)*WS2 + kk + kA; \
                bfr[nt][0] = *(const uint32_t*)bp; \
                bfr[nt][1] = *(const uint32_t*)(bp + 8); \
            } \
            _Pragma("unroll") \
            for (int mt = 0; mt < 2; mt++) \
                _Pragma("unroll") \
                for (int nt = 0; nt < 8; nt++) \
                    mma16816(acc[mt][nt], a[mt], bfr[nt]); \
        } \
    }

    GEMM_TERM(AH, WH)
    GEMM_TERM(AH, S2)
    __syncthreads();

    for (int r = wid; r < 128; r += 8) {
        int p = r >> 4;
        float4 uv = *reinterpret_cast<const float4*>(&d_u[(size_t)nidx[r]*128 + c0]);
        float h0 = fmaxf(uv.x - ucen[p*128 + c0+0] + b1s[c0+0], 0.f);
        float h1 = fmaxf(uv.y - ucen[p*128 + c0+1] + b1s[c0+1], 0.f);
        float h2 = fmaxf(uv.z - ucen[p*128 + c0+2] + b1s[c0+2], 0.f);
        float h3 = fmaxf(uv.w - ucen[p*128 + c0+3] + b1s[c0+3], 0.f);
        __nv_bfloat162 hA = __floats2bfloat162_rn(h0, h1);
        __nv_bfloat162 hB = __floats2bfloat162_rn(h2, h3);
        __nv_bfloat162 lA = __floats2bfloat162_rn(h0 - __low2float(hA), h1 - __high2float(hA));
        __nv_bfloat162 lB = __floats2bfloat162_rn(h2 - __low2float(hB), h3 - __high2float(hB));
        *(__nv_bfloat162*)&S2[r*WS2 + c0]     = lA;
        *(__nv_bfloat162*)&S2[r*WS2 + c0 + 2] = lB;
    }
    __syncthreads();

    GEMM_TERM(S2, WH)
    __syncthreads();

    for (int r = wid; r < 128; r += 8)
        *reinterpret_cast<float4*>(&xg[r*132 + c0]) =
            *reinterpret_cast<const float4*>(&x[(size_t)nidx[r]*128 + c0]);
    __syncthreads();

    #pragma unroll
    for (int mt = 0; mt < 2; mt++) {
        const int p  = wm*2 + mt;
        const int r0 = m0 + mt*16 + rA;
        const int r1 = r0 + 8;
        #pragma unroll
        for (int nt = 0; nt < 8; nt++) {
            const int col0 = n0 + nt*8 + (lane & 3)*2;
            float z00 = acc[mt][nt][0] + b2s[col0];
            float z01 = acc[mt][nt][1] + b2s[col0+1];
            float z10 = acc[mt][nt][2] + b2s[col0];
            float z11 = acc[mt][nt][3] + b2s[col0+1];
            float s00 = 1.f/(1.f + __expf(-z00));
            float s01 = 1.f/(1.f + __expf(-z01));
            float s10 = 1.f/(1.f + __expf(-z10));
            float s11 = 1.f/(1.f + __expf(-z11));
            float xc0 = xns[p*128 + col0], xc1 = xns[p*128 + col0+1];
            float t0 = (xg[r0*132 + col0]   - xc0)*s00 + (xg[r1*132 + col0]   - xc0)*s10;
            float t1 = (xg[r0*132 + col0+1] - xc1)*s01 + (xg[r1*132 + col0+1] - xc1)*s11;
            t0 += __shfl_xor_sync(0xffffffffu, t0, 4);
            t0 += __shfl_xor_sync(0xffffffffu, t0, 8);
            t0 += __shfl_xor_sync(0xffffffffu, t0, 16);
            t1 += __shfl_xor_sync(0xffffffffu, t1, 4);
            t1 += __shfl_xor_sync(0xffffffffu, t1, 8);
            t1 += __shfl_xor_sync(0xffffffffu, t1, 16);
            if (lane < 4) {
                const size_t ob = (size_t)(g0+p)*128;
                float w0 = d_wself[ob + col0], w1 = d_wself[ob + col0+1];
                d_res[ob + col0]   = xc0*(1.f + w0) - t0;
                d_res[ob + col0+1] = xc1*(1.f + w1) - t1;
            }
        }
    }
#undef GEMM_TERM
}

// ---------------- unified MMA tail GEMM (mode 1: res@m1 -> d_t; mode 2: bn+relu(d_t)@m2 -> out)
#define T_WH  0
#define T_WL  34816
#define T_AH  69632
#define T_AL  104448
#define T_BS  139264
#define T_SMEM 139776

__global__ void __launch_bounds__(512) tail_kernel(int mode, const float* __restrict__ bias,
                                                   float* __restrict__ out) {
    extern __shared__ char smem[];
    __nv_bfloat16* WH = (__nv_bfloat16*)(smem + T_WH);
    __nv_bfloat16* WL = (__nv_bfloat16*)(smem + T_WL);
    __nv_bfloat16* AH = (__nv_bfloat16*)(smem + T_AH);
    __nv_bfloat16* AL = (__nv_bfloat16*)(smem + T_AL);
    float* bs = (float*)(smem + T_BS);

    const int tid  = threadIdx.x;
    const int wid  = tid >> 5;
    const int lane = tid & 31;
    const int g0   = blockIdx.x * 128;

    {
        const uint4* whg = (const uint4*)(mode == 1 ? d_m1h : d_m2h);
        const uint4* wlg = (const uint4*)(mode == 1 ? d_m1l : d_m2l);
        uint4* whs = (uint4*)WH;
        uint4* wls = (uint4*)WL;
        for (int i = tid; i < 2176; i += 512) { whs[i] = whg[i]; wls[i] = wlg[i]; }
    }
    if (tid < 128) bs[tid] = bias[tid];
    {
        const int c0 = lane*4;
        for (int r = wid; r < 128; r += 16) {
            float4 v;
            if (mode == 1) {
                v = *(const float4*)&d_res[(size_t)(g0+r)*128 + c0];
            } else {
                float4 t = *(const float4*)&d_t[(size_t)(g0+r)*128 + c0];
                v.x = fmaxf(fmaf(t.x, d_scale1[c0+0], d_shift1[c0+0]), 0.f);
                v.y = fmaxf(fmaf(t.y, d_scale1[c0+1], d_shift1[c0+1]), 0.f);
                v.z = fmaxf(fmaf(t.z, d_scale1[c0+2], d_shift1[c0+2]), 0.f);
                v.w = fmaxf(fmaf(t.w, d_scale1[c0+3], d_shift1[c0+3]), 0.f);
            }
            split_store(AH, AL, r*WS2 + c0,     v.x, v.y);
            split_store(AH, AL, r*WS2 + c0 + 2, v.z, v.w);
        }
    }
    __syncthreads();

    const int wm = wid >> 2, wn = wid & 3;
    const int m0 = wm*32, n0 = wn*32;
    const int rA = lane >> 2;
    const int kA = (lane & 3) * 2;
    float acc[2][4][4];
    #pragma unroll
    for (int mt = 0; mt < 2; mt++)
        #pragma unroll
        for (int nt = 0; nt < 4; nt++)
            #pragma unroll
            for (int q = 0; q < 4; q++) acc[mt][nt][q] = 0.f;

    GEMM_TERM44(AH, WH, acc)
    GEMM_TERM44(AH, WL, acc)
    GEMM_TERM44(AL, WH, acc)

    float* dst = (mode == 1) ? d_t : out;
    float s[4][2], sq[4][2];
    #pragma unroll
    for (int nt = 0; nt < 4; nt++) { s[nt][0]=s[nt][1]=sq[nt][0]=sq[nt][1]=0.f; }

    #pragma unroll
    for (int mt = 0; mt < 2; mt++) {
        const int row0 = m0 + mt*16 + rA, row1 = row0 + 8;
        #pragma unroll
        for (int nt = 0; nt < 4; nt++) {
            const int col0 = n0 + nt*8 + (lane & 3)*2;
            float v00 = acc[mt][nt][0] + bs[col0];
            float v01 = acc[mt][nt][1] + bs[col0+1];
            float v10 = acc[mt][nt][2] + bs[col0];
            float v11 = acc[mt][nt][3] + bs[col0+1];
            *(float2*)&dst[(size_t)(g0+row0)*128 + col0] = make_float2(v00, v01);
            *(float2*)&dst[(size_t)(g0+row1)*128 + col0] = make_float2(v10, v11);
            s[nt][0]  += v00 + v10;      s[nt][1]  += v01 + v11;
            sq[nt][0] += v00*v00 + v10*v10;
            sq[nt][1] += v01*v01 + v11*v11;
        }
    }
    // reduce over the 8 rA groups (rows of the 32-row warp tile)
    #pragma unroll
    for (int nt = 0; nt < 4; nt++) {
        #pragma unroll
        for (int j = 0; j < 2; j++) {
            s[nt][j]  += __shfl_xor_sync(0xffffffffu, s[nt][j], 4);
            s[nt][j]  += __shfl_xor_sync(0xffffffffu, s[nt][j], 8);
            s[nt][j]  += __shfl_xor_sync(0xffffffffu, s[nt][j], 16);
            sq[nt][j] += __shfl_xor_sync(0xffffffffu, sq[nt][j], 4);
            sq[nt][j] += __shfl_xor_sync(0xffffffffu, sq[nt][j], 8);
            sq[nt][j] += __shfl_xor_sync(0xffffffffu, sq[nt][j], 16);
        }
    }
    __syncthreads();                      // done reading WH -> reuse for stats
    float* ps  = (float*)WH;              // 4*128
    float* ps2 = ps + 512;                // 4*128
    if (lane < 4) {
        #pragma unroll
        for (int nt = 0; nt < 4; nt++) {
            const int col0 = n0 + nt*8 + lane*2;
            ps [wm*128 + col0]   = s[nt][0];
            ps [wm*128 + col0+1] = s[nt][1];
            ps2[wm*128 + col0]   = sq[nt][0];
            ps2[wm*128 + col0+1] = sq[nt][1];
        }
    }
    __syncthreads();
    if (tid < 128) {
        float a = 0.f, b = 0.f;
        #pragma unroll
        for (int g = 0; g < 4; g++) { a += ps[g*128 + tid]; b += ps2[g*128 + tid]; }
        d_p1[blockIdx.x*128 + tid] = a;
        d_p2[blockIdx.x*128 + tid] = b;
    }
}

// ---------------- BN finalize / apply ----------------
__global__ void bn_finalize_kernel(const float* __restrict__ g, const float* __restrict__ be,
                                   int which) {
    const int o = threadIdx.x;
    float s = 0.f, s2 = 0.f;
    for (int b = 0; b < 128; b++) { s += d_p1[b*128 + o]; s2 += d_p2[b*128 + o]; }
    float mu  = s  * (1.f/16384.f);
    float var = s2 * (1.f/16384.f) - mu*mu;
    float sc  = g[o] * rsqrtf(var + EPS);
    if (which == 0) { d_scale1[o] = sc; d_shift1[o] = be[o] - mu*sc; }
    else            { d_scale2[o] = sc; d_shift2[o] = be[o] - mu*sc; }
}

__global__ void bn_apply_kernel(float* __restrict__ out) {
    int i = blockIdx.x*blockDim.x + threadIdx.x;
    int o = i & 127;
    out[i] = fmaf(out[i], d_scale2[o], d_shift2[o]);
}

// ---------------- launch ----------------
extern "C" void kernel_launch(void* const* d_in, const int* in_sizes, int n_in,
                              void* d_out, int out_size) {
    (void)in_sizes; (void)n_in; (void)out_size;
    const float* x   = (const float*)d_in[0];
    const float* pos = (const float*)d_in[1];
    const float* w1  = (const float*)d_in[2];
    const float* b1  = (const float*)d_in[3];
    const float* w2  = (const float*)d_in[4];
    const float* b2  = (const float*)d_in[5];
    const float* m1  = (const float*)d_in[6];
    const float* mb1 = (const float*)d_in[7];
    const float* m2  = (const float*)d_in[8];
    const float* mb2 = (const float*)d_in[9];
    const float* g1  = (const float*)d_in[10];
    const float* be1 = (const float*)d_in[11];
    const float* g2  = (const float*)d_in[12];
    const float* be2 = (const float*)d_in[13];
    float* out = (float*)d_out;

    const int SMEM_KNN = (32768 + 8192 + 8192) * 4;   // 196608

    cudaFuncSetAttribute(knn_kernel,      cudaFuncAttributeMaxDynamicSharedMemorySize, SMEM_KNN);
    cudaFuncSetAttribute(u_self_kernel,   cudaFuncAttributeMaxDynamicSharedMemorySize, US_SMEM);
    cudaFuncSetAttribute(neighbor_kernel, cudaFuncAttributeMaxDynamicSharedMemorySize, NB_SMEM);
    cudaFuncSetAttribute(tail_kernel,     cudaFuncAttributeMaxDynamicSharedMemorySize, T_SMEM);

    prep_kernel<<<64, 256>>>(w1, w2, m1, m2);
    knn_kernel<<<128, 512, SMEM_KNN>>>(pos);
    u_self_kernel<<<NPTS/128, 512, US_SMEM>>>(x, pos, b1, b2);
    neighbor_kernel<<<NPTS/8, 256, NB_SMEM>>>(x, b1, b2);
    tail_kernel<<<NPTS/128, 512, T_SMEM>>>(1, mb1, out);
    bn_finalize_kernel<<<1, 128>>>(g1, be1, 0);
    tail_kernel<<<NPTS/128, 512, T_SMEM>>>(2, mb2, out);
    bn_finalize_kernel<<<1, 128>>>(g2, be2, 1);
    bn_apply_kernel<<<(NPTS*CC)/256, 256>>>(out);
}

// round 12
// speedup vs baseline: 3.0571x; 1.0005x over previous
#include <cuda_runtime.h>
#include <cuda_bf16.h>
#include <cstdint>

// Problem constants
#define BB 2
#define NN 8192
#define CC 128
#define PP 3
#define KK 16
#define NPTS (BB*NN)          // 16384 total points
#define EPS 1e-5f

#define WS2 136               // bf16 row stride for MMA operands (conflict-free)

// ---------------- scratch (static device globals; no allocation) ----------------
__device__ __nv_bfloat16 d_w1h[128*WS2];  // W1x hi-split [o][c]
__device__ __nv_bfloat16 d_w1l[128*WS2];
__device__ float         d_w1p[128*3];    // W1 pos part (exact fp32)
__device__ __nv_bfloat16 d_w2h[128*WS2];
__device__ __nv_bfloat16 d_w2l[128*WS2];
__device__ __nv_bfloat16 d_m1h[128*WS2];
__device__ __nv_bfloat16 d_m1l[128*WS2];
__device__ __nv_bfloat16 d_m2h[128*WS2];
__device__ __nv_bfloat16 d_m2l[128*WS2];
__device__ int   d_nbr[NPTS*KK];
__device__ float d_u [NPTS*CC];
__device__ float d_wself[NPTS*CC];
__device__ float d_res[NPTS*CC];
__device__ float d_t [NPTS*CC];
__device__ float d_p1[128*128];
__device__ float d_p2[128*128];
__device__ float d_scale1[CC], d_shift1[CC], d_scale2[CC], d_shift2[CC];

// ---------------- mma/ldmatrix helpers (baseline PTX) ----------------
__device__ __forceinline__ void mma16816(float* c, const uint32_t* a, const uint32_t* b) {
    asm volatile(
        "mma.sync.aligned.m16n8k16.row.col.f32.bf16.bf16.f32 "
        "{%0,%1,%2,%3}, {%4,%5,%6,%7}, {%8,%9}, {%0,%1,%2,%3};"
        : "+f"(c[0]), "+f"(c[1]), "+f"(c[2]), "+f"(c[3])
        : "r"(a[0]), "r"(a[1]), "r"(a[2]), "r"(a[3]), "r"(b[0]), "r"(b[1]));
}
__device__ __forceinline__ void ldsm_x4(uint32_t addr, uint32_t* r) {
    asm volatile("ldmatrix.sync.aligned.m8n8.x4.shared.b16 {%0,%1,%2,%3}, [%4];"
        : "=r"(r[0]), "=r"(r[1]), "=r"(r[2]), "=r"(r[3]) : "r"(addr));
}
__device__ __forceinline__ uint32_t smem_u32(const void* p) {
    return (uint32_t)__cvta_generic_to_shared(p);
}
__device__ __forceinline__ void split_store(__nv_bfloat16* H, __nv_bfloat16* L,
                                            int off, float a, float b) {
    __nv_bfloat162 hi = __floats2bfloat162_rn(a, b);
    __nv_bfloat162 lo = __floats2bfloat162_rn(a - __low2float(hi), b - __high2float(hi));
    *(__nv_bfloat162*)&H[off] = hi;
    *(__nv_bfloat162*)&L[off] = lo;
}

// ldmatrix lane offsets (bytes) — reproduce the scalar fragment layout exactly.
// A (16x16 tile): mats {r0-7/k0-7, r8-15/k0-7, r0-7/k8-15, r8-15/k8-15}
#define AOFF(lane) ((uint32_t)((((lane)&7) + (((lane)>>3)&1)*8)*WS2*2 + ((lane)>>4)*16))
// B (two n8k16 tiles): mats {n0-7/k0-7, n0-7/k8-15, n8-15/k0-7, n8-15/k8-15}
#define BOFF(lane) ((uint32_t)((((lane)&7) + ((lane)>>4)*8)*WS2*2 + (((lane)>>3)&1)*16))

// GEMM term, 32x32 warp tile (4 nt), acc[2][4][4]
#define GEMM_TERM44(Au, Bu, ACC_) \
    { \
        const uint32_t ab = (Au) + (uint32_t)(m0*WS2*2) + aoff; \
        const uint32_t bb = (Bu) + (uint32_t)(n0*WS2*2) + boff; \
        _Pragma("unroll") \
        for (int kk = 0; kk < 128; kk += 16) { \
            uint32_t a[2][4], bfr[2][4]; \
            ldsm_x4(ab + (kk<<1), a[0]); \
            ldsm_x4(ab + 16*WS2*2 + (kk<<1), a[1]); \
            _Pragma("unroll") \
            for (int j = 0; j < 2; j++) ldsm_x4(bb + j*16*WS2*2 + (kk<<1), bfr[j]); \
            _Pragma("unroll") \
            for (int mt = 0; mt < 2; mt++) \
                _Pragma("unroll") \
                for (int j = 0; j < 2; j++) { \
                    mma16816(ACC_[mt][2*j],   a[mt], &bfr[j][0]); \
                    mma16816(ACC_[mt][2*j+1], a[mt], &bfr[j][2]); \
                } \
        } \
    }

// GEMM term, 32x64 warp tile (8 nt), acc[2][8][4]
#define GEMM_TERM48(Au, Bu) \
    { \
        const uint32_t ab = (Au) + (uint32_t)(m0*WS2*2) + aoff; \
        const uint32_t bb = (Bu) + (uint32_t)(n0*WS2*2) + boff; \
        _Pragma("unroll") \
        for (int kk = 0; kk < 128; kk += 16) { \
            uint32_t a[2][4], bfr[4][4]; \
            ldsm_x4(ab + (kk<<1), a[0]); \
            ldsm_x4(ab + 16*WS2*2 + (kk<<1), a[1]); \
            _Pragma("unroll") \
            for (int j = 0; j < 4; j++) ldsm_x4(bb + j*16*WS2*2 + (kk<<1), bfr[j]); \
            _Pragma("unroll") \
            for (int mt = 0; mt < 2; mt++) \
                _Pragma("unroll") \
                for (int j = 0; j < 4; j++) { \
                    mma16816(acc[mt][2*j],   a[mt], &bfr[j][0]); \
                    mma16816(acc[mt][2*j+1], a[mt], &bfr[j][2]); \
                } \
        } \
    }

// ---------------- prep: build all bf16 weight splits ----------------
__global__ void prep_kernel(const float* __restrict__ w1, const float* __restrict__ w2,
                            const float* __restrict__ m1, const float* __restrict__ m2) {
    int i = blockIdx.x*blockDim.x + threadIdx.x;
    if (i < 128*128) {
        int o = i>>7, c = i&127;
        int off = o*WS2 + c;
        {
            float w = w1[o*131 + c];
            __nv_bfloat16 hi = __float2bfloat16(w);
            d_w1h[off] = hi; d_w1l[off] = __float2bfloat16(w - __bfloat162float(hi));
        }
        {
            float w = w2[i];
            __nv_bfloat16 hi = __float2bfloat16(w);
            d_w2h[off] = hi; d_w2l[off] = __float2bfloat16(w - __bfloat162float(hi));
        }
        {
            float w = m1[i];
            __nv_bfloat16 hi = __float2bfloat16(w);
            d_m1h[off] = hi; d_m1l[off] = __float2bfloat16(w - __bfloat162float(hi));
        }
        {
            float w = m2[i];
            __nv_bfloat16 hi = __float2bfloat16(w);
            d_m2h[off] = hi; d_m2l[off] = __float2bfloat16(w - __bfloat162float(hi));
        }
        if (c < 3) d_w1p[o*3 + c] = w1[o*131 + 128 + c];
    }
}

// ---------------- KNN: 4 threads per query, two-pass (threshold + capture) --------
__global__ void __launch_bounds__(512) knn_kernel(const float* __restrict__ pos) {
    extern __shared__ float sm[];
    float4* sp = (float4*)sm;
    float*  cd = sm + 32768;
    int*    ci = (int*)(cd + 8192);
    const int b   = blockIdx.x >> 6;
    const int blk = blockIdx.x & 63;
    const int tid = threadIdx.x;
    const float* pb = pos + (size_t)b*NN*3;
    for (int j = tid; j < NN; j += 512) {
        float px = pb[j*3+0], py = pb[j*3+1], pz = pb[j*3+2];
        sp[j] = make_float4(px, py, pz, px*px + py*py + pz*pz);
    }
    __syncthreads();
    const int ql  = tid & 127;
    const int seg = tid >> 7;
    const int q   = blk*128 + ql;
    const float4 qp = sp[q];
    const int j0 = seg*2048, j1 = j0 + 2048;

    float bd[KK];
    #pragma unroll
    for (int t = 0; t < KK; t++) bd[t] = 3.4e38f;
    #pragma unroll 2
    for (int j = j0; j < j1; j++) {
        float4 c = sp[j];
        float d = qp.w + c.w - 2.f*(qp.x*c.x + qp.y*c.y + qp.z*c.z);
        if (d < bd[KK-1]) {
            float dd = d;
            #pragma unroll
            for (int t = 0; t < KK; t++) {
                float mn = fminf(bd[t], dd);
                dd = fmaxf(bd[t], dd);
                bd[t] = mn;
            }
        }
    }
    const float tau = bd[KK-1];

    unsigned long long capb[48];
    int cnt = 0;
    #pragma unroll 2
    for (int j = j0; j < j1; j++) {
        float4 c = sp[j];
        float d = qp.w + c.w - 2.f*(qp.x*c.x + qp.y*c.y + qp.z*c.z);
        if (d <= tau && cnt < 48) {
            capb[cnt] = ((unsigned long long)__float_as_uint(d) << 32) | (unsigned)j;
            cnt++;
        }
    }

    float bd2[KK]; int bi2[KK];
    #pragma unroll
    for (int t = 0; t < KK; t++) { bd2[t] = 3.4e38f; bi2[t] = 0; }
    for (int cix = 0; cix < cnt; cix++) {
        unsigned long long v = capb[cix];
        float dd = __uint_as_float((unsigned)(v >> 32));
        int   ii = (int)(unsigned)(v & 0xffffffffu);
        if (dd < bd2[KK-1]) {
            #pragma unroll
            for (int t = 0; t < KK; t++) {
                if (dd < bd2[t]) {
                    float tf = bd2[t]; bd2[t] = dd; dd = tf;
                    int   ti = bi2[t]; bi2[t] = ii; ii = ti;
                }
            }
        }
    }
    {
        int row = tid*16;
        #pragma unroll
        for (int t = 0; t < KK; t++) { cd[row+t] = bd2[t]; ci[row+t] = bi2[t]; }
    }
    __syncthreads();

    if (tid < 128) {
        int p[4] = {0,0,0,0};
        int base[4];
        #pragma unroll
        for (int s = 0; s < 4; s++) base[s] = (s*128 + ql)*16;
        const int obase = (b*NN + q)*KK;
        #pragma unroll
        for (int t = 0; t < KK; t++) {
            float best = 3.5e38f; int bs = 0;
            #pragma unroll
            for (int s = 0; s < 4; s++) {
                float v = (p[s] < 16) ? cd[base[s] + p[s]] : 3.6e38f;
                if (v < best) { best = v; bs = s; }
            }
            d_nbr[obase + t] = b*NN + ci[base[bs] + p[bs]];
            p[bs]++;
        }
    }
}

// ---------------- fused u + self kernel (all-MMA) ----------------
#define US_W1H 0
#define US_W1L 34816
#define US_W2H 69632
#define US_W2L 104448
#define US_AH  139264
#define US_AL  174080
#define US_POS 208896
#define US_WP  210432
#define US_B1  211968
#define US_B2  212480
#define US_SMEM 212992

__global__ void __launch_bounds__(512) u_self_kernel(const float* __restrict__ x,
                                                     const float* __restrict__ pos,
                                                     const float* __restrict__ b1,
                                                     const float* __restrict__ b2) {
    extern __shared__ char smem[];
    __nv_bfloat16* W1H = (__nv_bfloat16*)(smem + US_W1H);
    __nv_bfloat16* W1L = (__nv_bfloat16*)(smem + US_W1L);
    __nv_bfloat16* W2H = (__nv_bfloat16*)(smem + US_W2H);
    __nv_bfloat16* W2L = (__nv_bfloat16*)(smem + US_W2L);
    __nv_bfloat16* AH  = (__nv_bfloat16*)(smem + US_AH);
    __nv_bfloat16* AL  = (__nv_bfloat16*)(smem + US_AL);
    float* posS = (float*)(smem + US_POS);
    float* wpS  = (float*)(smem + US_WP);
    float* b1s  = (float*)(smem + US_B1);
    float* b2s  = (float*)(smem + US_B2);

    const int tid  = threadIdx.x;
    const int wid  = tid >> 5;
    const int lane = tid & 31;
    const int g0   = blockIdx.x * 128;

    {
        uint4* s1 = (uint4*)W1H; const uint4* g1 = (const uint4*)d_w1h;
        uint4* s2 = (uint4*)W1L; const uint4* g2 = (const uint4*)d_w1l;
        uint4* s3 = (uint4*)W2H; const uint4* g3 = (const uint4*)d_w2h;
        uint4* s4 = (uint4*)W2L; const uint4* g4 = (const uint4*)d_w2l;
        for (int i = tid; i < 2176; i += 512) {
            s1[i] = g1[i]; s2[i] = g2[i]; s3[i] = g3[i]; s4[i] = g4[i];
        }
    }
    if (tid < 384) {
        posS[tid] = pos[(size_t)g0*3 + tid];
        int o = tid/3, j = tid - o*3;
        wpS[tid] = d_w1p[o*3 + j];
    }
    if (tid < 128) { b1s[tid] = b1[tid]; b2s[tid] = b2[tid]; }
    {
        const int c0 = lane*4;
        for (int r = wid; r < 128; r += 16) {
            float4 v = *(const float4*)&x[(size_t)(g0+r)*128 + c0];
            split_store(AH, AL, r*WS2 + c0,     v.x, v.y);
            split_store(AH, AL, r*WS2 + c0 + 2, v.z, v.w);
        }
    }
    __syncthreads();

    const int wm = wid >> 2, wn = wid & 3;
    const int m0 = wm*32, n0 = wn*32;
    const int rA = lane >> 2;
    const uint32_t aoff = AOFF(lane), boff = BOFF(lane);
    const uint32_t AHu = smem_u32(AH), ALu = smem_u32(AL);
    const uint32_t W1Hu = smem_u32(W1H), W1Lu = smem_u32(W1L);
    const uint32_t W2Hu = smem_u32(W2H), W2Lu = smem_u32(W2L);
    float acc[2][4][4];
    #pragma unroll
    for (int mt = 0; mt < 2; mt++)
        #pragma unroll
        for (int nt = 0; nt < 4; nt++)
            #pragma unroll
            for (int q = 0; q < 4; q++) acc[mt][nt][q] = 0.f;

    GEMM_TERM44(AHu, W1Hu, acc)
    GEMM_TERM44(AHu, W1Lu, acc)
    GEMM_TERM44(ALu, W1Hu, acc)

    __nv_bfloat162 hhi[2][4][2], hlo[2][4][2];
    #pragma unroll
    for (int mt = 0; mt < 2; mt++) {
        const int row0 = m0 + mt*16 + rA, row1 = row0 + 8;
        float p00 = posS[row0*3], p01 = posS[row0*3+1], p02 = posS[row0*3+2];
        float p10 = posS[row1*3], p11 = posS[row1*3+1], p12 = posS[row1*3+2];
        #pragma unroll
        for (int nt = 0; nt < 4; nt++) {
            const int col0 = n0 + nt*8 + (lane & 3)*2;
            float wa0 = wpS[col0*3], wa1 = wpS[col0*3+1], wa2 = wpS[col0*3+2];
            float wb0 = wpS[col0*3+3], wb1 = wpS[col0*3+4], wb2 = wpS[col0*3+5];
            float u00 = fmaf(p02, wa2, fmaf(p01, wa1, fmaf(p00, wa0, acc[mt][nt][0])));
            float u01 = fmaf(p02, wb2, fmaf(p01, wb1, fmaf(p00, wb0, acc[mt][nt][1])));
            float u10 = fmaf(p12, wa2, fmaf(p11, wa1, fmaf(p10, wa0, acc[mt][nt][2])));
            float u11 = fmaf(p12, wb2, fmaf(p11, wb1, fmaf(p10, wb0, acc[mt][nt][3])));
            *(float2*)&d_u[(size_t)(g0+row0)*128 + col0] = make_float2(u00, u01);
            *(float2*)&d_u[(size_t)(g0+row1)*128 + col0] = make_float2(u10, u11);
            float h00 = fmaxf(acc[mt][nt][0] + b1s[col0],   0.f);
            float h01 = fmaxf(acc[mt][nt][1] + b1s[col0+1], 0.f);
            float h10 = fmaxf(acc[mt][nt][2] + b1s[col0],   0.f);
            float h11 = fmaxf(acc[mt][nt][3] + b1s[col0+1], 0.f);
            __nv_bfloat162 hi0 = __floats2bfloat162_rn(h00, h01);
            __nv_bfloat162 hi1 = __floats2bfloat162_rn(h10, h11);
            hhi[mt][nt][0] = hi0;
            hhi[mt][nt][1] = hi1;
            hlo[mt][nt][0] = __floats2bfloat162_rn(h00 - __low2float(hi0), h01 - __high2float(hi0));
            hlo[mt][nt][1] = __floats2bfloat162_rn(h10 - __low2float(hi1), h11 - __high2float(hi1));
        }
    }
    __syncthreads();
    #pragma unroll
    for (int mt = 0; mt < 2; mt++) {
        const int row0 = m0 + mt*16 + rA, row1 = row0 + 8;
        #pragma unroll
        for (int nt = 0; nt < 4; nt++) {
            const int col0 = n0 + nt*8 + (lane & 3)*2;
            *(__nv_bfloat162*)&AH[row0*WS2 + col0] = hhi[mt][nt][0];
            *(__nv_bfloat162*)&AH[row1*WS2 + col0] = hhi[mt][nt][1];
            *(__nv_bfloat162*)&AL[row0*WS2 + col0] = hlo[mt][nt][0];
            *(__nv_bfloat162*)&AL[row1*WS2 + col0] = hlo[mt][nt][1];
        }
    }
    __syncthreads();

    #pragma unroll
    for (int mt = 0; mt < 2; mt++)
        #pragma unroll
        for (int nt = 0; nt < 4; nt++)
            #pragma unroll
            for (int q = 0; q < 4; q++) acc[mt][nt][q] = 0.f;
    GEMM_TERM44(AHu, W2Hu, acc)
    GEMM_TERM44(AHu, W2Lu, acc)
    GEMM_TERM44(ALu, W2Hu, acc)

    #pragma unroll
    for (int mt = 0; mt < 2; mt++) {
        const int row0 = m0 + mt*16 + rA, row1 = row0 + 8;
        #pragma unroll
        for (int nt = 0; nt < 4; nt++) {
            const int col0 = n0 + nt*8 + (lane & 3)*2;
            float s00 = 1.f/(1.f + __expf(-(acc[mt][nt][0] + b2s[col0])));
            float s01 = 1.f/(1.f + __expf(-(acc[mt][nt][1] + b2s[col0+1])));
            float s10 = 1.f/(1.f + __expf(-(acc[mt][nt][2] + b2s[col0])));
            float s11 = 1.f/(1.f + __expf(-(acc[mt][nt][3] + b2s[col0+1])));
            *(float2*)&d_wself[(size_t)(g0+row0)*128 + col0] = make_float2(s00, s01);
            *(float2*)&d_wself[(size_t)(g0+row1)*128 + col0] = make_float2(s10, s11);
        }
    }
}

// ---------------- fused neighbor kernel: mma.sync bf16-split, 2 CTAs/SM ----------------
#define NB_WH   0
#define NB_AH   34816
#define NB_S2   69632
#define NB_XG   34816
#define NB_XNS  104448
#define NB_UCEN 108544
#define NB_B1   112640
#define NB_B2   113152
#define NB_NIDX 113664
#define NB_SMEM 114176

__global__ void __launch_bounds__(256, 2) neighbor_kernel(const float* __restrict__ x,
                                const float* __restrict__ b1, const float* __restrict__ b2) {
    extern __shared__ char smem[];
    __nv_bfloat16* WH = (__nv_bfloat16*)(smem + NB_WH);
    __nv_bfloat16* AH = (__nv_bfloat16*)(smem + NB_AH);
    __nv_bfloat16* S2 = (__nv_bfloat16*)(smem + NB_S2);
    float* xg   = (float*)(smem + NB_XG);
    float* xns  = (float*)(smem + NB_XNS);
    float* ucen = (float*)(smem + NB_UCEN);
    float* b1s  = (float*)(smem + NB_B1);
    float* b2s  = (float*)(smem + NB_B2);
    int*   nidx = (int*)  (smem + NB_NIDX);

    const int tid  = threadIdx.x;
    const int wid  = tid >> 5;
    const int lane = tid & 31;
    const int g0   = blockIdx.x * 8;

    {
        const uint4* whg = (const uint4*)d_w2h;
        const uint4* wlg = (const uint4*)d_w2l;
        uint4* whs = (uint4*)WH;
        uint4* wls = (uint4*)S2;
        for (int i = tid; i < 2176; i += 256) { whs[i] = whg[i]; wls[i] = wlg[i]; }
    }
    if (tid < 128) { nidx[tid] = d_nbr[g0*KK + tid]; b1s[tid] = b1[tid]; b2s[tid] = b2[tid]; }
    for (int i = tid; i < 1024; i += 256) {
        int p = i >> 7, c = i & 127;
        ucen[i] = d_u[(size_t)(g0+p)*128 + c];
        xns[i]  = x  [(size_t)(g0+p)*128 + c];
    }
    __syncthreads();

    const int c0 = lane*4;
    for (int r = wid; r < 128; r += 8) {
        int p = r >> 4;
        float4 uv = *reinterpret_cast<const float4*>(&d_u[(size_t)nidx[r]*128 + c0]);
        float h0 = fmaxf(uv.x - ucen[p*128 + c0+0] + b1s[c0+0], 0.f);
        float h1 = fmaxf(uv.y - ucen[p*128 + c0+1] + b1s[c0+1], 0.f);
        float h2 = fmaxf(uv.z - ucen[p*128 + c0+2] + b1s[c0+2], 0.f);
        float h3 = fmaxf(uv.w - ucen[p*128 + c0+3] + b1s[c0+3], 0.f);
        __nv_bfloat162 hA = __floats2bfloat162_rn(h0, h1);
        __nv_bfloat162 hB = __floats2bfloat162_rn(h2, h3);
        *(__nv_bfloat162*)&AH[r*WS2 + c0]     = hA;
        *(__nv_bfloat162*)&AH[r*WS2 + c0 + 2] = hB;
    }
    __syncthreads();

    const int wm = wid >> 1, wn = wid & 1;
    const int m0 = wm*32, n0 = wn*64;
    const int rA = lane >> 2;
    const uint32_t aoff = AOFF(lane), boff = BOFF(lane);
    const uint32_t WHu = smem_u32(WH), AHu = smem_u32(AH), S2u = smem_u32(S2);
    float acc[2][8][4];
    #pragma unroll
    for (int mt = 0; mt < 2; mt++)
        #pragma unroll
        for (int nt = 0; nt < 8; nt++)
            #pragma unroll
            for (int q = 0; q < 4; q++) acc[mt][nt][q] = 0.f;

    GEMM_TERM48(AHu, WHu)
    GEMM_TERM48(AHu, S2u)
    __syncthreads();

    // rebuild S2 as AL (same inputs, same arithmetic -> identical lo values)
    for (int r = wid; r < 128; r += 8) {
        int p = r >> 4;
        float4 uv = *reinterpret_cast<const float4*>(&d_u[(size_t)nidx[r]*128 + c0]);
        float h0 = fmaxf(uv.x - ucen[p*128 + c0+0] + b1s[c0+0], 0.f);
        float h1 = fmaxf(uv.y - ucen[p*128 + c0+1] + b1s[c0+1], 0.f);
        float h2 = fmaxf(uv.z - ucen[p*128 + c0+2] + b1s[c0+2], 0.f);
        float h3 = fmaxf(uv.w - ucen[p*128 + c0+3] + b1s[c0+3], 0.f);
        __nv_bfloat162 hA = __floats2bfloat162_rn(h0, h1);
        __nv_bfloat162 hB = __floats2bfloat162_rn(h2, h3);
        __nv_bfloat162 lA = __floats2bfloat162_rn(h0 - __low2float(hA), h1 - __high2float(hA));
        __nv_bfloat162 lB = __floats2bfloat162_rn(h2 - __low2float(hB), h3 - __high2float(hB));
        *(__nv_bfloat162*)&S2[r*WS2 + c0]     = lA;
        *(__nv_bfloat162*)&S2[r*WS2 + c0 + 2] = lB;
    }
    __syncthreads();

    GEMM_TERM48(S2u, WHu)
    __syncthreads();

    for (int r = wid; r < 128; r += 8)
        *reinterpret_cast<float4*>(&xg[r*132 + c0]) =
            *reinterpret_cast<const float4*>(&x[(size_t)nidx[r]*128 + c0]);
    __syncthreads();

    #pragma unroll
    for (int mt = 0; mt < 2; mt++) {
        const int p  = wm*2 + mt;
        const int r0 = m0 + mt*16 + rA;
        const int r1 = r0 + 8;
        #pragma unroll
        for (int nt = 0; nt < 8; nt++) {
            const int col0 = n0 + nt*8 + (lane & 3)*2;
            float z00 = acc[mt][nt][0] + b2s[col0];
            float z01 = acc[mt][nt][1] + b2s[col0+1];
            float z10 = acc[mt][nt][2] + b2s[col0];
            float z11 = acc[mt][nt][3] + b2s[col0+1];
            float s00 = 1.f/(1.f + __expf(-z00));
            float s01 = 1.f/(1.f + __expf(-z01));
            float s10 = 1.f/(1.f + __expf(-z10));
            float s11 = 1.f/(1.f + __expf(-z11));
            float xc0 = xns[p*128 + col0], xc1 = xns[p*128 + col0+1];
            float t0 = (xg[r0*132 + col0]   - xc0)*s00 + (xg[r1*132 + col0]   - xc0)*s10;
            float t1 = (xg[r0*132 + col0+1] - xc1)*s01 + (xg[r1*132 + col0+1] - xc1)*s11;
            t0 += __shfl_xor_sync(0xffffffffu, t0, 4);
            t0 += __shfl_xor_sync(0xffffffffu, t0, 8);
            t0 += __shfl_xor_sync(0xffffffffu, t0, 16);
            t1 += __shfl_xor_sync(0xffffffffu, t1, 4);
            t1 += __shfl_xor_sync(0xffffffffu, t1, 8);
            t1 += __shfl_xor_sync(0xffffffffu, t1, 16);
            if (lane < 4) {
                const size_t ob = (size_t)(g0+p)*128;
                float w0 = d_wself[ob + col0], w1 = d_wself[ob + col0+1];
                d_res[ob + col0]   = xc0*(1.f + w0) - t0;
                d_res[ob + col0+1] = xc1*(1.f + w1) - t1;
            }
        }
    }
}

// ---------------- unified MMA tail GEMM ----------------
#define T_WH  0
#define T_WL  34816
#define T_AH  69632
#define T_AL  104448
#define T_BS  139264
#define T_SMEM 139776

__global__ void __launch_bounds__(512) tail_kernel(int mode, const float* __restrict__ bias,
                                                   float* __restrict__ out) {
    extern __shared__ char smem[];
    __nv_bfloat16* WH = (__nv_bfloat16*)(smem + T_WH);
    __nv_bfloat16* WL = (__nv_bfloat16*)(smem + T_WL);
    __nv_bfloat16* AH = (__nv_bfloat16*)(smem + T_AH);
    __nv_bfloat16* AL = (__nv_bfloat16*)(smem + T_AL);
    float* bs = (float*)(smem + T_BS);

    const int tid  = threadIdx.x;
    const int wid  = tid >> 5;
    const int lane = tid & 31;
    const int g0   = blockIdx.x * 128;

    {
        const uint4* whg = (const uint4*)(mode == 1 ? d_m1h : d_m2h);
        const uint4* wlg = (const uint4*)(mode == 1 ? d_m1l : d_m2l);
        uint4* whs = (uint4*)WH;
        uint4* wls = (uint4*)WL;
        for (int i = tid; i < 2176; i += 512) { whs[i] = whg[i]; wls[i] = wlg[i]; }
    }
    if (tid < 128) bs[tid] = bias[tid];
    {
        const int c0 = lane*4;
        for (int r = wid; r < 128; r += 16) {
            float4 v;
            if (mode == 1) {
                v = *(const float4*)&d_res[(size_t)(g0+r)*128 + c0];
            } else {
                float4 t = *(const float4*)&d_t[(size_t)(g0+r)*128 + c0];
                v.x = fmaxf(fmaf(t.x, d_scale1[c0+0], d_shift1[c0+0]), 0.f);
                v.y = fmaxf(fmaf(t.y, d_scale1[c0+1], d_shift1[c0+1]), 0.f);
                v.z = fmaxf(fmaf(t.z, d_scale1[c0+2], d_shift1[c0+2]), 0.f);
                v.w = fmaxf(fmaf(t.w, d_scale1[c0+3], d_shift1[c0+3]), 0.f);
            }
            split_store(AH, AL, r*WS2 + c0,     v.x, v.y);
            split_store(AH, AL, r*WS2 + c0 + 2, v.z, v.w);
        }
    }
    __syncthreads();

    const int wm = wid >> 2, wn = wid & 3;
    const int m0 = wm*32, n0 = wn*32;
    const int rA = lane >> 2;
    const uint32_t aoff = AOFF(lane), boff = BOFF(lane);
    const uint32_t WHu = smem_u32(WH), WLu = smem_u32(WL);
    const uint32_t AHu = smem_u32(AH), ALu = smem_u32(AL);
    float acc[2][4][4];
    #pragma unroll
    for (int mt = 0; mt < 2; mt++)
        #pragma unroll
        for (int nt = 0; nt < 4; nt++)
            #pragma unroll
            for (int q = 0; q < 4; q++) acc[mt][nt][q] = 0.f;

    GEMM_TERM44(AHu, WHu, acc)
    GEMM_TERM44(AHu, WLu, acc)
    GEMM_TERM44(ALu, WHu, acc)

    float* dst = (mode == 1) ? d_t : out;
    float s[4][2], sq[4][2];
    #pragma unroll
    for (int nt = 0; nt < 4; nt++) { s[nt][0]=s[nt][1]=sq[nt][0]=sq[nt][1]=0.f; }

    #pragma unroll
    for (int mt = 0; mt < 2; mt++) {
        const int row0 = m0 + mt*16 + rA, row1 = row0 + 8;
        #pragma unroll
        for (int nt = 0; nt < 4; nt++) {
            const int col0 = n0 + nt*8 + (lane & 3)*2;
            float v00 = acc[mt][nt][0] + bs[col0];
            float v01 = acc[mt][nt][1] + bs[col0+1];
            float v10 = acc[mt][nt][2] + bs[col0];
            float v11 = acc[mt][nt][3] + bs[col0+1];
            *(float2*)&dst[(size_t)(g0+row0)*128 + col0] = make_float2(v00, v01);
            *(float2*)&dst[(size_t)(g0+row1)*128 + col0] = make_float2(v10, v11);
            s[nt][0]  += v00 + v10;      s[nt][1]  += v01 + v11;
            sq[nt][0] += v00*v00 + v10*v10;
            sq[nt][1] += v01*v01 + v11*v11;
        }
    }
    #pragma unroll
    for (int nt = 0; nt < 4; nt++) {
        #pragma unroll
        for (int j = 0; j < 2; j++) {
            s[nt][j]  += __shfl_xor_sync(0xffffffffu, s[nt][j], 4);
            s[nt][j]  += __shfl_xor_sync(0xffffffffu, s[nt][j], 8);
            s[nt][j]  += __shfl_xor_sync(0xffffffffu, s[nt][j], 16);
            sq[nt][j] += __shfl_xor_sync(0xffffffffu, sq[nt][j], 4);
            sq[nt][j] += __shfl_xor_sync(0xffffffffu, sq[nt][j], 8);
            sq[nt][j] += __shfl_xor_sync(0xffffffffu, sq[nt][j], 16);
        }
    }
    __syncthreads();
    float* ps  = (float*)WH;
    float* ps2 = ps + 512;
    if (lane < 4) {
        #pragma unroll
        for (int nt = 0; nt < 4; nt++) {
            const int col0 = n0 + nt*8 + lane*2;
            ps [wm*128 + col0]   = s[nt][0];
            ps [wm*128 + col0+1] = s[nt][1];
            ps2[wm*128 + col0]   = sq[nt][0];
            ps2[wm*128 + col0+1] = sq[nt][1];
        }
    }
    __syncthreads();
    if (tid < 128) {
        float a = 0.f, b = 0.f;
        #pragma unroll
        for (int g = 0; g < 4; g++) { a += ps[g*128 + tid]; b += ps2[g*128 + tid]; }
        d_p1[blockIdx.x*128 + tid] = a;
        d_p2[blockIdx.x*128 + tid] = b;
    }
}

// ---------------- BN finalize / apply ----------------
__global__ void bn_finalize_kernel(const float* __restrict__ g, const float* __restrict__ be,
                                   int which) {
    const int o = threadIdx.x;
    float s = 0.f, s2 = 0.f;
    for (int b = 0; b < 128; b++) { s += d_p1[b*128 + o]; s2 += d_p2[b*128 + o]; }
    float mu  = s  * (1.f/16384.f);
    float var = s2 * (1.f/16384.f) - mu*mu;
    float sc  = g[o] * rsqrtf(var + EPS);
    if (which == 0) { d_scale1[o] = sc; d_shift1[o] = be[o] - mu*sc; }
    else            { d_scale2[o] = sc; d_shift2[o] = be[o] - mu*sc; }
}

__global__ void bn_apply_kernel(float* __restrict__ out) {
    int i = blockIdx.x*blockDim.x + threadIdx.x;
    int o = i & 127;
    out[i] = fmaf(out[i], d_scale2[o], d_shift2[o]);
}

// ---------------- launch ----------------
extern "C" void kernel_launch(void* const* d_in, const int* in_sizes, int n_in,
                              void* d_out, int out_size) {
    (void)in_sizes; (void)n_in; (void)out_size;
    const float* x   = (const float*)d_in[0];
    const float* pos = (const float*)d_in[1];
    const float* w1  = (const float*)d_in[2];
    const float* b1  = (const float*)d_in[3];
    const float* w2  = (const float*)d_in[4];
    const float* b2  = (const float*)d_in[5];
    const float* m1  = (const float*)d_in[6];
    const float* mb1 = (const float*)d_in[7];
    const float* m2  = (const float*)d_in[8];
    const float* mb2 = (const float*)d_in[9];
    const float* g1  = (const float*)d_in[10];
    const float* be1 = (const float*)d_in[11];
    const float* g2  = (const float*)d_in[12];
    const float* be2 = (const float*)d_in[13];
    float* out = (float*)d_out;

    const int SMEM_KNN = (32768 + 8192 + 8192) * 4;   // 196608

    cudaFuncSetAttribute(knn_kernel,      cudaFuncAttributeMaxDynamicSharedMemorySize, SMEM_KNN);
    cudaFuncSetAttribute(u_self_kernel,   cudaFuncAttributeMaxDynamicSharedMemorySize, US_SMEM);
    cudaFuncSetAttribute(neighbor_kernel, cudaFuncAttributeMaxDynamicSharedMemorySize, NB_SMEM);
    cudaFuncSetAttribute(tail_kernel,     cudaFuncAttributeMaxDynamicSharedMemorySize, T_SMEM);

    prep_kernel<<<64, 256>>>(w1, w2, m1, m2);
    knn_kernel<<<128, 512, SMEM_KNN>>>(pos);
    u_self_kernel<<<NPTS/128, 512, US_SMEM>>>(x, pos, b1, b2);
    neighbor_kernel<<<NPTS/8, 256, NB_SMEM>>>(x, b1, b2);
    tail_kernel<<<NPTS/128, 512, T_SMEM>>>(1, mb1, out);
    bn_finalize_kernel<<<1, 128>>>(g1, be1, 0);
    tail_kernel<<<NPTS/128, 512, T_SMEM>>>(2, mb2, out);
    bn_finalize_kernel<<<1, 128>>>(g2, be2, 1);
    bn_apply_kernel<<<(NPTS*CC)/256, 256>>>(out);
}